// round 2
// baseline (speedup 1.0000x reference)
#include <cuda_runtime.h>

// Problem constants
#define BB   4
#define SS   2048
#define DD   1024
#define HH   16
#define HDIM 64
#define MTOT (BB * SS)   // 8192

// Scratch (allocations are forbidden; use __device__ globals)
__device__ float g_q[(size_t)BB * HH * SS * HDIM];   // 32 MB each
__device__ float g_k[(size_t)BB * HH * SS * HDIM];
__device__ float g_v[(size_t)BB * HH * SS * HDIM];
__device__ float g_ctx[(size_t)MTOT * DD];
__device__ float g_xn[(size_t)MTOT * DD];

// ---------------------------------------------------------------------------
// SGEMM: C[M=8192, N=1024] = A[M,K=1024] * W[N,K]^T + bias
// 128x128 block tile, BK=8, 256 threads, 8x8 register microtile (split tiles).
// MODE 0: scatter output into [B,H,S,HD] (QKV projections)
// MODE 1: fused bias + LeakyReLU + mask, row-major output (final projection)
// ---------------------------------------------------------------------------
template <int MODE>
__global__ __launch_bounds__(256)
void gemm_kernel(const float* __restrict__ A, const float* __restrict__ W,
                 const float* __restrict__ bias, const float* __restrict__ mask,
                 float* __restrict__ out)
{
    __shared__ float As[8][128];
    __shared__ float Bs[8][128];

    const int t    = threadIdx.x;
    const int tx   = t & 15;
    const int ty   = t >> 4;
    const int brow = blockIdx.y * 128;
    const int bcol = blockIdx.x * 128;

    // tile-load mapping: each thread loads one float4 of A and one of W
    const int lrow = t >> 1;         // 0..127
    const int lq   = (t & 1) * 4;    // 0 or 4

    const float* Aptr = A + (size_t)(brow + lrow) * DD + lq;
    const float* Wptr = W + (size_t)(bcol + lrow) * DD + lq;

    float acc[8][8];
#pragma unroll
    for (int i = 0; i < 8; i++)
#pragma unroll
        for (int j = 0; j < 8; j++) acc[i][j] = 0.0f;

    for (int k0 = 0; k0 < DD; k0 += 8) {
        float4 av = *(const float4*)(Aptr + k0);
        float4 wv = *(const float4*)(Wptr + k0);
        __syncthreads();   // previous compute done before overwriting smem
        As[lq + 0][lrow] = av.x; As[lq + 1][lrow] = av.y;
        As[lq + 2][lrow] = av.z; As[lq + 3][lrow] = av.w;
        Bs[lq + 0][lrow] = wv.x; Bs[lq + 1][lrow] = wv.y;
        Bs[lq + 2][lrow] = wv.z; Bs[lq + 3][lrow] = wv.w;
        __syncthreads();

#pragma unroll
        for (int kk = 0; kk < 8; kk++) {
            float4 a0 = *(const float4*)&As[kk][ty * 4];
            float4 a1 = *(const float4*)&As[kk][64 + ty * 4];
            float4 b0 = *(const float4*)&Bs[kk][tx * 4];
            float4 b1 = *(const float4*)&Bs[kk][64 + tx * 4];
            float a[8] = {a0.x, a0.y, a0.z, a0.w, a1.x, a1.y, a1.z, a1.w};
            float bb[8] = {b0.x, b0.y, b0.z, b0.w, b1.x, b1.y, b1.z, b1.w};
#pragma unroll
            for (int i = 0; i < 8; i++)
#pragma unroll
                for (int j = 0; j < 8; j++)
                    acc[i][j] = fmaf(a[i], bb[j], acc[i][j]);
        }
    }

    int rr[8], cc[8];
#pragma unroll
    for (int i = 0; i < 4; i++) {
        rr[i]     = brow + ty * 4 + i;
        rr[i + 4] = brow + 64 + ty * 4 + i;
        cc[i]     = bcol + tx * 4 + i;
        cc[i + 4] = bcol + 64 + tx * 4 + i;
    }

#pragma unroll
    for (int i = 0; i < 8; i++) {
#pragma unroll
        for (int j = 0; j < 8; j++) {
            float v = acc[i][j] + bias[cc[j]];
            if (MODE == 0) {
                // scatter into [B,H,S,HD]
                int b = rr[i] >> 11;       // /S
                int s = rr[i] & (SS - 1);
                int h = cc[j] >> 6;        // /HD
                int hd = cc[j] & (HDIM - 1);
                out[(((size_t)(b * HH + h) * SS + s) * HDIM) + hd] = v;
            } else {
                if (v < 0.0f) v *= 0.01f;  // LeakyReLU
                v *= mask[rr[i]];          // zero padded positions
                out[(size_t)rr[i] * DD + cc[j]] = v;
            }
        }
    }
}

// ---------------------------------------------------------------------------
// Flash-style attention: one block per (b, h, 64-row q tile).
// Streams 64-row K/V tiles; online softmax; 4x4 microtiles for QK^T and PV.
// 1/sqrt(HD)=0.125 folded into Q. Dynamic smem ~70 KB.
// ---------------------------------------------------------------------------
#define PAD 68   // 64 + 4, keeps float4 alignment, breaks bank periodicity

__global__ __launch_bounds__(256)
void attn_kernel(const float* __restrict__ mask, float* __restrict__ ctx)
{
    extern __shared__ float sm[];
    float (*Qs)[PAD] = (float(*)[PAD])(sm);
    float (*Ks)[PAD] = (float(*)[PAD])(sm + 64 * PAD);
    float (*Vs)[PAD] = (float(*)[PAD])(sm + 2 * 64 * PAD);
    float (*Ps)[PAD] = (float(*)[PAD])(sm + 3 * 64 * PAD);
    float* sm_m = sm + 4 * 64 * PAD;
    float* sm_l = sm_m + 64;
    float* mS   = sm_l + 64;

    const int t  = threadIdx.x;
    const int tx = t & 15;
    const int ty = t >> 4;
    const int qt = blockIdx.x;
    const int h  = blockIdx.y;
    const int b  = blockIdx.z;

    const int lrow = t >> 2;           // 0..63
    const int lseg = (t & 3) << 4;     // 0,16,32,48

    const size_t head_base = ((size_t)(b * HH + h) * SS) * HDIM;
    const float* qbase = g_q + head_base + (size_t)qt * 64 * HDIM;

    // load Q tile transposed [hd][row], pre-scaled by 1/8
#pragma unroll
    for (int q = 0; q < 4; q++) {
        float4 v = *(const float4*)&qbase[lrow * HDIM + lseg + q * 4];
        Qs[lseg + q * 4 + 0][lrow] = v.x * 0.125f;
        Qs[lseg + q * 4 + 1][lrow] = v.y * 0.125f;
        Qs[lseg + q * 4 + 2][lrow] = v.z * 0.125f;
        Qs[lseg + q * 4 + 3][lrow] = v.w * 0.125f;
    }
    if (t < 64) { sm_m[t] = -1e30f; sm_l[t] = 0.0f; }

    float oacc[4][4];
#pragma unroll
    for (int i = 0; i < 4; i++)
#pragma unroll
        for (int j = 0; j < 4; j++) oacc[i][j] = 0.0f;

    __syncthreads();

    for (int kt = 0; kt < SS / 64; kt++) {
        const float* kbase = g_k + head_base + (size_t)kt * 64 * HDIM;
        const float* vbase = g_v + head_base + (size_t)kt * 64 * HDIM;

        // stage next K/V tile in registers (overlaps with previous PV compute)
        float4 kreg[4], vreg[4];
#pragma unroll
        for (int q = 0; q < 4; q++) {
            kreg[q] = *(const float4*)&kbase[lrow * HDIM + lseg + q * 4];
            vreg[q] = *(const float4*)&vbase[lrow * HDIM + lseg + q * 4];
        }
        float mval = 0.0f;
        if (t < 64) mval = mask[b * SS + kt * 64 + t];

        __syncthreads();  // previous tile fully consumed
#pragma unroll
        for (int q = 0; q < 4; q++) {
            Ks[lseg + q * 4 + 0][lrow] = kreg[q].x;
            Ks[lseg + q * 4 + 1][lrow] = kreg[q].y;
            Ks[lseg + q * 4 + 2][lrow] = kreg[q].z;
            Ks[lseg + q * 4 + 3][lrow] = kreg[q].w;
            *(float4*)&Vs[lrow][lseg + q * 4] = vreg[q];
        }
        if (t < 64) mS[t] = (1.0f - mval) * -10000.0f;
        __syncthreads();

        // S tile = Q^T K (scaled), 4x4 per thread
        float sacc[4][4];
#pragma unroll
        for (int i = 0; i < 4; i++)
#pragma unroll
            for (int j = 0; j < 4; j++) sacc[i][j] = 0.0f;

#pragma unroll 8
        for (int kk = 0; kk < 64; kk++) {
            float4 a  = *(const float4*)&Qs[kk][ty * 4];
            float4 bq = *(const float4*)&Ks[kk][tx * 4];
            float av[4] = {a.x, a.y, a.z, a.w};
            float bv[4] = {bq.x, bq.y, bq.z, bq.w};
#pragma unroll
            for (int i = 0; i < 4; i++)
#pragma unroll
                for (int j = 0; j < 4; j++)
                    sacc[i][j] = fmaf(av[i], bv[j], sacc[i][j]);
        }

        float mc[4];
#pragma unroll
        for (int j = 0; j < 4; j++) mc[j] = mS[tx * 4 + j];

        // online softmax per row (16 lanes per row-group, aligned in a warp)
#pragma unroll
        for (int i = 0; i < 4; i++) {
            const int r = ty * 4 + i;
            float s0 = sacc[i][0] + mc[0];
            float s1 = sacc[i][1] + mc[1];
            float s2 = sacc[i][2] + mc[2];
            float s3 = sacc[i][3] + mc[3];
            float rmax = fmaxf(fmaxf(s0, s1), fmaxf(s2, s3));
#pragma unroll
            for (int off = 1; off < 16; off <<= 1)
                rmax = fmaxf(rmax, __shfl_xor_sync(0xffffffffu, rmax, off));
            float mo = sm_m[r];
            float mn = fmaxf(mo, rmax);
            float alpha = __expf(mo - mn);
            float p0 = __expf(s0 - mn);
            float p1 = __expf(s1 - mn);
            float p2 = __expf(s2 - mn);
            float p3 = __expf(s3 - mn);
            float rsum = p0 + p1 + p2 + p3;
#pragma unroll
            for (int off = 1; off < 16; off <<= 1)
                rsum += __shfl_xor_sync(0xffffffffu, rsum, off);
            if (tx == 0) { sm_m[r] = mn; sm_l[r] = sm_l[r] * alpha + rsum; }
#pragma unroll
            for (int j = 0; j < 4; j++) oacc[i][j] *= alpha;
            Ps[tx * 4 + 0][r] = p0;
            Ps[tx * 4 + 1][r] = p1;
            Ps[tx * 4 + 2][r] = p2;
            Ps[tx * 4 + 3][r] = p3;
        }
        __syncthreads();

        // O += P V
#pragma unroll 8
        for (int kk = 0; kk < 64; kk++) {
            float4 a  = *(const float4*)&Ps[kk][ty * 4];
            float4 bq = *(const float4*)&Vs[kk][tx * 4];
            float av[4] = {a.x, a.y, a.z, a.w};
            float bv[4] = {bq.x, bq.y, bq.z, bq.w};
#pragma unroll
            for (int i = 0; i < 4; i++)
#pragma unroll
                for (int j = 0; j < 4; j++)
                    oacc[i][j] = fmaf(av[i], bv[j], oacc[i][j]);
        }
    }

    // normalize and write ctx as [B,S,D]
#pragma unroll
    for (int i = 0; i < 4; i++) {
        const int r = ty * 4 + i;
        const float inv = 1.0f / sm_l[r];
        float4 o;
        o.x = oacc[i][0] * inv;
        o.y = oacc[i][1] * inv;
        o.z = oacc[i][2] * inv;
        o.w = oacc[i][3] * inv;
        const int srow = qt * 64 + r;
        *(float4*)&ctx[(((size_t)b * SS + srow) * DD) + h * HDIM + tx * 4] = o;
    }
}

// ---------------------------------------------------------------------------
// Residual add + LayerNorm: one block (256 threads) per row of 1024
// ---------------------------------------------------------------------------
__global__ __launch_bounds__(256)
void ln_kernel(const float* __restrict__ x0, const float* __restrict__ gam,
               const float* __restrict__ bet)
{
    __shared__ float red[16];
    const int row = blockIdx.x;
    const int t = threadIdx.x;
    const float* cptr = g_ctx + (size_t)row * DD;
    const float* xptr = x0 + (size_t)row * DD;

    float v[4];
    float sum = 0.0f, sq = 0.0f;
#pragma unroll
    for (int e = 0; e < 4; e++) {
        int idx = e * 256 + t;
        float x = cptr[idx] + xptr[idx];
        v[e] = x;
        sum += x;
        sq += x * x;
    }
#pragma unroll
    for (int off = 16; off; off >>= 1) {
        sum += __shfl_xor_sync(0xffffffffu, sum, off);
        sq  += __shfl_xor_sync(0xffffffffu, sq, off);
    }
    const int w = t >> 5;
    if ((t & 31) == 0) { red[w] = sum; red[8 + w] = sq; }
    __syncthreads();
    float tsum = 0.0f, tsq = 0.0f;
#pragma unroll
    for (int i = 0; i < 8; i++) { tsum += red[i]; tsq += red[8 + i]; }
    const float mu = tsum * (1.0f / DD);
    const float var = tsq * (1.0f / DD) - mu * mu;
    const float rs = rsqrtf(var + 1e-5f);

    float* outp = g_xn + (size_t)row * DD;
#pragma unroll
    for (int e = 0; e < 4; e++) {
        int idx = e * 256 + t;
        outp[idx] = (v[e] - mu) * rs * gam[idx] + bet[idx];
    }
}

// ---------------------------------------------------------------------------
extern "C" void kernel_launch(void* const* d_in, const int* in_sizes, int n_in,
                              void* d_out, int out_size)
{
    (void)in_sizes; (void)n_in; (void)out_size;
    const float* inputs = (const float*)d_in[0];
    const float* mask   = (const float*)d_in[1];
    const float* Wq     = (const float*)d_in[2];
    const float* bq     = (const float*)d_in[3];
    const float* Wk     = (const float*)d_in[4];
    const float* bk     = (const float*)d_in[5];
    const float* Wv     = (const float*)d_in[6];
    const float* bv     = (const float*)d_in[7];
    const float* Wo     = (const float*)d_in[8];
    const float* bo     = (const float*)d_in[9];
    const float* ln_g   = (const float*)d_in[10];
    const float* ln_b   = (const float*)d_in[11];
    float* out = (float*)d_out;

    float *qp, *kp, *vp, *ctxp, *xnp;
    cudaGetSymbolAddress((void**)&qp, g_q);
    cudaGetSymbolAddress((void**)&kp, g_k);
    cudaGetSymbolAddress((void**)&vp, g_v);
    cudaGetSymbolAddress((void**)&ctxp, g_ctx);
    cudaGetSymbolAddress((void**)&xnp, g_xn);

    const int smem_attn = (4 * 64 * PAD + 3 * 64) * (int)sizeof(float);
    cudaFuncSetAttribute((const void*)attn_kernel,
                         cudaFuncAttributeMaxDynamicSharedMemorySize, smem_attn);

    dim3 ggrid(DD / 128, MTOT / 128);

    gemm_kernel<0><<<ggrid, 256>>>(inputs, Wq, bq, nullptr, qp);
    gemm_kernel<0><<<ggrid, 256>>>(inputs, Wk, bk, nullptr, kp);
    gemm_kernel<0><<<ggrid, 256>>>(inputs, Wv, bv, nullptr, vp);

    attn_kernel<<<dim3(SS / 64, HH, BB), 256, smem_attn>>>(mask, ctxp);

    ln_kernel<<<MTOT, 256>>>(inputs, ln_g, ln_b);

    gemm_kernel<1><<<ggrid, 256>>>(xnp, Wo, bo, mask, out);
}

// round 5
// speedup vs baseline: 1.3132x; 1.3132x over previous
#include <cuda_runtime.h>
#include <cuda_bf16.h>
#include <cstdint>

// Problem constants
#define BB   4
#define SS   2048
#define DD   1024
#define HH   16
#define HDIM 64
#define MTOT (BB * SS)   // 8192

// ---------------------------------------------------------------------------
// Scratch (__device__ globals; allocation is forbidden)
// ---------------------------------------------------------------------------
__device__ float g_q[(size_t)BB * HH * SS * HDIM];
__device__ float g_k[(size_t)BB * HH * SS * HDIM];
__device__ float g_v[(size_t)BB * HH * SS * HDIM];
__device__ float g_ctx[(size_t)MTOT * DD];

__device__ __nv_bfloat16 g_in_hi[(size_t)MTOT * DD];
__device__ __nv_bfloat16 g_in_lo[(size_t)MTOT * DD];
__device__ __nv_bfloat16 g_wq_hi[(size_t)DD * DD], g_wq_lo[(size_t)DD * DD];
__device__ __nv_bfloat16 g_wk_hi[(size_t)DD * DD], g_wk_lo[(size_t)DD * DD];
__device__ __nv_bfloat16 g_wv_hi[(size_t)DD * DD], g_wv_lo[(size_t)DD * DD];
__device__ __nv_bfloat16 g_wo_hi[(size_t)DD * DD], g_wo_lo[(size_t)DD * DD];
__device__ __nv_bfloat16 g_xn_hi[(size_t)MTOT * DD];
__device__ __nv_bfloat16 g_xn_lo[(size_t)MTOT * DD];

// ---------------------------------------------------------------------------
// PTX helpers (base-target only: mma.sync / ldmatrix / cp.async)
// ---------------------------------------------------------------------------
__device__ __forceinline__ uint32_t smem_u32(const void* p) {
    uint32_t a;
    asm("{ .reg .u64 t; cvta.to.shared.u64 t, %1; cvt.u32.u64 %0, t; }"
        : "=r"(a) : "l"(p));
    return a;
}

__device__ __forceinline__ void ldsm_x4(uint32_t* r, uint32_t addr) {
    asm volatile("ldmatrix.sync.aligned.m8n8.x4.shared.b16 {%0,%1,%2,%3}, [%4];"
                 : "=r"(r[0]), "=r"(r[1]), "=r"(r[2]), "=r"(r[3]) : "r"(addr));
}

__device__ __forceinline__ void mma_bf16(float* d, const uint32_t* a, const uint32_t* b) {
    asm volatile("mma.sync.aligned.m16n8k16.row.col.f32.bf16.bf16.f32 "
                 "{%0,%1,%2,%3}, {%4,%5,%6,%7}, {%8,%9}, {%0,%1,%2,%3};"
                 : "+f"(d[0]), "+f"(d[1]), "+f"(d[2]), "+f"(d[3])
                 : "r"(a[0]), "r"(a[1]), "r"(a[2]), "r"(a[3]), "r"(b[0]), "r"(b[1]));
}

#define CP_ASYNC16(dst, src) \
    asm volatile("cp.async.cg.shared.global [%0], [%1], 16;" \
                 :: "r"(dst), "l"(src) : "memory")
#define CP_COMMIT() asm volatile("cp.async.commit_group;" ::: "memory")
#define CP_WAIT1()  asm volatile("cp.async.wait_group 1;" ::: "memory")
#define CP_WAIT0()  asm volatile("cp.async.wait_group 0;" ::: "memory")

// ---------------------------------------------------------------------------
// fp32 -> bf16 hi/lo split
// ---------------------------------------------------------------------------
__global__ __launch_bounds__(256)
void split_kernel(const float* __restrict__ src, __nv_bfloat16* __restrict__ hi,
                  __nv_bfloat16* __restrict__ lo, int n4)
{
    int i = blockIdx.x * 256 + threadIdx.x;
    if (i >= n4) return;
    float4 v = ((const float4*)src)[i];
    __nv_bfloat16 h[4], l[4];
    float x[4] = {v.x, v.y, v.z, v.w};
#pragma unroll
    for (int e = 0; e < 4; e++) {
        h[e] = __float2bfloat16(x[e]);
        l[e] = __float2bfloat16(x[e] - __bfloat162float(h[e]));
    }
    ((uint2*)hi)[i] = *(uint2*)h;
    ((uint2*)lo)[i] = *(uint2*)l;
}

// ---------------------------------------------------------------------------
// mma.sync bf16 3-split GEMM: C[8192,1024] = A[M,K] * W[N,K]^T + bias
// 128x128 CTA tile, 8 warps of 64x32, BK=32, cp.async double buffer.
// Smem rows padded to 40 bf16 (80 B) -> conflict-free ldmatrix.
// MODE 0: scatter into [B,H,S,HD]. MODE 1: LeakyReLU + mask, row-major.
// ---------------------------------------------------------------------------
#define SROW   40
#define TILE_B (128 * SROW * 2)     // 10240 B per operand tile
#define BUF_B  (4 * TILE_B)         // 40960 B (Ahi,Alo,Bhi,Blo)
#define NKT    (DD / 32)            // 32 k-iterations

__device__ __forceinline__ void stage_tile(uint32_t dst, const __nv_bfloat16* src,
                                           int rowbase, int k0, int t)
{
#pragma unroll
    for (int i = 0; i < 2; i++) {
        int id  = t + i * 256;
        int row = id >> 2;
        int c8  = (id & 3) * 8;
        const __nv_bfloat16* g = src + (size_t)(rowbase + row) * DD + k0 + c8;
        CP_ASYNC16(dst + row * (SROW * 2) + c8 * 2, g);
    }
}

template <int MODE>
__global__ __launch_bounds__(256, 1)
void gemm_mma(const __nv_bfloat16* __restrict__ Ahi, const __nv_bfloat16* __restrict__ Alo,
              const __nv_bfloat16* __restrict__ Bhi, const __nv_bfloat16* __restrict__ Blo,
              const float* __restrict__ bias, const float* __restrict__ mask,
              float* __restrict__ out)
{
    extern __shared__ __align__(128) char smem[];
    const uint32_t sb = smem_u32(smem);
    const int t    = threadIdx.x;
    const int wid  = t >> 5;
    const int lane = t & 31;
    const int brow = blockIdx.y * 128;
    const int bcol = blockIdx.x * 128;
    const int wm = wid & 1;     // 2 warps along M (64 rows each)
    const int wn = wid >> 1;    // 4 warps along N (32 cols each)

    // prologue: stage k-tile 0 into buffer 0
    stage_tile(sb + 0 * TILE_B, Ahi, brow, 0, t);
    stage_tile(sb + 1 * TILE_B, Alo, brow, 0, t);
    stage_tile(sb + 2 * TILE_B, Bhi, bcol, 0, t);
    stage_tile(sb + 3 * TILE_B, Blo, bcol, 0, t);
    CP_COMMIT();

    float acc[4][4][4];
#pragma unroll
    for (int mt = 0; mt < 4; mt++)
#pragma unroll
        for (int nt = 0; nt < 4; nt++)
#pragma unroll
            for (int e = 0; e < 4; e++) acc[mt][nt][e] = 0.0f;

    const int sub = lane >> 3;
    const int lr  = lane & 7;
    // A ldmatrix mapping: reg order (m0-7,k0-7),(m8-15,k0-7),(m0-7,k8-15),(m8-15,k8-15)
    const int a_roff = lr + (sub & 1) * 8;
    const int a_koff = (sub >> 1) * 16;        // bytes
    // B ldmatrix mapping: reg order (n0-7,k0-7),(n0-7,k8-15),(n8-15,k0-7),(n8-15,k8-15)
    const int b_roff = lr + (sub >> 1) * 8;
    const int b_koff = (sub & 1) * 16;         // bytes

    for (int kt = 0; kt < NKT; kt++) {
        if (kt + 1 < NKT) {
            const uint32_t nb = sb + ((kt + 1) & 1) * BUF_B;
            const int k0 = (kt + 1) * 32;
            stage_tile(nb + 0 * TILE_B, Ahi, brow, k0, t);
            stage_tile(nb + 1 * TILE_B, Alo, brow, k0, t);
            stage_tile(nb + 2 * TILE_B, Bhi, bcol, k0, t);
            stage_tile(nb + 3 * TILE_B, Blo, bcol, k0, t);
            CP_COMMIT();
            CP_WAIT1();
        } else {
            CP_WAIT0();
        }
        __syncthreads();

        const uint32_t bufb = sb + (kt & 1) * BUF_B;

#pragma unroll
        for (int ks = 0; ks < 2; ks++) {
            const int ksb = ks * 32;   // 16 elems = 32 bytes
            // B fragments: 2 ldmatrix.x4 cover 4 n8-tiles (hi), 2 more (lo)
            uint32_t bh[2][4], bl[2][4];
#pragma unroll
            for (int np = 0; np < 2; np++) {
                const int nrow = wn * 32 + np * 16 + b_roff;
                ldsm_x4(bh[np], bufb + 2 * TILE_B + nrow * (SROW * 2) + ksb + b_koff);
                ldsm_x4(bl[np], bufb + 3 * TILE_B + nrow * (SROW * 2) + ksb + b_koff);
            }
#pragma unroll
            for (int mt = 0; mt < 4; mt++) {
                const int mrow = wm * 64 + mt * 16 + a_roff;
                uint32_t ah[4], al[4];
                ldsm_x4(ah, bufb + 0 * TILE_B + mrow * (SROW * 2) + ksb + a_koff);
                ldsm_x4(al, bufb + 1 * TILE_B + mrow * (SROW * 2) + ksb + a_koff);
#pragma unroll
                for (int nt = 0; nt < 4; nt++) {
                    const uint32_t* bhp = &bh[nt >> 1][(nt & 1) * 2];
                    const uint32_t* blp = &bl[nt >> 1][(nt & 1) * 2];
                    mma_bf16(acc[mt][nt], ah, bhp);   // hi*hi
                    mma_bf16(acc[mt][nt], ah, blp);   // hi*lo
                    mma_bf16(acc[mt][nt], al, bhp);   // lo*hi
                }
            }
        }
        __syncthreads();   // compute done before next stage overwrites this buffer
    }

    // epilogue
    const int g  = lane >> 2;
    const int tq = lane & 3;
#pragma unroll
    for (int mt = 0; mt < 4; mt++) {
        const int r0 = brow + wm * 64 + mt * 16 + g;
        float mr0 = 1.0f, mr1 = 1.0f;
        if (MODE == 1) { mr0 = mask[r0]; mr1 = mask[r0 + 8]; }
#pragma unroll
        for (int nt = 0; nt < 4; nt++) {
            const int c = bcol + wn * 32 + nt * 8 + tq * 2;
            const float b0 = bias[c], b1 = bias[c + 1];
            float2 v0, v1;
            v0.x = acc[mt][nt][0] + b0; v0.y = acc[mt][nt][1] + b1;   // row r0
            v1.x = acc[mt][nt][2] + b0; v1.y = acc[mt][nt][3] + b1;   // row r0+8
            if (MODE == 0) {
                const int h  = c >> 6;
                const int hd = c & (HDIM - 1);
                const int bi = r0 >> 11;
                const int s0 = r0 & (SS - 1);
                const size_t base = ((size_t)(bi * HH + h) * SS) * HDIM + hd;
                *(float2*)&out[base + (size_t)s0 * HDIM] = v0;
                *(float2*)&out[base + (size_t)(s0 + 8) * HDIM] = v1;
            } else {
                if (v0.x < 0.0f) v0.x *= 0.01f;
                if (v0.y < 0.0f) v0.y *= 0.01f;
                if (v1.x < 0.0f) v1.x *= 0.01f;
                if (v1.y < 0.0f) v1.y *= 0.01f;
                v0.x *= mr0; v0.y *= mr0;
                v1.x *= mr1; v1.y *= mr1;
                *(float2*)&out[(size_t)r0 * DD + c] = v0;
                *(float2*)&out[(size_t)(r0 + 8) * DD + c] = v1;
            }
        }
    }
}

// ---------------------------------------------------------------------------
// Flash-style attention (SIMT fp32, validated in R2)
// ---------------------------------------------------------------------------
#define PAD 68

__global__ __launch_bounds__(256)
void attn_kernel(const float* __restrict__ mask, float* __restrict__ ctx)
{
    extern __shared__ float sm[];
    float (*Qs)[PAD] = (float(*)[PAD])(sm);
    float (*Ks)[PAD] = (float(*)[PAD])(sm + 64 * PAD);
    float (*Vs)[PAD] = (float(*)[PAD])(sm + 2 * 64 * PAD);
    float (*Ps)[PAD] = (float(*)[PAD])(sm + 3 * 64 * PAD);
    float* sm_m = sm + 4 * 64 * PAD;
    float* sm_l = sm_m + 64;
    float* mS   = sm_l + 64;

    const int t  = threadIdx.x;
    const int tx = t & 15;
    const int ty = t >> 4;
    const int qt = blockIdx.x;
    const int h  = blockIdx.y;
    const int b  = blockIdx.z;

    const int lrow = t >> 2;
    const int lseg = (t & 3) << 4;

    const size_t head_base = ((size_t)(b * HH + h) * SS) * HDIM;
    const float* qbase = g_q + head_base + (size_t)qt * 64 * HDIM;

#pragma unroll
    for (int q = 0; q < 4; q++) {
        float4 v = *(const float4*)&qbase[lrow * HDIM + lseg + q * 4];
        Qs[lseg + q * 4 + 0][lrow] = v.x * 0.125f;
        Qs[lseg + q * 4 + 1][lrow] = v.y * 0.125f;
        Qs[lseg + q * 4 + 2][lrow] = v.z * 0.125f;
        Qs[lseg + q * 4 + 3][lrow] = v.w * 0.125f;
    }
    if (t < 64) { sm_m[t] = -1e30f; sm_l[t] = 0.0f; }

    float oacc[4][4];
#pragma unroll
    for (int i = 0; i < 4; i++)
#pragma unroll
        for (int j = 0; j < 4; j++) oacc[i][j] = 0.0f;

    __syncthreads();

    for (int kt = 0; kt < SS / 64; kt++) {
        const float* kbase = g_k + head_base + (size_t)kt * 64 * HDIM;
        const float* vbase = g_v + head_base + (size_t)kt * 64 * HDIM;

        float4 kreg[4], vreg[4];
#pragma unroll
        for (int q = 0; q < 4; q++) {
            kreg[q] = *(const float4*)&kbase[lrow * HDIM + lseg + q * 4];
            vreg[q] = *(const float4*)&vbase[lrow * HDIM + lseg + q * 4];
        }
        float mval = 0.0f;
        if (t < 64) mval = mask[b * SS + kt * 64 + t];

        __syncthreads();
#pragma unroll
        for (int q = 0; q < 4; q++) {
            Ks[lseg + q * 4 + 0][lrow] = kreg[q].x;
            Ks[lseg + q * 4 + 1][lrow] = kreg[q].y;
            Ks[lseg + q * 4 + 2][lrow] = kreg[q].z;
            Ks[lseg + q * 4 + 3][lrow] = kreg[q].w;
            *(float4*)&Vs[lrow][lseg + q * 4] = vreg[q];
        }
        if (t < 64) mS[t] = (1.0f - mval) * -10000.0f;
        __syncthreads();

        float sacc[4][4];
#pragma unroll
        for (int i = 0; i < 4; i++)
#pragma unroll
            for (int j = 0; j < 4; j++) sacc[i][j] = 0.0f;

#pragma unroll 8
        for (int kk = 0; kk < 64; kk++) {
            float4 a  = *(const float4*)&Qs[kk][ty * 4];
            float4 bq = *(const float4*)&Ks[kk][tx * 4];
            float av[4] = {a.x, a.y, a.z, a.w};
            float bv[4] = {bq.x, bq.y, bq.z, bq.w};
#pragma unroll
            for (int i = 0; i < 4; i++)
#pragma unroll
                for (int j = 0; j < 4; j++)
                    sacc[i][j] = fmaf(av[i], bv[j], sacc[i][j]);
        }

        float mc[4];
#pragma unroll
        for (int j = 0; j < 4; j++) mc[j] = mS[tx * 4 + j];

#pragma unroll
        for (int i = 0; i < 4; i++) {
            const int r = ty * 4 + i;
            float s0 = sacc[i][0] + mc[0];
            float s1 = sacc[i][1] + mc[1];
            float s2 = sacc[i][2] + mc[2];
            float s3 = sacc[i][3] + mc[3];
            float rmax = fmaxf(fmaxf(s0, s1), fmaxf(s2, s3));
#pragma unroll
            for (int off = 1; off < 16; off <<= 1)
                rmax = fmaxf(rmax, __shfl_xor_sync(0xffffffffu, rmax, off));
            float mo = sm_m[r];
            float mn = fmaxf(mo, rmax);
            float alpha = __expf(mo - mn);
            float p0 = __expf(s0 - mn);
            float p1 = __expf(s1 - mn);
            float p2 = __expf(s2 - mn);
            float p3 = __expf(s3 - mn);
            float rsum = p0 + p1 + p2 + p3;
#pragma unroll
            for (int off = 1; off < 16; off <<= 1)
                rsum += __shfl_xor_sync(0xffffffffu, rsum, off);
            if (tx == 0) { sm_m[r] = mn; sm_l[r] = sm_l[r] * alpha + rsum; }
#pragma unroll
            for (int j = 0; j < 4; j++) oacc[i][j] *= alpha;
            Ps[tx * 4 + 0][r] = p0;
            Ps[tx * 4 + 1][r] = p1;
            Ps[tx * 4 + 2][r] = p2;
            Ps[tx * 4 + 3][r] = p3;
        }
        __syncthreads();

#pragma unroll 8
        for (int kk = 0; kk < 64; kk++) {
            float4 a  = *(const float4*)&Ps[kk][ty * 4];
            float4 bq = *(const float4*)&Vs[kk][tx * 4];
            float av[4] = {a.x, a.y, a.z, a.w};
            float bv[4] = {bq.x, bq.y, bq.z, bq.w};
#pragma unroll
            for (int i = 0; i < 4; i++)
#pragma unroll
                for (int j = 0; j < 4; j++)
                    oacc[i][j] = fmaf(av[i], bv[j], oacc[i][j]);
        }
    }

#pragma unroll
    for (int i = 0; i < 4; i++) {
        const int r = ty * 4 + i;
        const float inv = 1.0f / sm_l[r];
        float4 o;
        o.x = oacc[i][0] * inv;
        o.y = oacc[i][1] * inv;
        o.z = oacc[i][2] * inv;
        o.w = oacc[i][3] * inv;
        const int srow = qt * 64 + r;
        *(float4*)&ctx[(((size_t)b * SS + srow) * DD) + h * HDIM + tx * 4] = o;
    }
}

// ---------------------------------------------------------------------------
// Residual add + LayerNorm -> bf16 hi/lo split output
// ---------------------------------------------------------------------------
__global__ __launch_bounds__(256)
void ln_kernel(const float* __restrict__ x0, const float* __restrict__ gam,
               const float* __restrict__ bet)
{
    __shared__ float red[16];
    const int row = blockIdx.x;
    const int t = threadIdx.x;
    const float* cptr = g_ctx + (size_t)row * DD;
    const float* xptr = x0 + (size_t)row * DD;

    float v[4];
    float sum = 0.0f, sq = 0.0f;
#pragma unroll
    for (int e = 0; e < 4; e++) {
        int idx = e * 256 + t;
        float x = cptr[idx] + xptr[idx];
        v[e] = x;
        sum += x;
        sq += x * x;
    }
#pragma unroll
    for (int off = 16; off; off >>= 1) {
        sum += __shfl_xor_sync(0xffffffffu, sum, off);
        sq  += __shfl_xor_sync(0xffffffffu, sq, off);
    }
    const int w = t >> 5;
    if ((t & 31) == 0) { red[w] = sum; red[8 + w] = sq; }
    __syncthreads();
    float tsum = 0.0f, tsq = 0.0f;
#pragma unroll
    for (int i = 0; i < 8; i++) { tsum += red[i]; tsq += red[8 + i]; }
    const float mu = tsum * (1.0f / DD);
    const float var = tsq * (1.0f / DD) - mu * mu;
    const float rs = rsqrtf(var + 1e-5f);

#pragma unroll
    for (int e = 0; e < 4; e++) {
        int idx = e * 256 + t;
        float y = (v[e] - mu) * rs * gam[idx] + bet[idx];
        __nv_bfloat16 h = __float2bfloat16(y);
        g_xn_hi[(size_t)row * DD + idx] = h;
        g_xn_lo[(size_t)row * DD + idx] = __float2bfloat16(y - __bfloat162float(h));
    }
}

// ---------------------------------------------------------------------------
extern "C" void kernel_launch(void* const* d_in, const int* in_sizes, int n_in,
                              void* d_out, int out_size)
{
    (void)in_sizes; (void)n_in; (void)out_size;
    const float* inputs = (const float*)d_in[0];
    const float* mask   = (const float*)d_in[1];
    const float* Wq     = (const float*)d_in[2];
    const float* bq     = (const float*)d_in[3];
    const float* Wk     = (const float*)d_in[4];
    const float* bk     = (const float*)d_in[5];
    const float* Wv     = (const float*)d_in[6];
    const float* bv     = (const float*)d_in[7];
    const float* Wo     = (const float*)d_in[8];
    const float* bo     = (const float*)d_in[9];
    const float* ln_g   = (const float*)d_in[10];
    const float* ln_b   = (const float*)d_in[11];
    float* out = (float*)d_out;

    float *qp, *kp, *vp, *ctxp;
    __nv_bfloat16 *inh, *inl, *wqh, *wql, *wkh, *wkl, *wvh, *wvl, *woh, *wol, *xnh, *xnl;
    cudaGetSymbolAddress((void**)&qp,  g_q);
    cudaGetSymbolAddress((void**)&kp,  g_k);
    cudaGetSymbolAddress((void**)&vp,  g_v);
    cudaGetSymbolAddress((void**)&ctxp, g_ctx);
    cudaGetSymbolAddress((void**)&inh, g_in_hi);
    cudaGetSymbolAddress((void**)&inl, g_in_lo);
    cudaGetSymbolAddress((void**)&wqh, g_wq_hi);
    cudaGetSymbolAddress((void**)&wql, g_wq_lo);
    cudaGetSymbolAddress((void**)&wkh, g_wk_hi);
    cudaGetSymbolAddress((void**)&wkl, g_wk_lo);
    cudaGetSymbolAddress((void**)&wvh, g_wv_hi);
    cudaGetSymbolAddress((void**)&wvl, g_wv_lo);
    cudaGetSymbolAddress((void**)&woh, g_wo_hi);
    cudaGetSymbolAddress((void**)&wol, g_wo_lo);
    cudaGetSymbolAddress((void**)&xnh, g_xn_hi);
    cudaGetSymbolAddress((void**)&xnl, g_xn_lo);

    const int smem_attn = (4 * 64 * PAD + 3 * 64) * (int)sizeof(float);
    const int smem_gemm = 2 * BUF_B;   // 81920
    cudaFuncSetAttribute((const void*)attn_kernel,
                         cudaFuncAttributeMaxDynamicSharedMemorySize, smem_attn);
    cudaFuncSetAttribute((const void*)gemm_mma<0>,
                         cudaFuncAttributeMaxDynamicSharedMemorySize, smem_gemm);
    cudaFuncSetAttribute((const void*)gemm_mma<1>,
                         cudaFuncAttributeMaxDynamicSharedMemorySize, smem_gemm);

    // split inputs + weights into bf16 hi/lo
    split_kernel<<<(MTOT * DD / 4) / 256, 256>>>(inputs, inh, inl, MTOT * DD / 4);
    split_kernel<<<(DD * DD / 4) / 256, 256>>>(Wq, wqh, wql, DD * DD / 4);
    split_kernel<<<(DD * DD / 4) / 256, 256>>>(Wk, wkh, wkl, DD * DD / 4);
    split_kernel<<<(DD * DD / 4) / 256, 256>>>(Wv, wvh, wvl, DD * DD / 4);
    split_kernel<<<(DD * DD / 4) / 256, 256>>>(Wo, woh, wol, DD * DD / 4);

    dim3 ggrid(DD / 128, MTOT / 128);
    gemm_mma<0><<<ggrid, 256, smem_gemm>>>(inh, inl, wqh, wql, bq, nullptr, qp);
    gemm_mma<0><<<ggrid, 256, smem_gemm>>>(inh, inl, wkh, wkl, bk, nullptr, kp);
    gemm_mma<0><<<ggrid, 256, smem_gemm>>>(inh, inl, wvh, wvl, bv, nullptr, vp);

    attn_kernel<<<dim3(SS / 64, HH, BB), 256, smem_attn>>>(mask, ctxp);

    ln_kernel<<<MTOT, 256>>>(inputs, ln_g, ln_b);

    gemm_mma<1><<<ggrid, 256, smem_gemm>>>(xnh, xnl, woh, wol, bo, mask, out);
}

// round 6
// speedup vs baseline: 2.8498x; 2.1701x over previous
#include <cuda_runtime.h>
#include <cuda_bf16.h>
#include <cstdint>

// Problem constants
#define BB   4
#define SS   2048
#define DD   1024
#define HH   16
#define HDIM 64
#define MTOT (BB * SS)   // 8192

// ---------------------------------------------------------------------------
// Scratch (__device__ globals; allocation is forbidden)
// ---------------------------------------------------------------------------
__device__ float g_ctx[(size_t)MTOT * DD];

__device__ __nv_bfloat16 g_qh[(size_t)BB * HH * SS * HDIM], g_ql[(size_t)BB * HH * SS * HDIM];
__device__ __nv_bfloat16 g_kh[(size_t)BB * HH * SS * HDIM], g_kl[(size_t)BB * HH * SS * HDIM];
__device__ __nv_bfloat16 g_vh[(size_t)BB * HH * SS * HDIM], g_vl[(size_t)BB * HH * SS * HDIM];

__device__ __nv_bfloat16 g_in_hi[(size_t)MTOT * DD];
__device__ __nv_bfloat16 g_in_lo[(size_t)MTOT * DD];
__device__ __nv_bfloat16 g_wq_hi[(size_t)DD * DD], g_wq_lo[(size_t)DD * DD];
__device__ __nv_bfloat16 g_wk_hi[(size_t)DD * DD], g_wk_lo[(size_t)DD * DD];
__device__ __nv_bfloat16 g_wv_hi[(size_t)DD * DD], g_wv_lo[(size_t)DD * DD];
__device__ __nv_bfloat16 g_wo_hi[(size_t)DD * DD], g_wo_lo[(size_t)DD * DD];
__device__ __nv_bfloat16 g_xn_hi[(size_t)MTOT * DD];
__device__ __nv_bfloat16 g_xn_lo[(size_t)MTOT * DD];

// ---------------------------------------------------------------------------
// PTX helpers (base-target: mma.sync / ldmatrix / cp.async)
// ---------------------------------------------------------------------------
__device__ __forceinline__ uint32_t smem_u32(const void* p) {
    uint32_t a;
    asm("{ .reg .u64 t; cvta.to.shared.u64 t, %1; cvt.u32.u64 %0, t; }"
        : "=r"(a) : "l"(p));
    return a;
}

__device__ __forceinline__ void ldsm_x4(uint32_t* r, uint32_t addr) {
    asm volatile("ldmatrix.sync.aligned.m8n8.x4.shared.b16 {%0,%1,%2,%3}, [%4];"
                 : "=r"(r[0]), "=r"(r[1]), "=r"(r[2]), "=r"(r[3]) : "r"(addr));
}

__device__ __forceinline__ void ldsm_x4_t(uint32_t* r, uint32_t addr) {
    asm volatile("ldmatrix.sync.aligned.m8n8.x4.trans.shared.b16 {%0,%1,%2,%3}, [%4];"
                 : "=r"(r[0]), "=r"(r[1]), "=r"(r[2]), "=r"(r[3]) : "r"(addr));
}

__device__ __forceinline__ void mma_bf16(float* d, const uint32_t* a, const uint32_t* b) {
    asm volatile("mma.sync.aligned.m16n8k16.row.col.f32.bf16.bf16.f32 "
                 "{%0,%1,%2,%3}, {%4,%5,%6,%7}, {%8,%9}, {%0,%1,%2,%3};"
                 : "+f"(d[0]), "+f"(d[1]), "+f"(d[2]), "+f"(d[3])
                 : "r"(a[0]), "r"(a[1]), "r"(a[2]), "r"(a[3]), "r"(b[0]), "r"(b[1]));
}

#define CP_ASYNC16(dst, src) \
    asm volatile("cp.async.cg.shared.global [%0], [%1], 16;" \
                 :: "r"(dst), "l"(src) : "memory")
#define CP_COMMIT() asm volatile("cp.async.commit_group;" ::: "memory")
#define CP_WAIT1()  asm volatile("cp.async.wait_group 1;" ::: "memory")
#define CP_WAIT0()  asm volatile("cp.async.wait_group 0;" ::: "memory")

// split two floats into packed bf16x2 hi and lo
__device__ __forceinline__ void split2(float a, float b, uint32_t& hi, uint32_t& lo) {
    __nv_bfloat16 ha = __float2bfloat16(a), hb = __float2bfloat16(b);
    __nv_bfloat16 la = __float2bfloat16(a - __bfloat162float(ha));
    __nv_bfloat16 lb = __float2bfloat16(b - __bfloat162float(hb));
    __nv_bfloat162 H; H.x = ha; H.y = hb;
    __nv_bfloat162 L; L.x = la; L.y = lb;
    hi = *(uint32_t*)&H;
    lo = *(uint32_t*)&L;
}

// ---------------------------------------------------------------------------
// fp32 -> bf16 hi/lo split
// ---------------------------------------------------------------------------
__global__ __launch_bounds__(256)
void split_kernel(const float* __restrict__ src, __nv_bfloat16* __restrict__ hi,
                  __nv_bfloat16* __restrict__ lo, int n4)
{
    int i = blockIdx.x * 256 + threadIdx.x;
    if (i >= n4) return;
    float4 v = ((const float4*)src)[i];
    __nv_bfloat16 h[4], l[4];
    float x[4] = {v.x, v.y, v.z, v.w};
#pragma unroll
    for (int e = 0; e < 4; e++) {
        h[e] = __float2bfloat16(x[e]);
        l[e] = __float2bfloat16(x[e] - __bfloat162float(h[e]));
    }
    ((uint2*)hi)[i] = *(uint2*)h;
    ((uint2*)lo)[i] = *(uint2*)l;
}

// ---------------------------------------------------------------------------
// mma.sync bf16 3-split GEMM: C[8192,1024] = A[M,K] * W[N,K]^T + bias
// MODE 0: scatter (c+bias)*scale as bf16 hi/lo into [B,H,S,HD] arrays
// MODE 1: fp32 LeakyReLU + mask, row-major
// ---------------------------------------------------------------------------
#define SROW   40
#define TILE_B (128 * SROW * 2)
#define BUF_B  (4 * TILE_B)
#define NKT    (DD / 32)

__device__ __forceinline__ void stage_tile(uint32_t dst, const __nv_bfloat16* src,
                                           int rowbase, int k0, int t)
{
#pragma unroll
    for (int i = 0; i < 2; i++) {
        int id  = t + i * 256;
        int row = id >> 2;
        int c8  = (id & 3) * 8;
        const __nv_bfloat16* g = src + (size_t)(rowbase + row) * DD + k0 + c8;
        CP_ASYNC16(dst + row * (SROW * 2) + c8 * 2, g);
    }
}

template <int MODE>
__global__ __launch_bounds__(256, 1)
void gemm_mma(const __nv_bfloat16* __restrict__ Ahi, const __nv_bfloat16* __restrict__ Alo,
              const __nv_bfloat16* __restrict__ Bhi, const __nv_bfloat16* __restrict__ Blo,
              const float* __restrict__ bias, const float* __restrict__ mask,
              float* __restrict__ out,
              __nv_bfloat16* __restrict__ out_hi, __nv_bfloat16* __restrict__ out_lo,
              float scale)
{
    extern __shared__ __align__(128) char smem[];
    const uint32_t sb = smem_u32(smem);
    const int t    = threadIdx.x;
    const int wid  = t >> 5;
    const int lane = t & 31;
    const int brow = blockIdx.y * 128;
    const int bcol = blockIdx.x * 128;
    const int wm = wid & 1;
    const int wn = wid >> 1;

    stage_tile(sb + 0 * TILE_B, Ahi, brow, 0, t);
    stage_tile(sb + 1 * TILE_B, Alo, brow, 0, t);
    stage_tile(sb + 2 * TILE_B, Bhi, bcol, 0, t);
    stage_tile(sb + 3 * TILE_B, Blo, bcol, 0, t);
    CP_COMMIT();

    float acc[4][4][4];
#pragma unroll
    for (int mt = 0; mt < 4; mt++)
#pragma unroll
        for (int nt = 0; nt < 4; nt++)
#pragma unroll
            for (int e = 0; e < 4; e++) acc[mt][nt][e] = 0.0f;

    const int sub = lane >> 3;
    const int lr  = lane & 7;
    const int a_roff = lr + (sub & 1) * 8;
    const int a_koff = (sub >> 1) * 16;
    const int b_roff = lr + (sub >> 1) * 8;
    const int b_koff = (sub & 1) * 16;

    for (int kt = 0; kt < NKT; kt++) {
        if (kt + 1 < NKT) {
            const uint32_t nb = sb + ((kt + 1) & 1) * BUF_B;
            const int k0 = (kt + 1) * 32;
            stage_tile(nb + 0 * TILE_B, Ahi, brow, k0, t);
            stage_tile(nb + 1 * TILE_B, Alo, brow, k0, t);
            stage_tile(nb + 2 * TILE_B, Bhi, bcol, k0, t);
            stage_tile(nb + 3 * TILE_B, Blo, bcol, k0, t);
            CP_COMMIT();
            CP_WAIT1();
        } else {
            CP_WAIT0();
        }
        __syncthreads();

        const uint32_t bufb = sb + (kt & 1) * BUF_B;

#pragma unroll
        for (int ks = 0; ks < 2; ks++) {
            const int ksb = ks * 32;
            uint32_t bh[2][4], bl[2][4];
#pragma unroll
            for (int np = 0; np < 2; np++) {
                const int nrow = wn * 32 + np * 16 + b_roff;
                ldsm_x4(bh[np], bufb + 2 * TILE_B + nrow * (SROW * 2) + ksb + b_koff);
                ldsm_x4(bl[np], bufb + 3 * TILE_B + nrow * (SROW * 2) + ksb + b_koff);
            }
#pragma unroll
            for (int mt = 0; mt < 4; mt++) {
                const int mrow = wm * 64 + mt * 16 + a_roff;
                uint32_t ah[4], al[4];
                ldsm_x4(ah, bufb + 0 * TILE_B + mrow * (SROW * 2) + ksb + a_koff);
                ldsm_x4(al, bufb + 1 * TILE_B + mrow * (SROW * 2) + ksb + a_koff);
#pragma unroll
                for (int nt = 0; nt < 4; nt++) {
                    const uint32_t* bhp = &bh[nt >> 1][(nt & 1) * 2];
                    const uint32_t* blp = &bl[nt >> 1][(nt & 1) * 2];
                    mma_bf16(acc[mt][nt], ah, bhp);
                    mma_bf16(acc[mt][nt], ah, blp);
                    mma_bf16(acc[mt][nt], al, bhp);
                }
            }
        }
        __syncthreads();
    }

    const int g  = lane >> 2;
    const int tq = lane & 3;
#pragma unroll
    for (int mt = 0; mt < 4; mt++) {
        const int r0 = brow + wm * 64 + mt * 16 + g;
        float mr0 = 1.0f, mr1 = 1.0f;
        if (MODE == 1) { mr0 = mask[r0]; mr1 = mask[r0 + 8]; }
#pragma unroll
        for (int nt = 0; nt < 4; nt++) {
            const int c = bcol + wn * 32 + nt * 8 + tq * 2;
            const float b0 = bias[c], b1 = bias[c + 1];
            float2 v0, v1;
            v0.x = acc[mt][nt][0] + b0; v0.y = acc[mt][nt][1] + b1;
            v1.x = acc[mt][nt][2] + b0; v1.y = acc[mt][nt][3] + b1;
            if (MODE == 0) {
                v0.x *= scale; v0.y *= scale; v1.x *= scale; v1.y *= scale;
                const int h  = c >> 6;
                const int hd = c & (HDIM - 1);
                const int bi = r0 >> 11;
                const int s0 = r0 & (SS - 1);
                const size_t base = ((size_t)(bi * HH + h) * SS) * HDIM + hd;
                uint32_t h0, l0, h1, l1;
                split2(v0.x, v0.y, h0, l0);
                split2(v1.x, v1.y, h1, l1);
                *(uint32_t*)&out_hi[base + (size_t)s0 * HDIM] = h0;
                *(uint32_t*)&out_lo[base + (size_t)s0 * HDIM] = l0;
                *(uint32_t*)&out_hi[base + (size_t)(s0 + 8) * HDIM] = h1;
                *(uint32_t*)&out_lo[base + (size_t)(s0 + 8) * HDIM] = l1;
            } else {
                if (v0.x < 0.0f) v0.x *= 0.01f;
                if (v0.y < 0.0f) v0.y *= 0.01f;
                if (v1.x < 0.0f) v1.x *= 0.01f;
                if (v1.y < 0.0f) v1.y *= 0.01f;
                v0.x *= mr0; v0.y *= mr0;
                v1.x *= mr1; v1.y *= mr1;
                *(float2*)&out[(size_t)r0 * DD + c] = v0;
                *(float2*)&out[(size_t)(r0 + 8) * DD + c] = v1;
            }
        }
    }
}

// ---------------------------------------------------------------------------
// Flash attention with mma.sync bf16 3-split.
// Block: 128 q-rows x (b,h). 8 warps, each 16 q-rows. K/V tiles of 128 keys,
// cp.async double-buffered. Online softmax in registers.
// ---------------------------------------------------------------------------
#define BQ    128
#define BK    128
#define AP    72                       // bf16 elems per padded smem row
#define ROWB  (AP * 2)                 // 144 bytes
#define ATILE (BQ * ROWB)              // 18432 bytes per operand tile
// smem layout offsets (bytes)
#define OFF_Q  0
#define OFF_K  (2 * ATILE)             // 36864
#define OFF_V  (OFF_K + 4 * ATILE)     // 110592 (2 bufs x hi/lo)
#define OFF_M  (OFF_V + 4 * ATILE)     // 184320 (2 bufs x 128 floats)
#define SM_ATTN (OFF_M + 2 * 512)      // 185344

__device__ __forceinline__ void stage_att(uint32_t dst, const __nv_bfloat16* src,
                                          size_t gbase, int t)
{
#pragma unroll
    for (int i = 0; i < 4; i++) {
        int id  = t + i * 256;
        int row = id >> 3;
        int c8  = (id & 7) * 8;
        CP_ASYNC16(dst + row * ROWB + c8 * 2, src + gbase + (size_t)row * HDIM + c8);
    }
}

__global__ __launch_bounds__(256, 1)
void attn_mma(const float* __restrict__ mask, float* __restrict__ ctx)
{
    extern __shared__ __align__(128) char smem[];
    const uint32_t sb = smem_u32(smem);
    const int t    = threadIdx.x;
    const int wid  = t >> 5;
    const int lane = t & 31;
    const int qt = blockIdx.x;
    const int h  = blockIdx.y;
    const int b  = blockIdx.z;

    const int gidx = lane >> 2;
    const int tq   = lane & 3;
    const int sub  = lane >> 3;
    const int lr   = lane & 7;
    const int a_roff = lr + (sub & 1) * 8;
    const int a_koff = (sub >> 1) * 16;
    const int b_roff = lr + (sub >> 1) * 8;
    const int b_koff = (sub & 1) * 16;
    // V trans-ldsm lane mapping: tiles (k0-7,n0-7),(k8-15,n0-7),(k0-7,n8-15),(k8-15,n8-15)
    const int v_koff = lr + ((lane >> 3) & 1) * 8;
    const int v_nbyte = (lane >> 4) * 16;

    const size_t head = ((size_t)(b * HH + h) * SS) * HDIM;
    const size_t qg = head + (size_t)qt * BQ * HDIM;

    // prologue: Q hi/lo + kt0 K/V/mask
    stage_att(sb + OFF_Q,           g_qh, qg, t);
    stage_att(sb + OFF_Q + ATILE,   g_ql, qg, t);
    stage_att(sb + OFF_K,           g_kh, head, t);
    stage_att(sb + OFF_K + ATILE,   g_kl, head, t);
    stage_att(sb + OFF_V,           g_vh, head, t);
    stage_att(sb + OFF_V + ATILE,   g_vl, head, t);
    if (t < 32) CP_ASYNC16(sb + OFF_M + t * 16, mask + b * SS + t * 4);
    CP_COMMIT();

    float oacc[8][4];
#pragma unroll
    for (int nt = 0; nt < 8; nt++)
#pragma unroll
        for (int e = 0; e < 4; e++) oacc[nt][e] = 0.0f;
    float m0 = -1e30f, m1 = -1e30f, l0 = 0.0f, l1 = 0.0f;

    const uint32_t qrow_base = sb + OFF_Q + (wid * 16 + a_roff) * ROWB + a_koff;

    for (int kt = 0; kt < SS / BK; kt++) {
        if (kt + 1 < SS / BK) {
            const uint32_t kb = sb + OFF_K + ((kt + 1) & 1) * 2 * ATILE;
            const uint32_t vb = sb + OFF_V + ((kt + 1) & 1) * 2 * ATILE;
            const size_t kg = head + (size_t)(kt + 1) * BK * HDIM;
            stage_att(kb,          g_kh, kg, t);
            stage_att(kb + ATILE,  g_kl, kg, t);
            stage_att(vb,          g_vh, kg, t);
            stage_att(vb + ATILE,  g_vl, kg, t);
            if (t < 32)
                CP_ASYNC16(sb + OFF_M + ((kt + 1) & 1) * 512 + t * 16,
                           mask + b * SS + (kt + 1) * BK + t * 4);
            CP_COMMIT();
            CP_WAIT1();
        } else {
            CP_WAIT0();
        }
        __syncthreads();

        const uint32_t kbuf = sb + OFF_K + (kt & 1) * 2 * ATILE;
        const uint32_t vbuf = sb + OFF_V + (kt & 1) * 2 * ATILE;
        const float* mbuf = (const float*)(smem + OFF_M + (kt & 1) * 512);

        // ---- S = Q K^T (16 n8-tiles of 8 keys each) ----
        float sacc[16][4];
#pragma unroll
        for (int nt = 0; nt < 16; nt++)
#pragma unroll
            for (int e = 0; e < 4; e++) sacc[nt][e] = 0.0f;

#pragma unroll
        for (int kc = 0; kc < 4; kc++) {
            uint32_t ah[4], al[4];
            ldsm_x4(ah, qrow_base + kc * 32);
            ldsm_x4(al, qrow_base + ATILE + kc * 32);
#pragma unroll
            for (int np = 0; np < 8; np++) {
                uint32_t bh[4], bl[4];
                const uint32_t kaddr = kbuf + (np * 16 + b_roff) * ROWB + kc * 32 + b_koff;
                ldsm_x4(bh, kaddr);
                ldsm_x4(bl, kaddr + ATILE);
#pragma unroll
                for (int half = 0; half < 2; half++) {
                    float* d = sacc[np * 2 + half];
                    mma_bf16(d, ah, &bh[half * 2]);
                    mma_bf16(d, ah, &bl[half * 2]);
                    mma_bf16(d, al, &bh[half * 2]);
                }
            }
        }

        // ---- add mask, online softmax (rows g, g+8) ----
        float mx0 = -1e30f, mx1 = -1e30f;
#pragma unroll
        for (int nt = 0; nt < 16; nt++) {
            const int col = nt * 8 + tq * 2;
            const float ma0 = (1.0f - mbuf[col]) * -10000.0f;
            const float ma1 = (1.0f - mbuf[col + 1]) * -10000.0f;
            sacc[nt][0] += ma0; sacc[nt][1] += ma1;
            sacc[nt][2] += ma0; sacc[nt][3] += ma1;
            mx0 = fmaxf(mx0, fmaxf(sacc[nt][0], sacc[nt][1]));
            mx1 = fmaxf(mx1, fmaxf(sacc[nt][2], sacc[nt][3]));
        }
        mx0 = fmaxf(mx0, __shfl_xor_sync(0xffffffffu, mx0, 1));
        mx0 = fmaxf(mx0, __shfl_xor_sync(0xffffffffu, mx0, 2));
        mx1 = fmaxf(mx1, __shfl_xor_sync(0xffffffffu, mx1, 1));
        mx1 = fmaxf(mx1, __shfl_xor_sync(0xffffffffu, mx1, 2));

        const float mn0 = fmaxf(m0, mx0);
        const float mn1 = fmaxf(m1, mx1);
        const float al0 = __expf(m0 - mn0);
        const float al1 = __expf(m1 - mn1);
        m0 = mn0; m1 = mn1;

        float rs0 = 0.0f, rs1 = 0.0f;
#pragma unroll
        for (int nt = 0; nt < 16; nt++) {
            sacc[nt][0] = __expf(sacc[nt][0] - mn0);
            sacc[nt][1] = __expf(sacc[nt][1] - mn0);
            sacc[nt][2] = __expf(sacc[nt][2] - mn1);
            sacc[nt][3] = __expf(sacc[nt][3] - mn1);
            rs0 += sacc[nt][0] + sacc[nt][1];
            rs1 += sacc[nt][2] + sacc[nt][3];
        }
        rs0 += __shfl_xor_sync(0xffffffffu, rs0, 1);
        rs0 += __shfl_xor_sync(0xffffffffu, rs0, 2);
        rs1 += __shfl_xor_sync(0xffffffffu, rs1, 1);
        rs1 += __shfl_xor_sync(0xffffffffu, rs1, 2);
        l0 = l0 * al0 + rs0;
        l1 = l1 * al1 + rs1;

#pragma unroll
        for (int nt = 0; nt < 8; nt++) {
            oacc[nt][0] *= al0; oacc[nt][1] *= al0;
            oacc[nt][2] *= al1; oacc[nt][3] *= al1;
        }

        // ---- O += P V (8 k16 chunks over 128 keys) ----
#pragma unroll
        for (int j = 0; j < 8; j++) {
            uint32_t ph[4], pl[4];
            split2(sacc[2*j][0],   sacc[2*j][1],   ph[0], pl[0]);
            split2(sacc[2*j][2],   sacc[2*j][3],   ph[1], pl[1]);
            split2(sacc[2*j+1][0], sacc[2*j+1][1], ph[2], pl[2]);
            split2(sacc[2*j+1][2], sacc[2*j+1][3], ph[3], pl[3]);
#pragma unroll
            for (int np = 0; np < 4; np++) {
                uint32_t bvh[4], bvl[4];
                const uint32_t vaddr = vbuf + (j * 16 + v_koff) * ROWB + np * 32 + v_nbyte;
                ldsm_x4_t(bvh, vaddr);
                ldsm_x4_t(bvl, vaddr + ATILE);
#pragma unroll
                for (int half = 0; half < 2; half++) {
                    float* d = oacc[np * 2 + half];
                    mma_bf16(d, ph, &bvh[half * 2]);
                    mma_bf16(d, ph, &bvl[half * 2]);
                    mma_bf16(d, pl, &bvh[half * 2]);
                }
            }
        }
        __syncthreads();
    }

    // epilogue: O / l -> ctx [B,S,D]
    const float inv0 = 1.0f / l0;
    const float inv1 = 1.0f / l1;
    const int row0 = qt * BQ + wid * 16 + gidx;
#pragma unroll
    for (int nt = 0; nt < 8; nt++) {
        const int col = h * HDIM + nt * 8 + tq * 2;
        float2 v0, v1;
        v0.x = oacc[nt][0] * inv0; v0.y = oacc[nt][1] * inv0;
        v1.x = oacc[nt][2] * inv1; v1.y = oacc[nt][3] * inv1;
        *(float2*)&ctx[((size_t)b * SS + row0) * DD + col] = v0;
        *(float2*)&ctx[((size_t)b * SS + row0 + 8) * DD + col] = v1;
    }
}

// ---------------------------------------------------------------------------
// Residual add + LayerNorm -> bf16 hi/lo split output
// ---------------------------------------------------------------------------
__global__ __launch_bounds__(256)
void ln_kernel(const float* __restrict__ x0, const float* __restrict__ gam,
               const float* __restrict__ bet)
{
    __shared__ float red[16];
    const int row = blockIdx.x;
    const int t = threadIdx.x;
    const float* cptr = g_ctx + (size_t)row * DD;
    const float* xptr = x0 + (size_t)row * DD;

    float v[4];
    float sum = 0.0f, sq = 0.0f;
#pragma unroll
    for (int e = 0; e < 4; e++) {
        int idx = e * 256 + t;
        float x = cptr[idx] + xptr[idx];
        v[e] = x;
        sum += x;
        sq += x * x;
    }
#pragma unroll
    for (int off = 16; off; off >>= 1) {
        sum += __shfl_xor_sync(0xffffffffu, sum, off);
        sq  += __shfl_xor_sync(0xffffffffu, sq, off);
    }
    const int w = t >> 5;
    if ((t & 31) == 0) { red[w] = sum; red[8 + w] = sq; }
    __syncthreads();
    float tsum = 0.0f, tsq = 0.0f;
#pragma unroll
    for (int i = 0; i < 8; i++) { tsum += red[i]; tsq += red[8 + i]; }
    const float mu = tsum * (1.0f / DD);
    const float var = tsq * (1.0f / DD) - mu * mu;
    const float rs = rsqrtf(var + 1e-5f);

#pragma unroll
    for (int e = 0; e < 4; e++) {
        int idx = e * 256 + t;
        float y = (v[e] - mu) * rs * gam[idx] + bet[idx];
        __nv_bfloat16 hh = __float2bfloat16(y);
        g_xn_hi[(size_t)row * DD + idx] = hh;
        g_xn_lo[(size_t)row * DD + idx] = __float2bfloat16(y - __bfloat162float(hh));
    }
}

// ---------------------------------------------------------------------------
extern "C" void kernel_launch(void* const* d_in, const int* in_sizes, int n_in,
                              void* d_out, int out_size)
{
    (void)in_sizes; (void)n_in; (void)out_size;
    const float* inputs = (const float*)d_in[0];
    const float* mask   = (const float*)d_in[1];
    const float* Wq     = (const float*)d_in[2];
    const float* bq     = (const float*)d_in[3];
    const float* Wk     = (const float*)d_in[4];
    const float* bk     = (const float*)d_in[5];
    const float* Wv     = (const float*)d_in[6];
    const float* bv     = (const float*)d_in[7];
    const float* Wo     = (const float*)d_in[8];
    const float* bo     = (const float*)d_in[9];
    const float* ln_g   = (const float*)d_in[10];
    const float* ln_b   = (const float*)d_in[11];
    float* out = (float*)d_out;

    float *ctxp;
    __nv_bfloat16 *qh, *ql, *kh, *kl, *vh, *vl;
    __nv_bfloat16 *inh, *inl, *wqh, *wql, *wkh, *wkl, *wvh, *wvl, *woh, *wol, *xnh, *xnl;
    cudaGetSymbolAddress((void**)&ctxp, g_ctx);
    cudaGetSymbolAddress((void**)&qh, g_qh);
    cudaGetSymbolAddress((void**)&ql, g_ql);
    cudaGetSymbolAddress((void**)&kh, g_kh);
    cudaGetSymbolAddress((void**)&kl, g_kl);
    cudaGetSymbolAddress((void**)&vh, g_vh);
    cudaGetSymbolAddress((void**)&vl, g_vl);
    cudaGetSymbolAddress((void**)&inh, g_in_hi);
    cudaGetSymbolAddress((void**)&inl, g_in_lo);
    cudaGetSymbolAddress((void**)&wqh, g_wq_hi);
    cudaGetSymbolAddress((void**)&wql, g_wq_lo);
    cudaGetSymbolAddress((void**)&wkh, g_wk_hi);
    cudaGetSymbolAddress((void**)&wkl, g_wk_lo);
    cudaGetSymbolAddress((void**)&wvh, g_wv_hi);
    cudaGetSymbolAddress((void**)&wvl, g_wv_lo);
    cudaGetSymbolAddress((void**)&woh, g_wo_hi);
    cudaGetSymbolAddress((void**)&wol, g_wo_lo);
    cudaGetSymbolAddress((void**)&xnh, g_xn_hi);
    cudaGetSymbolAddress((void**)&xnl, g_xn_lo);

    const int smem_gemm = 2 * BUF_B;
    cudaFuncSetAttribute((const void*)gemm_mma<0>,
                         cudaFuncAttributeMaxDynamicSharedMemorySize, smem_gemm);
    cudaFuncSetAttribute((const void*)gemm_mma<1>,
                         cudaFuncAttributeMaxDynamicSharedMemorySize, smem_gemm);
    cudaFuncSetAttribute((const void*)attn_mma,
                         cudaFuncAttributeMaxDynamicSharedMemorySize, SM_ATTN);

    split_kernel<<<(MTOT * DD / 4) / 256, 256>>>(inputs, inh, inl, MTOT * DD / 4);
    split_kernel<<<(DD * DD / 4) / 256, 256>>>(Wq, wqh, wql, DD * DD / 4);
    split_kernel<<<(DD * DD / 4) / 256, 256>>>(Wk, wkh, wkl, DD * DD / 4);
    split_kernel<<<(DD * DD / 4) / 256, 256>>>(Wv, wvh, wvl, DD * DD / 4);
    split_kernel<<<(DD * DD / 4) / 256, 256>>>(Wo, woh, wol, DD * DD / 4);

    dim3 ggrid(DD / 128, MTOT / 128);
    gemm_mma<0><<<ggrid, 256, smem_gemm>>>(inh, inl, wqh, wql, bq, nullptr,
                                           nullptr, qh, ql, 0.125f);
    gemm_mma<0><<<ggrid, 256, smem_gemm>>>(inh, inl, wkh, wkl, bk, nullptr,
                                           nullptr, kh, kl, 1.0f);
    gemm_mma<0><<<ggrid, 256, smem_gemm>>>(inh, inl, wvh, wvl, bv, nullptr,
                                           nullptr, vh, vl, 1.0f);

    attn_mma<<<dim3(SS / BQ, HH, BB), 256, SM_ATTN>>>(mask, ctxp);

    ln_kernel<<<MTOT, 256>>>(inputs, ln_g, ln_b);

    gemm_mma<1><<<ggrid, 256, smem_gemm>>>(xnh, xnl, woh, wol, bo, mask,
                                           out, nullptr, nullptr, 1.0f);
}

// round 7
// speedup vs baseline: 3.4824x; 1.2220x over previous
#include <cuda_runtime.h>
#include <cuda_bf16.h>
#include <cstdint>

// Problem constants
#define BB   4
#define SS   2048
#define DD   1024
#define HH   16
#define HDIM 64
#define MTOT (BB * SS)   // 8192

// ---------------------------------------------------------------------------
// Scratch (__device__ globals; allocation is forbidden)
// ---------------------------------------------------------------------------
__device__ float g_ctx[(size_t)MTOT * DD];

__device__ __nv_bfloat16 g_qh[(size_t)BB * HH * SS * HDIM], g_ql[(size_t)BB * HH * SS * HDIM];
__device__ __nv_bfloat16 g_kh[(size_t)BB * HH * SS * HDIM], g_kl[(size_t)BB * HH * SS * HDIM];
__device__ __nv_bfloat16 g_vh[(size_t)BB * HH * SS * HDIM], g_vl[(size_t)BB * HH * SS * HDIM];

__device__ __nv_bfloat16 g_in_hi[(size_t)MTOT * DD];
__device__ __nv_bfloat16 g_in_lo[(size_t)MTOT * DD];
__device__ __nv_bfloat16 g_wq_hi[(size_t)DD * DD], g_wq_lo[(size_t)DD * DD];
__device__ __nv_bfloat16 g_wk_hi[(size_t)DD * DD], g_wk_lo[(size_t)DD * DD];
__device__ __nv_bfloat16 g_wv_hi[(size_t)DD * DD], g_wv_lo[(size_t)DD * DD];
__device__ __nv_bfloat16 g_wo_hi[(size_t)DD * DD], g_wo_lo[(size_t)DD * DD];
__device__ __nv_bfloat16 g_xn_hi[(size_t)MTOT * DD];
__device__ __nv_bfloat16 g_xn_lo[(size_t)MTOT * DD];

// ---------------------------------------------------------------------------
// PTX helpers
// ---------------------------------------------------------------------------
__device__ __forceinline__ uint32_t smem_u32(const void* p) {
    uint32_t a;
    asm("{ .reg .u64 t; cvta.to.shared.u64 t, %1; cvt.u32.u64 %0, t; }"
        : "=r"(a) : "l"(p));
    return a;
}

__device__ __forceinline__ void ldsm_x4(uint32_t* r, uint32_t addr) {
    asm volatile("ldmatrix.sync.aligned.m8n8.x4.shared.b16 {%0,%1,%2,%3}, [%4];"
                 : "=r"(r[0]), "=r"(r[1]), "=r"(r[2]), "=r"(r[3]) : "r"(addr));
}

__device__ __forceinline__ void ldsm_x4_t(uint32_t* r, uint32_t addr) {
    asm volatile("ldmatrix.sync.aligned.m8n8.x4.trans.shared.b16 {%0,%1,%2,%3}, [%4];"
                 : "=r"(r[0]), "=r"(r[1]), "=r"(r[2]), "=r"(r[3]) : "r"(addr));
}

__device__ __forceinline__ void mma_bf16(float* d, const uint32_t* a, const uint32_t* b) {
    asm volatile("mma.sync.aligned.m16n8k16.row.col.f32.bf16.bf16.f32 "
                 "{%0,%1,%2,%3}, {%4,%5,%6,%7}, {%8,%9}, {%0,%1,%2,%3};"
                 : "+f"(d[0]), "+f"(d[1]), "+f"(d[2]), "+f"(d[3])
                 : "r"(a[0]), "r"(a[1]), "r"(a[2]), "r"(a[3]), "r"(b[0]), "r"(b[1]));
}

#define CP_ASYNC16(dst, src) \
    asm volatile("cp.async.cg.shared.global [%0], [%1], 16;" \
                 :: "r"(dst), "l"(src) : "memory")
#define CP_COMMIT() asm volatile("cp.async.commit_group;" ::: "memory")
#define CP_WAIT0()  asm volatile("cp.async.wait_group 0;" ::: "memory")

// smem swizzles (applied to tile-relative byte offsets)
__device__ __forceinline__ uint32_t sw64(uint32_t o)  { return o ^ (((o >> 7) & 3) << 4); }
__device__ __forceinline__ uint32_t sw128(uint32_t o) { return o ^ ((o >> 3) & 0x70); }

// split two floats into packed bf16x2 hi and lo
__device__ __forceinline__ void split2(float a, float b, uint32_t& hi, uint32_t& lo) {
    __nv_bfloat16 ha = __float2bfloat16(a), hb = __float2bfloat16(b);
    __nv_bfloat16 la = __float2bfloat16(a - __bfloat162float(ha));
    __nv_bfloat16 lb = __float2bfloat16(b - __bfloat162float(hb));
    __nv_bfloat162 H; H.x = ha; H.y = hb;
    __nv_bfloat162 L; L.x = la; L.y = lb;
    hi = *(uint32_t*)&H;
    lo = *(uint32_t*)&L;
}

// ---------------------------------------------------------------------------
// fp32 -> bf16 hi/lo split
// ---------------------------------------------------------------------------
__global__ __launch_bounds__(256)
void split_kernel(const float* __restrict__ src, __nv_bfloat16* __restrict__ hi,
                  __nv_bfloat16* __restrict__ lo, int n4)
{
    int i = blockIdx.x * 256 + threadIdx.x;
    if (i >= n4) return;
    float4 v = ((const float4*)src)[i];
    __nv_bfloat16 h[4], l[4];
    float x[4] = {v.x, v.y, v.z, v.w};
#pragma unroll
    for (int e = 0; e < 4; e++) {
        h[e] = __float2bfloat16(x[e]);
        l[e] = __float2bfloat16(x[e] - __bfloat162float(h[e]));
    }
    ((uint2*)hi)[i] = *(uint2*)h;
    ((uint2*)lo)[i] = *(uint2*)l;
}

// ---------------------------------------------------------------------------
// mma.sync bf16 3-split GEMM: C[8192,1024] = A[M,K] * W[N,K]^T + bias
// 128x128 tile, 8 warps (64x32 each), BK=32, swizzled 64B rows, 2 CTAs/SM.
// Single __syncthreads per k-iteration; term-major MMA ordering.
// ---------------------------------------------------------------------------
#define GK_TILE 8192                 // 128 rows * 64 B
#define GK_BUF  (4 * GK_TILE)        // 32768
#define SM_GEMM (2 * GK_BUF)         // 65536
#define NKT     (DD / 32)            // 32

__device__ __forceinline__ void stage_g(uint32_t dst, const __nv_bfloat16* src,
                                        int rowbase, int k0, int t)
{
#pragma unroll
    for (int i = 0; i < 2; i++) {
        int id  = t + i * 256;
        int row = id >> 2;
        int c   = (id & 3);
        CP_ASYNC16(dst + sw64((uint32_t)(row * 64 + c * 16)),
                   src + (size_t)(rowbase + row) * DD + k0 + c * 8);
    }
}

template <int MODE>
__global__ __launch_bounds__(256, 2)
void gemm_mma(const __nv_bfloat16* __restrict__ Ahi, const __nv_bfloat16* __restrict__ Alo,
              const __nv_bfloat16* __restrict__ Bhi, const __nv_bfloat16* __restrict__ Blo,
              const float* __restrict__ bias, const float* __restrict__ mask,
              float* __restrict__ out,
              __nv_bfloat16* __restrict__ out_hi, __nv_bfloat16* __restrict__ out_lo,
              float scale)
{
    extern __shared__ __align__(128) char smem[];
    const uint32_t sb = smem_u32(smem);
    const int t    = threadIdx.x;
    const int wid  = t >> 5;
    const int lane = t & 31;
    const int brow = blockIdx.y * 128;
    const int bcol = blockIdx.x * 128;
    const int wm = wid & 1;
    const int wn = wid >> 1;

    const int sub = lane >> 3;
    const int lr  = lane & 7;
    const int a_roff = lr + (sub & 1) * 8;
    const int a_koff = (sub >> 1) * 16;
    const int b_roff = lr + (sub >> 1) * 8;
    const int b_koff = (sub & 1) * 16;

    // prologue: stage k-tile 0 into buffer 0
    stage_g(sb + 0 * GK_TILE, Ahi, brow, 0, t);
    stage_g(sb + 1 * GK_TILE, Alo, brow, 0, t);
    stage_g(sb + 2 * GK_TILE, Bhi, bcol, 0, t);
    stage_g(sb + 3 * GK_TILE, Blo, bcol, 0, t);
    CP_COMMIT();

    float acc[4][4][4];
#pragma unroll
    for (int mt = 0; mt < 4; mt++)
#pragma unroll
        for (int nt = 0; nt < 4; nt++)
#pragma unroll
            for (int e = 0; e < 4; e++) acc[mt][nt][e] = 0.0f;

    for (int kt = 0; kt < NKT; kt++) {
        CP_WAIT0();
        __syncthreads();
        if (kt + 1 < NKT) {
            const uint32_t nb = sb + ((kt + 1) & 1) * GK_BUF;
            const int k0 = (kt + 1) * 32;
            stage_g(nb + 0 * GK_TILE, Ahi, brow, k0, t);
            stage_g(nb + 1 * GK_TILE, Alo, brow, k0, t);
            stage_g(nb + 2 * GK_TILE, Bhi, bcol, k0, t);
            stage_g(nb + 3 * GK_TILE, Blo, bcol, k0, t);
            CP_COMMIT();
        }
        const uint32_t bufb = sb + (kt & 1) * GK_BUF;

#pragma unroll
        for (int ks = 0; ks < 2; ks++) {
            const int ksb = ks * 32;
            uint32_t bh[2][4], bl[2][4];
#pragma unroll
            for (int np = 0; np < 2; np++) {
                const uint32_t off = (uint32_t)((wn * 32 + np * 16 + b_roff) * 64 + ksb + b_koff);
                ldsm_x4(bh[np], bufb + 2 * GK_TILE + sw64(off));
                ldsm_x4(bl[np], bufb + 3 * GK_TILE + sw64(off));
            }
#pragma unroll
            for (int mp = 0; mp < 2; mp++) {
                uint32_t ah[2][4], al[2][4];
#pragma unroll
                for (int q = 0; q < 2; q++) {
                    const int mt = mp * 2 + q;
                    const uint32_t off = (uint32_t)((wm * 64 + mt * 16 + a_roff) * 64 + ksb + a_koff);
                    ldsm_x4(ah[q], bufb + 0 * GK_TILE + sw64(off));
                    ldsm_x4(al[q], bufb + 1 * GK_TILE + sw64(off));
                }
                // term-major: same-acc MMAs spaced 8 apart
#pragma unroll
                for (int q = 0; q < 2; q++)
#pragma unroll
                    for (int nt = 0; nt < 4; nt++)
                        mma_bf16(acc[mp * 2 + q][nt], ah[q], &bh[nt >> 1][(nt & 1) * 2]);
#pragma unroll
                for (int q = 0; q < 2; q++)
#pragma unroll
                    for (int nt = 0; nt < 4; nt++)
                        mma_bf16(acc[mp * 2 + q][nt], ah[q], &bl[nt >> 1][(nt & 1) * 2]);
#pragma unroll
                for (int q = 0; q < 2; q++)
#pragma unroll
                    for (int nt = 0; nt < 4; nt++)
                        mma_bf16(acc[mp * 2 + q][nt], al[q], &bh[nt >> 1][(nt & 1) * 2]);
            }
        }
    }

    const int g  = lane >> 2;
    const int tq = lane & 3;
#pragma unroll
    for (int mt = 0; mt < 4; mt++) {
        const int r0 = brow + wm * 64 + mt * 16 + g;
        float mr0 = 1.0f, mr1 = 1.0f;
        if (MODE == 1) { mr0 = mask[r0]; mr1 = mask[r0 + 8]; }
#pragma unroll
        for (int nt = 0; nt < 4; nt++) {
            const int c = bcol + wn * 32 + nt * 8 + tq * 2;
            const float b0 = bias[c], b1 = bias[c + 1];
            float2 v0, v1;
            v0.x = acc[mt][nt][0] + b0; v0.y = acc[mt][nt][1] + b1;
            v1.x = acc[mt][nt][2] + b0; v1.y = acc[mt][nt][3] + b1;
            if (MODE == 0) {
                v0.x *= scale; v0.y *= scale; v1.x *= scale; v1.y *= scale;
                const int h  = c >> 6;
                const int hd = c & (HDIM - 1);
                const int bi = r0 >> 11;
                const int s0 = r0 & (SS - 1);
                const size_t base = ((size_t)(bi * HH + h) * SS) * HDIM + hd;
                uint32_t h0, l0, h1, l1;
                split2(v0.x, v0.y, h0, l0);
                split2(v1.x, v1.y, h1, l1);
                *(uint32_t*)&out_hi[base + (size_t)s0 * HDIM] = h0;
                *(uint32_t*)&out_lo[base + (size_t)s0 * HDIM] = l0;
                *(uint32_t*)&out_hi[base + (size_t)(s0 + 8) * HDIM] = h1;
                *(uint32_t*)&out_lo[base + (size_t)(s0 + 8) * HDIM] = l1;
            } else {
                if (v0.x < 0.0f) v0.x *= 0.01f;
                if (v0.y < 0.0f) v0.y *= 0.01f;
                if (v1.x < 0.0f) v1.x *= 0.01f;
                if (v1.y < 0.0f) v1.y *= 0.01f;
                v0.x *= mr0; v0.y *= mr0;
                v1.x *= mr1; v1.y *= mr1;
                *(float2*)&out[(size_t)r0 * DD + c] = v0;
                *(float2*)&out[(size_t)(r0 + 8) * DD + c] = v1;
            }
        }
    }
}

// ---------------------------------------------------------------------------
// Flash attention, mma.sync bf16 3-split. BQ=128, BK=64, SW128 swizzle.
// smem 96.5KB -> 2 CTAs/SM. Single sync per k-iteration.
// ---------------------------------------------------------------------------
#define BQ     128
#define BK     64
#define QTILE  16384                 // 128 rows * 128 B
#define KVTILE 8192                  // 64 rows * 128 B
#define OFF_Q  0                     // Qhi, Qlo (2 * 16384)
#define OFF_K  (2 * QTILE)           // 2 bufs x (hi,lo) = 2*16384
#define OFF_V  (OFF_K + 4 * KVTILE)  // same
#define OFF_M  (OFF_V + 4 * KVTILE)  // 2 bufs x 256 B
#define SM_ATTN (OFF_M + 2 * 256)    // 98816

__device__ __forceinline__ void stage_q(uint32_t dst, const __nv_bfloat16* src,
                                        size_t gbase, int t)
{
#pragma unroll
    for (int i = 0; i < 4; i++) {
        int id  = t + i * 256;
        int row = id >> 3;
        int c   = id & 7;
        CP_ASYNC16(dst + sw128((uint32_t)(row * 128 + c * 16)),
                   src + gbase + (size_t)row * HDIM + c * 8);
    }
}

__device__ __forceinline__ void stage_kv(uint32_t dst, const __nv_bfloat16* src,
                                         size_t gbase, int t)
{
#pragma unroll
    for (int i = 0; i < 2; i++) {
        int id  = t + i * 256;
        int row = id >> 3;
        int c   = id & 7;
        CP_ASYNC16(dst + sw128((uint32_t)(row * 128 + c * 16)),
                   src + gbase + (size_t)row * HDIM + c * 8);
    }
}

__global__ __launch_bounds__(256, 2)
void attn_mma(const float* __restrict__ mask, float* __restrict__ ctx)
{
    extern __shared__ __align__(128) char smem[];
    const uint32_t sb = smem_u32(smem);
    const int t    = threadIdx.x;
    const int wid  = t >> 5;
    const int lane = t & 31;
    const int qt = blockIdx.x;
    const int h  = blockIdx.y;
    const int b  = blockIdx.z;

    const int gidx = lane >> 2;
    const int tq   = lane & 3;
    const int sub  = lane >> 3;
    const int lr   = lane & 7;
    const int a_roff = lr + (sub & 1) * 8;
    const int a_koff = (sub >> 1) * 16;
    const int b_roff = lr + (sub >> 1) * 8;
    const int b_koff = (sub & 1) * 16;
    const int v_koff = lr + ((lane >> 3) & 1) * 8;
    const int v_nbyte = (lane >> 4) * 16;

    const size_t head = ((size_t)(b * HH + h) * SS) * HDIM;
    const size_t qg = head + (size_t)qt * BQ * HDIM;

    // prologue: Q hi/lo + kt0 K/V/mask (group 0)
    stage_q(sb + OFF_Q,          g_qh, qg, t);
    stage_q(sb + OFF_Q + QTILE,  g_ql, qg, t);
    stage_kv(sb + OFF_K,            g_kh, head, t);
    stage_kv(sb + OFF_K + KVTILE,   g_kl, head, t);
    stage_kv(sb + OFF_V,            g_vh, head, t);
    stage_kv(sb + OFF_V + KVTILE,   g_vl, head, t);
    if (t < 16) CP_ASYNC16(sb + OFF_M + t * 16, mask + b * SS + t * 4);
    CP_COMMIT();

    float oacc[8][4];
#pragma unroll
    for (int nt = 0; nt < 8; nt++)
#pragma unroll
        for (int e = 0; e < 4; e++) oacc[nt][e] = 0.0f;
    float m0 = -1e30f, m1 = -1e30f, l0 = 0.0f, l1 = 0.0f;

    for (int kt = 0; kt < SS / BK; kt++) {
        CP_WAIT0();
        __syncthreads();
        if (kt + 1 < SS / BK) {
            const uint32_t kb = sb + OFF_K + ((kt + 1) & 1) * 2 * KVTILE;
            const uint32_t vb = sb + OFF_V + ((kt + 1) & 1) * 2 * KVTILE;
            const size_t kg = head + (size_t)(kt + 1) * BK * HDIM;
            stage_kv(kb,           g_kh, kg, t);
            stage_kv(kb + KVTILE,  g_kl, kg, t);
            stage_kv(vb,           g_vh, kg, t);
            stage_kv(vb + KVTILE,  g_vl, kg, t);
            if (t < 16)
                CP_ASYNC16(sb + OFF_M + ((kt + 1) & 1) * 256 + t * 16,
                           mask + b * SS + (kt + 1) * BK + t * 4);
            CP_COMMIT();
        }
        const uint32_t kbuf = sb + OFF_K + (kt & 1) * 2 * KVTILE;
        const uint32_t vbuf = sb + OFF_V + (kt & 1) * 2 * KVTILE;
        const float* mbuf = (const float*)(smem + OFF_M + (kt & 1) * 256);

        // ---- S = Q K^T (8 n8-tiles of 8 keys) ----
        float sacc[8][4];
#pragma unroll
        for (int nt = 0; nt < 8; nt++)
#pragma unroll
            for (int e = 0; e < 4; e++) sacc[nt][e] = 0.0f;

#pragma unroll
        for (int kc = 0; kc < 4; kc++) {
            uint32_t ah[4], al[4];
            const uint32_t qoff = (uint32_t)((wid * 16 + a_roff) * 128 + kc * 32 + a_koff);
            ldsm_x4(ah, sb + OFF_Q + sw128(qoff));
            ldsm_x4(al, sb + OFF_Q + QTILE + sw128(qoff));
#pragma unroll
            for (int np = 0; np < 4; np++) {
                uint32_t bh[4], bl[4];
                const uint32_t koff = (uint32_t)((np * 16 + b_roff) * 128 + kc * 32 + b_koff);
                ldsm_x4(bh, kbuf + sw128(koff));
                ldsm_x4(bl, kbuf + KVTILE + sw128(koff));
#pragma unroll
                for (int half = 0; half < 2; half++) {
                    float* d = sacc[np * 2 + half];
                    mma_bf16(d, ah, &bh[half * 2]);
                    mma_bf16(d, ah, &bl[half * 2]);
                    mma_bf16(d, al, &bh[half * 2]);
                }
            }
        }

        // ---- add mask, online softmax ----
        float mx0 = -1e30f, mx1 = -1e30f;
#pragma unroll
        for (int nt = 0; nt < 8; nt++) {
            const int col = nt * 8 + tq * 2;
            const float ma0 = (1.0f - mbuf[col]) * -10000.0f;
            const float ma1 = (1.0f - mbuf[col + 1]) * -10000.0f;
            sacc[nt][0] += ma0; sacc[nt][1] += ma1;
            sacc[nt][2] += ma0; sacc[nt][3] += ma1;
            mx0 = fmaxf(mx0, fmaxf(sacc[nt][0], sacc[nt][1]));
            mx1 = fmaxf(mx1, fmaxf(sacc[nt][2], sacc[nt][3]));
        }
        mx0 = fmaxf(mx0, __shfl_xor_sync(0xffffffffu, mx0, 1));
        mx0 = fmaxf(mx0, __shfl_xor_sync(0xffffffffu, mx0, 2));
        mx1 = fmaxf(mx1, __shfl_xor_sync(0xffffffffu, mx1, 1));
        mx1 = fmaxf(mx1, __shfl_xor_sync(0xffffffffu, mx1, 2));

        const float mn0 = fmaxf(m0, mx0);
        const float mn1 = fmaxf(m1, mx1);
        const float al0 = __expf(m0 - mn0);
        const float al1 = __expf(m1 - mn1);
        m0 = mn0; m1 = mn1;

        float rs0 = 0.0f, rs1 = 0.0f;
#pragma unroll
        for (int nt = 0; nt < 8; nt++) {
            sacc[nt][0] = __expf(sacc[nt][0] - mn0);
            sacc[nt][1] = __expf(sacc[nt][1] - mn0);
            sacc[nt][2] = __expf(sacc[nt][2] - mn1);
            sacc[nt][3] = __expf(sacc[nt][3] - mn1);
            rs0 += sacc[nt][0] + sacc[nt][1];
            rs1 += sacc[nt][2] + sacc[nt][3];
        }
        rs0 += __shfl_xor_sync(0xffffffffu, rs0, 1);
        rs0 += __shfl_xor_sync(0xffffffffu, rs0, 2);
        rs1 += __shfl_xor_sync(0xffffffffu, rs1, 1);
        rs1 += __shfl_xor_sync(0xffffffffu, rs1, 2);
        l0 = l0 * al0 + rs0;
        l1 = l1 * al1 + rs1;

#pragma unroll
        for (int nt = 0; nt < 8; nt++) {
            oacc[nt][0] *= al0; oacc[nt][1] *= al0;
            oacc[nt][2] *= al1; oacc[nt][3] *= al1;
        }

        // ---- O += P V (4 k16 chunks over 64 keys) ----
#pragma unroll
        for (int j = 0; j < 4; j++) {
            uint32_t ph[4], pl[4];
            split2(sacc[2*j][0],   sacc[2*j][1],   ph[0], pl[0]);
            split2(sacc[2*j][2],   sacc[2*j][3],   ph[1], pl[1]);
            split2(sacc[2*j+1][0], sacc[2*j+1][1], ph[2], pl[2]);
            split2(sacc[2*j+1][2], sacc[2*j+1][3], ph[3], pl[3]);
#pragma unroll
            for (int np = 0; np < 4; np++) {
                uint32_t bvh[4], bvl[4];
                const uint32_t voff = (uint32_t)((j * 16 + v_koff) * 128 + np * 32 + v_nbyte);
                ldsm_x4_t(bvh, vbuf + sw128(voff));
                ldsm_x4_t(bvl, vbuf + KVTILE + sw128(voff));
#pragma unroll
                for (int half = 0; half < 2; half++) {
                    float* d = oacc[np * 2 + half];
                    mma_bf16(d, ph, &bvh[half * 2]);
                    mma_bf16(d, ph, &bvl[half * 2]);
                    mma_bf16(d, pl, &bvh[half * 2]);
                }
            }
        }
    }

    // epilogue: O / l -> ctx [B,S,D]
    const float inv0 = 1.0f / l0;
    const float inv1 = 1.0f / l1;
    const int row0 = qt * BQ + wid * 16 + gidx;
#pragma unroll
    for (int nt = 0; nt < 8; nt++) {
        const int col = h * HDIM + nt * 8 + tq * 2;
        float2 v0, v1;
        v0.x = oacc[nt][0] * inv0; v0.y = oacc[nt][1] * inv0;
        v1.x = oacc[nt][2] * inv1; v1.y = oacc[nt][3] * inv1;
        *(float2*)&ctx[((size_t)b * SS + row0) * DD + col] = v0;
        *(float2*)&ctx[((size_t)b * SS + row0 + 8) * DD + col] = v1;
    }
}

// ---------------------------------------------------------------------------
// Residual add + LayerNorm -> bf16 hi/lo split output
// ---------------------------------------------------------------------------
__global__ __launch_bounds__(256)
void ln_kernel(const float* __restrict__ x0, const float* __restrict__ gam,
               const float* __restrict__ bet)
{
    __shared__ float red[16];
    const int row = blockIdx.x;
    const int t = threadIdx.x;
    const float* cptr = g_ctx + (size_t)row * DD;
    const float* xptr = x0 + (size_t)row * DD;

    float v[4];
    float sum = 0.0f, sq = 0.0f;
#pragma unroll
    for (int e = 0; e < 4; e++) {
        int idx = e * 256 + t;
        float x = cptr[idx] + xptr[idx];
        v[e] = x;
        sum += x;
        sq += x * x;
    }
#pragma unroll
    for (int off = 16; off; off >>= 1) {
        sum += __shfl_xor_sync(0xffffffffu, sum, off);
        sq  += __shfl_xor_sync(0xffffffffu, sq, off);
    }
    const int w = t >> 5;
    if ((t & 31) == 0) { red[w] = sum; red[8 + w] = sq; }
    __syncthreads();
    float tsum = 0.0f, tsq = 0.0f;
#pragma unroll
    for (int i = 0; i < 8; i++) { tsum += red[i]; tsq += red[8 + i]; }
    const float mu = tsum * (1.0f / DD);
    const float var = tsq * (1.0f / DD) - mu * mu;
    const float rs = rsqrtf(var + 1e-5f);

#pragma unroll
    for (int e = 0; e < 4; e++) {
        int idx = e * 256 + t;
        float y = (v[e] - mu) * rs * gam[idx] + bet[idx];
        __nv_bfloat16 hh = __float2bfloat16(y);
        g_xn_hi[(size_t)row * DD + idx] = hh;
        g_xn_lo[(size_t)row * DD + idx] = __float2bfloat16(y - __bfloat162float(hh));
    }
}

// ---------------------------------------------------------------------------
extern "C" void kernel_launch(void* const* d_in, const int* in_sizes, int n_in,
                              void* d_out, int out_size)
{
    (void)in_sizes; (void)n_in; (void)out_size;
    const float* inputs = (const float*)d_in[0];
    const float* mask   = (const float*)d_in[1];
    const float* Wq     = (const float*)d_in[2];
    const float* bq     = (const float*)d_in[3];
    const float* Wk     = (const float*)d_in[4];
    const float* bk     = (const float*)d_in[5];
    const float* Wv     = (const float*)d_in[6];
    const float* bv     = (const float*)d_in[7];
    const float* Wo     = (const float*)d_in[8];
    const float* bo     = (const float*)d_in[9];
    const float* ln_g   = (const float*)d_in[10];
    const float* ln_b   = (const float*)d_in[11];
    float* out = (float*)d_out;

    float *ctxp;
    __nv_bfloat16 *qh, *ql, *kh, *kl, *vh, *vl;
    __nv_bfloat16 *inh, *inl, *wqh, *wql, *wkh, *wkl, *wvh, *wvl, *woh, *wol, *xnh, *xnl;
    cudaGetSymbolAddress((void**)&ctxp, g_ctx);
    cudaGetSymbolAddress((void**)&qh, g_qh);
    cudaGetSymbolAddress((void**)&ql, g_ql);
    cudaGetSymbolAddress((void**)&kh, g_kh);
    cudaGetSymbolAddress((void**)&kl, g_kl);
    cudaGetSymbolAddress((void**)&vh, g_vh);
    cudaGetSymbolAddress((void**)&vl, g_vl);
    cudaGetSymbolAddress((void**)&inh, g_in_hi);
    cudaGetSymbolAddress((void**)&inl, g_in_lo);
    cudaGetSymbolAddress((void**)&wqh, g_wq_hi);
    cudaGetSymbolAddress((void**)&wql, g_wq_lo);
    cudaGetSymbolAddress((void**)&wkh, g_wk_hi);
    cudaGetSymbolAddress((void**)&wkl, g_wk_lo);
    cudaGetSymbolAddress((void**)&wvh, g_wv_hi);
    cudaGetSymbolAddress((void**)&wvl, g_wv_lo);
    cudaGetSymbolAddress((void**)&woh, g_wo_hi);
    cudaGetSymbolAddress((void**)&wol, g_wo_lo);
    cudaGetSymbolAddress((void**)&xnh, g_xn_hi);
    cudaGetSymbolAddress((void**)&xnl, g_xn_lo);

    cudaFuncSetAttribute((const void*)gemm_mma<0>,
                         cudaFuncAttributeMaxDynamicSharedMemorySize, SM_GEMM);
    cudaFuncSetAttribute((const void*)gemm_mma<1>,
                         cudaFuncAttributeMaxDynamicSharedMemorySize, SM_GEMM);
    cudaFuncSetAttribute((const void*)attn_mma,
                         cudaFuncAttributeMaxDynamicSharedMemorySize, SM_ATTN);

    split_kernel<<<(MTOT * DD / 4) / 256, 256>>>(inputs, inh, inl, MTOT * DD / 4);
    split_kernel<<<(DD * DD / 4) / 256, 256>>>(Wq, wqh, wql, DD * DD / 4);
    split_kernel<<<(DD * DD / 4) / 256, 256>>>(Wk, wkh, wkl, DD * DD / 4);
    split_kernel<<<(DD * DD / 4) / 256, 256>>>(Wv, wvh, wvl, DD * DD / 4);
    split_kernel<<<(DD * DD / 4) / 256, 256>>>(Wo, woh, wol, DD * DD / 4);

    dim3 ggrid(DD / 128, MTOT / 128);
    gemm_mma<0><<<ggrid, 256, SM_GEMM>>>(inh, inl, wqh, wql, bq, nullptr,
                                         nullptr, qh, ql, 0.125f);
    gemm_mma<0><<<ggrid, 256, SM_GEMM>>>(inh, inl, wkh, wkl, bk, nullptr,
                                         nullptr, kh, kl, 1.0f);
    gemm_mma<0><<<ggrid, 256, SM_GEMM>>>(inh, inl, wvh, wvl, bv, nullptr,
                                         nullptr, vh, vl, 1.0f);

    attn_mma<<<dim3(SS / BQ, HH, BB), 256, SM_ATTN>>>(mask, ctxp);

    ln_kernel<<<MTOT, 256>>>(inputs, ln_g, ln_b);

    gemm_mma<1><<<ggrid, 256, SM_GEMM>>>(xnh, xnl, woh, wol, bo, mask,
                                         out, nullptr, nullptr, 1.0f);
}

// round 10
// speedup vs baseline: 4.0660x; 1.1676x over previous
#include <cuda_runtime.h>
#include <cuda_fp16.h>
#include <cstdint>

// Problem constants
#define BB   4
#define SS   2048
#define DD   1024
#define HH   16
#define HDIM 64
#define MTOT (BB * SS)   // 8192

// ---------------------------------------------------------------------------
// Scratch (__device__ globals; allocation is forbidden)
// ---------------------------------------------------------------------------
__device__ float g_ctx[(size_t)MTOT * DD];

__device__ __half g_qh[(size_t)BB * HH * SS * HDIM], g_ql[(size_t)BB * HH * SS * HDIM];
__device__ __half g_kh[(size_t)BB * HH * SS * HDIM], g_kl[(size_t)BB * HH * SS * HDIM];
__device__ __half g_vh[(size_t)BB * HH * SS * HDIM], g_vl[(size_t)BB * HH * SS * HDIM];

__device__ __half g_in_h[(size_t)MTOT * DD];
__device__ __half g_in_l[(size_t)MTOT * DD];
__device__ __half g_wq_h[(size_t)DD * DD], g_wq_l[(size_t)DD * DD];
__device__ __half g_wk_h[(size_t)DD * DD], g_wk_l[(size_t)DD * DD];
__device__ __half g_wv_h[(size_t)DD * DD], g_wv_l[(size_t)DD * DD];
__device__ __half g_wo_h[(size_t)DD * DD], g_wo_l[(size_t)DD * DD];
__device__ __half g_xn_h[(size_t)MTOT * DD];

// ---------------------------------------------------------------------------
// PTX helpers
// ---------------------------------------------------------------------------
__device__ __forceinline__ uint32_t smem_u32(const void* p) {
    uint32_t a;
    asm("{ .reg .u64 t; cvta.to.shared.u64 t, %1; cvt.u32.u64 %0, t; }"
        : "=r"(a) : "l"(p));
    return a;
}

__device__ __forceinline__ void ldsm_x4(uint32_t* r, uint32_t addr) {
    asm volatile("ldmatrix.sync.aligned.m8n8.x4.shared.b16 {%0,%1,%2,%3}, [%4];"
                 : "=r"(r[0]), "=r"(r[1]), "=r"(r[2]), "=r"(r[3]) : "r"(addr));
}

__device__ __forceinline__ void ldsm_x4_t(uint32_t* r, uint32_t addr) {
    asm volatile("ldmatrix.sync.aligned.m8n8.x4.trans.shared.b16 {%0,%1,%2,%3}, [%4];"
                 : "=r"(r[0]), "=r"(r[1]), "=r"(r[2]), "=r"(r[3]) : "r"(addr));
}

__device__ __forceinline__ void mma_f16(float* d, const uint32_t* a, const uint32_t* b) {
    asm volatile("mma.sync.aligned.m16n8k16.row.col.f32.f16.f16.f32 "
                 "{%0,%1,%2,%3}, {%4,%5,%6,%7}, {%8,%9}, {%0,%1,%2,%3};"
                 : "+f"(d[0]), "+f"(d[1]), "+f"(d[2]), "+f"(d[3])
                 : "r"(a[0]), "r"(a[1]), "r"(a[2]), "r"(a[3]), "r"(b[0]), "r"(b[1]));
}

#define CP_ASYNC16(dst, src) \
    asm volatile("cp.async.cg.shared.global [%0], [%1], 16;" \
                 :: "r"(dst), "l"(src) : "memory")
#define CP_COMMIT() asm volatile("cp.async.commit_group;" ::: "memory")
#define CP_WAIT0()  asm volatile("cp.async.wait_group 0;" ::: "memory")

// smem swizzles (tile-relative byte offsets)
__device__ __forceinline__ uint32_t sw64(uint32_t o)  { return o ^ (((o >> 7) & 3) << 4); }
__device__ __forceinline__ uint32_t sw128(uint32_t o) { return o ^ ((o >> 3) & 0x70); }

// split two floats into packed fp16x2 hi and lo
__device__ __forceinline__ void split2h(float a, float b, uint32_t& hi, uint32_t& lo) {
    __half2 H = __floats2half2_rn(a, b);
    float ra = a - __half2float(__low2half(H));
    float rb = b - __half2float(__high2half(H));
    __half2 L = __floats2half2_rn(ra, rb);
    hi = *(uint32_t*)&H;
    lo = *(uint32_t*)&L;
}

__device__ __forceinline__ uint32_t pack_h2(float a, float b) {
    __half2 H = __floats2half2_rn(a, b);
    return *(uint32_t*)&H;
}

// ---------------------------------------------------------------------------
// fp32 -> fp16 hi/lo split
// ---------------------------------------------------------------------------
__global__ __launch_bounds__(256)
void split_kernel(const float* __restrict__ src, __half* __restrict__ hi,
                  __half* __restrict__ lo, int n4)
{
    int i = blockIdx.x * 256 + threadIdx.x;
    if (i >= n4) return;
    float4 v = ((const float4*)src)[i];
    uint32_t h0, l0, h1, l1;
    split2h(v.x, v.y, h0, l0);
    split2h(v.z, v.w, h1, l1);
    uint2 H; H.x = h0; H.y = h1;
    uint2 L; L.x = l0; L.y = l1;
    ((uint2*)hi)[i] = H;
    ((uint2*)lo)[i] = L;
}

// ---------------------------------------------------------------------------
// mma.sync fp16 compensated GEMM: C[8192,1024] = A[M,K] * W[N,K]^T + bias
// NTERMS=3: ah*bh + ah*bl + al*bh (exact to 2^-22)
// NTERMS=2: ah*bh + ah*bl (A hi-only, error ~2^-12)
// 128x128 tile, 8 warps (64x32), BK=32, sw64 rows, 2 CTAs/SM.
// MODE 0: scatter (c+bias)*scale as fp16 hi/lo into [B,H,S,HD]
// MODE 1: fp32 LeakyReLU + mask, row-major
// ---------------------------------------------------------------------------
#define GK_TILE 8192                 // 128 rows * 64 B
#define GK_BUF  (4 * GK_TILE)
#define SM_GEMM (2 * GK_BUF)         // 65536
#define NKT     (DD / 32)

__device__ __forceinline__ void stage_g(uint32_t dst, const __half* src,
                                        int rowbase, int k0, int t)
{
#pragma unroll
    for (int i = 0; i < 2; i++) {
        int id  = t + i * 256;
        int row = id >> 2;
        int c   = (id & 3);
        CP_ASYNC16(dst + sw64((uint32_t)(row * 64 + c * 16)),
                   src + (size_t)(rowbase + row) * DD + k0 + c * 8);
    }
}

template <int MODE, int NTERMS>
__global__ __launch_bounds__(256, 2)
void gemm_mma(const __half* __restrict__ Ahi, const __half* __restrict__ Alo,
              const __half* __restrict__ Bhi, const __half* __restrict__ Blo,
              const float* __restrict__ bias, const float* __restrict__ mask,
              float* __restrict__ out,
              __half* __restrict__ out_hi, __half* __restrict__ out_lo,
              float scale)
{
    extern __shared__ __align__(128) char smem[];
    const uint32_t sb = smem_u32(smem);
    const int t    = threadIdx.x;
    const int wid  = t >> 5;
    const int lane = t & 31;
    const int brow = blockIdx.y * 128;
    const int bcol = blockIdx.x * 128;
    const int wm = wid & 1;
    const int wn = wid >> 1;

    const int sub = lane >> 3;
    const int lr  = lane & 7;
    const int a_roff = lr + (sub & 1) * 8;
    const int a_koff = (sub >> 1) * 16;
    const int b_roff = lr + (sub >> 1) * 8;
    const int b_koff = (sub & 1) * 16;

    stage_g(sb + 0 * GK_TILE, Ahi, brow, 0, t);
    if (NTERMS == 3) stage_g(sb + 1 * GK_TILE, Alo, brow, 0, t);
    stage_g(sb + 2 * GK_TILE, Bhi, bcol, 0, t);
    stage_g(sb + 3 * GK_TILE, Blo, bcol, 0, t);
    CP_COMMIT();

    float acc[4][4][4];
#pragma unroll
    for (int mt = 0; mt < 4; mt++)
#pragma unroll
        for (int nt = 0; nt < 4; nt++)
#pragma unroll
            for (int e = 0; e < 4; e++) acc[mt][nt][e] = 0.0f;

    for (int kt = 0; kt < NKT; kt++) {
        CP_WAIT0();
        __syncthreads();
        if (kt + 1 < NKT) {
            const uint32_t nb = sb + ((kt + 1) & 1) * GK_BUF;
            const int k0 = (kt + 1) * 32;
            stage_g(nb + 0 * GK_TILE, Ahi, brow, k0, t);
            if (NTERMS == 3) stage_g(nb + 1 * GK_TILE, Alo, brow, k0, t);
            stage_g(nb + 2 * GK_TILE, Bhi, bcol, k0, t);
            stage_g(nb + 3 * GK_TILE, Blo, bcol, k0, t);
            CP_COMMIT();
        }
        const uint32_t bufb = sb + (kt & 1) * GK_BUF;

#pragma unroll
        for (int ks = 0; ks < 2; ks++) {
            const int ksb = ks * 32;
            uint32_t bh[2][4], bl[2][4];
#pragma unroll
            for (int np = 0; np < 2; np++) {
                const uint32_t off = (uint32_t)((wn * 32 + np * 16 + b_roff) * 64 + ksb + b_koff);
                ldsm_x4(bh[np], bufb + 2 * GK_TILE + sw64(off));
                ldsm_x4(bl[np], bufb + 3 * GK_TILE + sw64(off));
            }
#pragma unroll
            for (int mp = 0; mp < 2; mp++) {
                uint32_t ah[2][4], al[2][4];
#pragma unroll
                for (int q = 0; q < 2; q++) {
                    const int mt = mp * 2 + q;
                    const uint32_t off = (uint32_t)((wm * 64 + mt * 16 + a_roff) * 64 + ksb + a_koff);
                    ldsm_x4(ah[q], bufb + 0 * GK_TILE + sw64(off));
                    if (NTERMS == 3)
                        ldsm_x4(al[q], bufb + 1 * GK_TILE + sw64(off));
                }
#pragma unroll
                for (int q = 0; q < 2; q++)
#pragma unroll
                    for (int nt = 0; nt < 4; nt++)
                        mma_f16(acc[mp * 2 + q][nt], ah[q], &bh[nt >> 1][(nt & 1) * 2]);
#pragma unroll
                for (int q = 0; q < 2; q++)
#pragma unroll
                    for (int nt = 0; nt < 4; nt++)
                        mma_f16(acc[mp * 2 + q][nt], ah[q], &bl[nt >> 1][(nt & 1) * 2]);
                if (NTERMS == 3) {
#pragma unroll
                    for (int q = 0; q < 2; q++)
#pragma unroll
                        for (int nt = 0; nt < 4; nt++)
                            mma_f16(acc[mp * 2 + q][nt], al[q], &bh[nt >> 1][(nt & 1) * 2]);
                }
            }
        }
    }

    const int g  = lane >> 2;
    const int tq = lane & 3;
#pragma unroll
    for (int mt = 0; mt < 4; mt++) {
        const int r0 = brow + wm * 64 + mt * 16 + g;
        float mr0 = 1.0f, mr1 = 1.0f;
        if (MODE == 1) { mr0 = mask[r0]; mr1 = mask[r0 + 8]; }
#pragma unroll
        for (int nt = 0; nt < 4; nt++) {
            const int c = bcol + wn * 32 + nt * 8 + tq * 2;
            const float b0 = bias[c], b1 = bias[c + 1];
            float2 v0, v1;
            v0.x = acc[mt][nt][0] + b0; v0.y = acc[mt][nt][1] + b1;
            v1.x = acc[mt][nt][2] + b0; v1.y = acc[mt][nt][3] + b1;
            if (MODE == 0) {
                v0.x *= scale; v0.y *= scale; v1.x *= scale; v1.y *= scale;
                const int h  = c >> 6;
                const int hd = c & (HDIM - 1);
                const int bi = r0 >> 11;
                const int s0 = r0 & (SS - 1);
                const size_t base = ((size_t)(bi * HH + h) * SS) * HDIM + hd;
                uint32_t h0, l0, h1, l1;
                split2h(v0.x, v0.y, h0, l0);
                split2h(v1.x, v1.y, h1, l1);
                *(uint32_t*)&out_hi[base + (size_t)s0 * HDIM] = h0;
                *(uint32_t*)&out_lo[base + (size_t)s0 * HDIM] = l0;
                *(uint32_t*)&out_hi[base + (size_t)(s0 + 8) * HDIM] = h1;
                *(uint32_t*)&out_lo[base + (size_t)(s0 + 8) * HDIM] = l1;
            } else {
                if (v0.x < 0.0f) v0.x *= 0.01f;
                if (v0.y < 0.0f) v0.y *= 0.01f;
                if (v1.x < 0.0f) v1.x *= 0.01f;
                if (v1.y < 0.0f) v1.y *= 0.01f;
                v0.x *= mr0; v0.y *= mr0;
                v1.x *= mr1; v1.y *= mr1;
                *(float2*)&out[(size_t)r0 * DD + c] = v0;
                *(float2*)&out[(size_t)(r0 + 8) * DD + c] = v1;
            }
        }
    }
}

// ---------------------------------------------------------------------------
// Flash attention, fp16 mma. BQ=128, BK=64, SW128. QK: 3-term. PV: 2-term
// (P as fp16 hi only). smem 96.5KB -> 2 CTAs/SM.
// ---------------------------------------------------------------------------
#define BQ     128
#define BK     64
#define QTILE  16384                 // 128 rows * 128 B
#define KVTILE 8192                  // 64 rows * 128 B
#define OFF_Q  0                     // Qhi, Qlo
#define OFF_K  (2 * QTILE)
#define OFF_V  (OFF_K + 4 * KVTILE)
#define OFF_M  (OFF_V + 4 * KVTILE)
#define SM_ATTN (OFF_M + 2 * 256)    // 98816

__device__ __forceinline__ void stage_q(uint32_t dst, const __half* src,
                                        size_t gbase, int t)
{
#pragma unroll
    for (int i = 0; i < 4; i++) {
        int id  = t + i * 256;
        int row = id >> 3;
        int c   = id & 7;
        CP_ASYNC16(dst + sw128((uint32_t)(row * 128 + c * 16)),
                   src + gbase + (size_t)row * HDIM + c * 8);
    }
}

__device__ __forceinline__ void stage_kv(uint32_t dst, const __half* src,
                                         size_t gbase, int t)
{
#pragma unroll
    for (int i = 0; i < 2; i++) {
        int id  = t + i * 256;
        int row = id >> 3;
        int c   = id & 7;
        CP_ASYNC16(dst + sw128((uint32_t)(row * 128 + c * 16)),
                   src + gbase + (size_t)row * HDIM + c * 8);
    }
}

__global__ __launch_bounds__(256, 2)
void attn_mma(const float* __restrict__ mask, float* __restrict__ ctx)
{
    extern __shared__ __align__(128) char smem[];
    const uint32_t sb = smem_u32(smem);
    const int t    = threadIdx.x;
    const int wid  = t >> 5;
    const int lane = t & 31;
    const int qt = blockIdx.x;
    const int h  = blockIdx.y;
    const int b  = blockIdx.z;

    const int gidx = lane >> 2;
    const int tq   = lane & 3;
    const int sub  = lane >> 3;
    const int lr   = lane & 7;
    const int a_roff = lr + (sub & 1) * 8;
    const int a_koff = (sub >> 1) * 16;
    const int b_roff = lr + (sub >> 1) * 8;
    const int b_koff = (sub & 1) * 16;
    const int v_koff = lr + ((lane >> 3) & 1) * 8;
    const int v_nbyte = (lane >> 4) * 16;

    const size_t head = ((size_t)(b * HH + h) * SS) * HDIM;
    const size_t qg = head + (size_t)qt * BQ * HDIM;

    stage_q(sb + OFF_Q,          g_qh, qg, t);
    stage_q(sb + OFF_Q + QTILE,  g_ql, qg, t);
    stage_kv(sb + OFF_K,            g_kh, head, t);
    stage_kv(sb + OFF_K + KVTILE,   g_kl, head, t);
    stage_kv(sb + OFF_V,            g_vh, head, t);
    stage_kv(sb + OFF_V + KVTILE,   g_vl, head, t);
    if (t < 16) CP_ASYNC16(sb + OFF_M + t * 16, mask + b * SS + t * 4);
    CP_COMMIT();

    float oacc[8][4];
#pragma unroll
    for (int nt = 0; nt < 8; nt++)
#pragma unroll
        for (int e = 0; e < 4; e++) oacc[nt][e] = 0.0f;
    float m0 = -1e30f, m1 = -1e30f, l0 = 0.0f, l1 = 0.0f;

    for (int kt = 0; kt < SS / BK; kt++) {
        CP_WAIT0();
        __syncthreads();
        if (kt + 1 < SS / BK) {
            const uint32_t kb = sb + OFF_K + ((kt + 1) & 1) * 2 * KVTILE;
            const uint32_t vb = sb + OFF_V + ((kt + 1) & 1) * 2 * KVTILE;
            const size_t kg = head + (size_t)(kt + 1) * BK * HDIM;
            stage_kv(kb,           g_kh, kg, t);
            stage_kv(kb + KVTILE,  g_kl, kg, t);
            stage_kv(vb,           g_vh, kg, t);
            stage_kv(vb + KVTILE,  g_vl, kg, t);
            if (t < 16)
                CP_ASYNC16(sb + OFF_M + ((kt + 1) & 1) * 256 + t * 16,
                           mask + b * SS + (kt + 1) * BK + t * 4);
            CP_COMMIT();
        }
        const uint32_t kbuf = sb + OFF_K + (kt & 1) * 2 * KVTILE;
        const uint32_t vbuf = sb + OFF_V + (kt & 1) * 2 * KVTILE;
        const float* mbuf = (const float*)(smem + OFF_M + (kt & 1) * 256);

        // ---- S = Q K^T, 3-term ----
        float sacc[8][4];
#pragma unroll
        for (int nt = 0; nt < 8; nt++)
#pragma unroll
            for (int e = 0; e < 4; e++) sacc[nt][e] = 0.0f;

#pragma unroll
        for (int kc = 0; kc < 4; kc++) {
            uint32_t ah[4], al[4];
            const uint32_t qoff = (uint32_t)((wid * 16 + a_roff) * 128 + kc * 32 + a_koff);
            ldsm_x4(ah, sb + OFF_Q + sw128(qoff));
            ldsm_x4(al, sb + OFF_Q + QTILE + sw128(qoff));
#pragma unroll
            for (int np = 0; np < 4; np++) {
                uint32_t bh[4], bl[4];
                const uint32_t koff = (uint32_t)((np * 16 + b_roff) * 128 + kc * 32 + b_koff);
                ldsm_x4(bh, kbuf + sw128(koff));
                ldsm_x4(bl, kbuf + KVTILE + sw128(koff));
#pragma unroll
                for (int half = 0; half < 2; half++) {
                    float* d = sacc[np * 2 + half];
                    mma_f16(d, ah, &bh[half * 2]);
                    mma_f16(d, ah, &bl[half * 2]);
                    mma_f16(d, al, &bh[half * 2]);
                }
            }
        }

        // ---- add mask, online softmax ----
        float mx0 = -1e30f, mx1 = -1e30f;
#pragma unroll
        for (int nt = 0; nt < 8; nt++) {
            const int col = nt * 8 + tq * 2;
            const float ma0 = (1.0f - mbuf[col]) * -10000.0f;
            const float ma1 = (1.0f - mbuf[col + 1]) * -10000.0f;
            sacc[nt][0] += ma0; sacc[nt][1] += ma1;
            sacc[nt][2] += ma0; sacc[nt][3] += ma1;
            mx0 = fmaxf(mx0, fmaxf(sacc[nt][0], sacc[nt][1]));
            mx1 = fmaxf(mx1, fmaxf(sacc[nt][2], sacc[nt][3]));
        }
        mx0 = fmaxf(mx0, __shfl_xor_sync(0xffffffffu, mx0, 1));
        mx0 = fmaxf(mx0, __shfl_xor_sync(0xffffffffu, mx0, 2));
        mx1 = fmaxf(mx1, __shfl_xor_sync(0xffffffffu, mx1, 1));
        mx1 = fmaxf(mx1, __shfl_xor_sync(0xffffffffu, mx1, 2));

        const float mn0 = fmaxf(m0, mx0);
        const float mn1 = fmaxf(m1, mx1);
        const float al0 = __expf(m0 - mn0);
        const float al1 = __expf(m1 - mn1);
        m0 = mn0; m1 = mn1;

        float rs0 = 0.0f, rs1 = 0.0f;
#pragma unroll
        for (int nt = 0; nt < 8; nt++) {
            sacc[nt][0] = __expf(sacc[nt][0] - mn0);
            sacc[nt][1] = __expf(sacc[nt][1] - mn0);
            sacc[nt][2] = __expf(sacc[nt][2] - mn1);
            sacc[nt][3] = __expf(sacc[nt][3] - mn1);
            rs0 += sacc[nt][0] + sacc[nt][1];
            rs1 += sacc[nt][2] + sacc[nt][3];
        }
        rs0 += __shfl_xor_sync(0xffffffffu, rs0, 1);
        rs0 += __shfl_xor_sync(0xffffffffu, rs0, 2);
        rs1 += __shfl_xor_sync(0xffffffffu, rs1, 1);
        rs1 += __shfl_xor_sync(0xffffffffu, rs1, 2);
        l0 = l0 * al0 + rs0;
        l1 = l1 * al1 + rs1;

#pragma unroll
        for (int nt = 0; nt < 8; nt++) {
            oacc[nt][0] *= al0; oacc[nt][1] *= al0;
            oacc[nt][2] *= al1; oacc[nt][3] *= al1;
        }

        // ---- O += P V, 2-term (P hi only) ----
#pragma unroll
        for (int j = 0; j < 4; j++) {
            uint32_t ph[4];
            ph[0] = pack_h2(sacc[2*j][0],   sacc[2*j][1]);
            ph[1] = pack_h2(sacc[2*j][2],   sacc[2*j][3]);
            ph[2] = pack_h2(sacc[2*j+1][0], sacc[2*j+1][1]);
            ph[3] = pack_h2(sacc[2*j+1][2], sacc[2*j+1][3]);
#pragma unroll
            for (int np = 0; np < 4; np++) {
                uint32_t bvh[4], bvl[4];
                const uint32_t voff = (uint32_t)((j * 16 + v_koff) * 128 + np * 32 + v_nbyte);
                ldsm_x4_t(bvh, vbuf + sw128(voff));
                ldsm_x4_t(bvl, vbuf + KVTILE + sw128(voff));
#pragma unroll
                for (int half = 0; half < 2; half++) {
                    float* d = oacc[np * 2 + half];
                    mma_f16(d, ph, &bvh[half * 2]);
                    mma_f16(d, ph, &bvl[half * 2]);
                }
            }
        }
    }

    const float inv0 = 1.0f / l0;
    const float inv1 = 1.0f / l1;
    const int row0 = qt * BQ + wid * 16 + gidx;
#pragma unroll
    for (int nt = 0; nt < 8; nt++) {
        const int col = h * HDIM + nt * 8 + tq * 2;
        float2 v0, v1;
        v0.x = oacc[nt][0] * inv0; v0.y = oacc[nt][1] * inv0;
        v1.x = oacc[nt][2] * inv1; v1.y = oacc[nt][3] * inv1;
        *(float2*)&ctx[((size_t)b * SS + row0) * DD + col] = v0;
        *(float2*)&ctx[((size_t)b * SS + row0 + 8) * DD + col] = v1;
    }
}

// ---------------------------------------------------------------------------
// Residual add + LayerNorm -> fp16 hi output (out-proj uses 2-term)
// ---------------------------------------------------------------------------
__global__ __launch_bounds__(256)
void ln_kernel(const float* __restrict__ x0, const float* __restrict__ gam,
               const float* __restrict__ bet)
{
    __shared__ float red[16];
    const int row = blockIdx.x;
    const int t = threadIdx.x;
    const float* cptr = g_ctx + (size_t)row * DD;
    const float* xptr = x0 + (size_t)row * DD;

    float v[4];
    float sum = 0.0f, sq = 0.0f;
#pragma unroll
    for (int e = 0; e < 4; e++) {
        int idx = e * 256 + t;
        float x = cptr[idx] + xptr[idx];
        v[e] = x;
        sum += x;
        sq += x * x;
    }
#pragma unroll
    for (int off = 16; off; off >>= 1) {
        sum += __shfl_xor_sync(0xffffffffu, sum, off);
        sq  += __shfl_xor_sync(0xffffffffu, sq, off);
    }
    const int w = t >> 5;
    if ((t & 31) == 0) { red[w] = sum; red[8 + w] = sq; }
    __syncthreads();
    float tsum = 0.0f, tsq = 0.0f;
#pragma unroll
    for (int i = 0; i < 8; i++) { tsum += red[i]; tsq += red[8 + i]; }
    const float mu = tsum * (1.0f / DD);
    const float var = tsq * (1.0f / DD) - mu * mu;
    const float rs = rsqrtf(var + 1e-5f);

#pragma unroll
    for (int e = 0; e < 4; e++) {
        int idx = e * 256 + t;
        float y = (v[e] - mu) * rs * gam[idx] + bet[idx];
        g_xn_h[(size_t)row * DD + idx] = __float2half_rn(y);
    }
}

// ---------------------------------------------------------------------------
extern "C" void kernel_launch(void* const* d_in, const int* in_sizes, int n_in,
                              void* d_out, int out_size)
{
    (void)in_sizes; (void)n_in; (void)out_size;
    const float* inputs = (const float*)d_in[0];
    const float* mask   = (const float*)d_in[1];
    const float* Wq     = (const float*)d_in[2];
    const float* bq     = (const float*)d_in[3];
    const float* Wk     = (const float*)d_in[4];
    const float* bk     = (const float*)d_in[5];
    const float* Wv     = (const float*)d_in[6];
    const float* bv     = (const float*)d_in[7];
    const float* Wo     = (const float*)d_in[8];
    const float* bo     = (const float*)d_in[9];
    const float* ln_g   = (const float*)d_in[10];
    const float* ln_b   = (const float*)d_in[11];
    float* out = (float*)d_out;

    float* ctxp;
    __half *qh, *ql, *kh, *kl, *vh, *vl;
    __half *inh, *inl, *wqh, *wql, *wkh, *wkl, *wvh, *wvl, *woh, *wol, *xnh;
    cudaGetSymbolAddress((void**)&ctxp, g_ctx);
    cudaGetSymbolAddress((void**)&qh, g_qh);
    cudaGetSymbolAddress((void**)&ql, g_ql);
    cudaGetSymbolAddress((void**)&kh, g_kh);
    cudaGetSymbolAddress((void**)&kl, g_kl);
    cudaGetSymbolAddress((void**)&vh, g_vh);
    cudaGetSymbolAddress((void**)&vl, g_vl);
    cudaGetSymbolAddress((void**)&inh, g_in_h);
    cudaGetSymbolAddress((void**)&inl, g_in_l);
    cudaGetSymbolAddress((void**)&wqh, g_wq_h);
    cudaGetSymbolAddress((void**)&wql, g_wq_l);
    cudaGetSymbolAddress((void**)&wkh, g_wk_h);
    cudaGetSymbolAddress((void**)&wkl, g_wk_l);
    cudaGetSymbolAddress((void**)&wvh, g_wv_h);
    cudaGetSymbolAddress((void**)&wvl, g_wv_l);
    cudaGetSymbolAddress((void**)&woh, g_wo_h);
    cudaGetSymbolAddress((void**)&wol, g_wo_l);
    cudaGetSymbolAddress((void**)&xnh, g_xn_h);

    cudaFuncSetAttribute((const void*)gemm_mma<0, 3>,
                         cudaFuncAttributeMaxDynamicSharedMemorySize, SM_GEMM);
    cudaFuncSetAttribute((const void*)gemm_mma<0, 2>,
                         cudaFuncAttributeMaxDynamicSharedMemorySize, SM_GEMM);
    cudaFuncSetAttribute((const void*)gemm_mma<1, 2>,
                         cudaFuncAttributeMaxDynamicSharedMemorySize, SM_GEMM);
    cudaFuncSetAttribute((const void*)attn_mma,
                         cudaFuncAttributeMaxDynamicSharedMemorySize, SM_ATTN);

    split_kernel<<<(MTOT * DD / 4) / 256, 256>>>(inputs, inh, inl, MTOT * DD / 4);
    split_kernel<<<(DD * DD / 4) / 256, 256>>>(Wq, wqh, wql, DD * DD / 4);
    split_kernel<<<(DD * DD / 4) / 256, 256>>>(Wk, wkh, wkl, DD * DD / 4);
    split_kernel<<<(DD * DD / 4) / 256, 256>>>(Wv, wvh, wvl, DD * DD / 4);
    split_kernel<<<(DD * DD / 4) / 256, 256>>>(Wo, woh, wol, DD * DD / 4);

    dim3 ggrid(DD / 128, MTOT / 128);
    // Q, K projections: 3-term (logit-sensitive). V: 2-term.
    gemm_mma<0, 3><<<ggrid, 256, SM_GEMM>>>(inh, inl, wqh, wql, bq, nullptr,
                                            nullptr, qh, ql, 0.125f);
    gemm_mma<0, 3><<<ggrid, 256, SM_GEMM>>>(inh, inl, wkh, wkl, bk, nullptr,
                                            nullptr, kh, kl, 1.0f);
    gemm_mma<0, 2><<<ggrid, 256, SM_GEMM>>>(inh, nullptr, wvh, wvl, bv, nullptr,
                                            nullptr, vh, vl, 1.0f);

    attn_mma<<<dim3(SS / BQ, HH, BB), 256, SM_ATTN>>>(mask, ctxp);

    ln_kernel<<<MTOT, 256>>>(inputs, ln_g, ln_b);

    // out projection: 2-term
    gemm_mma<1, 2><<<ggrid, 256, SM_GEMM>>>(xnh, nullptr, woh, wol, bo, mask,
                                            out, nullptr, nullptr, 1.0f);
}

// round 12
// speedup vs baseline: 4.8933x; 1.2035x over previous
#include <cuda_runtime.h>
#include <cuda_fp16.h>
#include <cstdint>

// Problem constants
#define BB   4
#define SS   2048
#define DD   1024
#define HH   16
#define HDIM 64
#define MTOT (BB * SS)   // 8192

// ---------------------------------------------------------------------------
// Scratch (__device__ globals; allocation is forbidden)
// ---------------------------------------------------------------------------
__device__ float g_ctx[(size_t)MTOT * DD];

__device__ __half g_qh[(size_t)BB * HH * SS * HDIM], g_ql[(size_t)BB * HH * SS * HDIM];
__device__ __half g_kh[(size_t)BB * HH * SS * HDIM];
__device__ __half g_vh[(size_t)BB * HH * SS * HDIM], g_vl[(size_t)BB * HH * SS * HDIM];

__device__ __half g_in_h[(size_t)MTOT * DD];
__device__ __half g_wq_h[(size_t)DD * DD], g_wq_l[(size_t)DD * DD];
__device__ __half g_wk_h[(size_t)DD * DD], g_wk_l[(size_t)DD * DD];
__device__ __half g_wv_h[(size_t)DD * DD], g_wv_l[(size_t)DD * DD];
__device__ __half g_wo_h[(size_t)DD * DD], g_wo_l[(size_t)DD * DD];
__device__ __half g_xn_h[(size_t)MTOT * DD];

// ---------------------------------------------------------------------------
// PTX helpers
// ---------------------------------------------------------------------------
__device__ __forceinline__ uint32_t smem_u32(const void* p) {
    uint32_t a;
    asm("{ .reg .u64 t; cvta.to.shared.u64 t, %1; cvt.u32.u64 %0, t; }"
        : "=r"(a) : "l"(p));
    return a;
}

__device__ __forceinline__ void ldsm_x4(uint32_t* r, uint32_t addr) {
    asm volatile("ldmatrix.sync.aligned.m8n8.x4.shared.b16 {%0,%1,%2,%3}, [%4];"
                 : "=r"(r[0]), "=r"(r[1]), "=r"(r[2]), "=r"(r[3]) : "r"(addr));
}

__device__ __forceinline__ void ldsm_x4_t(uint32_t* r, uint32_t addr) {
    asm volatile("ldmatrix.sync.aligned.m8n8.x4.trans.shared.b16 {%0,%1,%2,%3}, [%4];"
                 : "=r"(r[0]), "=r"(r[1]), "=r"(r[2]), "=r"(r[3]) : "r"(addr));
}

__device__ __forceinline__ void mma_f16(float* d, const uint32_t* a, const uint32_t* b) {
    asm volatile("mma.sync.aligned.m16n8k16.row.col.f32.f16.f16.f32 "
                 "{%0,%1,%2,%3}, {%4,%5,%6,%7}, {%8,%9}, {%0,%1,%2,%3};"
                 : "+f"(d[0]), "+f"(d[1]), "+f"(d[2]), "+f"(d[3])
                 : "r"(a[0]), "r"(a[1]), "r"(a[2]), "r"(a[3]), "r"(b[0]), "r"(b[1]));
}

#define CP_ASYNC16(dst, src) \
    asm volatile("cp.async.cg.shared.global [%0], [%1], 16;" \
                 :: "r"(dst), "l"(src) : "memory")
#define CP_COMMIT() asm volatile("cp.async.commit_group;" ::: "memory")
#define CP_WAIT0()  asm volatile("cp.async.wait_group 0;" ::: "memory")

// smem swizzles (tile-relative byte offsets)
__device__ __forceinline__ uint32_t sw64(uint32_t o)  { return o ^ (((o >> 7) & 3) << 4); }
__device__ __forceinline__ uint32_t sw128(uint32_t o) { return o ^ ((o >> 3) & 0x70); }

// split two floats into packed fp16x2 hi and lo
__device__ __forceinline__ void split2h(float a, float b, uint32_t& hi, uint32_t& lo) {
    __half2 H = __floats2half2_rn(a, b);
    float ra = a - __half2float(__low2half(H));
    float rb = b - __half2float(__high2half(H));
    __half2 L = __floats2half2_rn(ra, rb);
    hi = *(uint32_t*)&H;
    lo = *(uint32_t*)&L;
}

__device__ __forceinline__ uint32_t pack_h2(float a, float b) {
    __half2 H = __floats2half2_rn(a, b);
    return *(uint32_t*)&H;
}

// ---------------------------------------------------------------------------
// fp32 -> fp16 hi/lo split (weights) and hi-only convert (inputs)
// ---------------------------------------------------------------------------
__global__ __launch_bounds__(256)
void split_kernel(const float* __restrict__ src, __half* __restrict__ hi,
                  __half* __restrict__ lo, int n4)
{
    int i = blockIdx.x * 256 + threadIdx.x;
    if (i >= n4) return;
    float4 v = ((const float4*)src)[i];
    uint32_t h0, l0, h1, l1;
    split2h(v.x, v.y, h0, l0);
    split2h(v.z, v.w, h1, l1);
    uint2 H; H.x = h0; H.y = h1;
    uint2 L; L.x = l0; L.y = l1;
    ((uint2*)hi)[i] = H;
    ((uint2*)lo)[i] = L;
}

__global__ __launch_bounds__(256)
void cvt_kernel(const float* __restrict__ src, __half* __restrict__ hi, int n4)
{
    int i = blockIdx.x * 256 + threadIdx.x;
    if (i >= n4) return;
    float4 v = ((const float4*)src)[i];
    uint2 H;
    H.x = pack_h2(v.x, v.y);
    H.y = pack_h2(v.z, v.w);
    ((uint2*)hi)[i] = H;
}

// ---------------------------------------------------------------------------
// mma.sync fp16 2-term GEMM: C = A_hi * (W_hi + W_lo)^T + bias
// 128x128 tile, 8 warps (64x32), BK=32, sw64 rows, 2 CTAs/SM.
// MODE 0: scatter (c+bias)*scale as fp16 into [B,H,S,HD] (STORE_LO: hi+lo pair)
// MODE 1: fp32 LeakyReLU + mask, row-major
// ---------------------------------------------------------------------------
#define GK_TILE 8192                 // 128 rows * 64 B
#define GK_BUF  (3 * GK_TILE)        // Ahi, Bhi, Blo
#define SM_GEMM (2 * GK_BUF)         // 49152
#define NKT     (DD / 32)

__device__ __forceinline__ void stage_g(uint32_t dst, const __half* src,
                                        int rowbase, int k0, int t)
{
#pragma unroll
    for (int i = 0; i < 2; i++) {
        int id  = t + i * 256;
        int row = id >> 2;
        int c   = (id & 3);
        CP_ASYNC16(dst + sw64((uint32_t)(row * 64 + c * 16)),
                   src + (size_t)(rowbase + row) * DD + k0 + c * 8);
    }
}

template <int MODE, int STORE_LO>
__global__ __launch_bounds__(256, 2)
void gemm_mma(const __half* __restrict__ Ahi,
              const __half* __restrict__ Bhi, const __half* __restrict__ Blo,
              const float* __restrict__ bias, const float* __restrict__ mask,
              float* __restrict__ out,
              __half* __restrict__ out_hi, __half* __restrict__ out_lo,
              float scale)
{
    extern __shared__ __align__(128) char smem[];
    const uint32_t sb = smem_u32(smem);
    const int t    = threadIdx.x;
    const int wid  = t >> 5;
    const int lane = t & 31;
    const int brow = blockIdx.y * 128;
    const int bcol = blockIdx.x * 128;
    const int wm = wid & 1;
    const int wn = wid >> 1;

    const int sub = lane >> 3;
    const int lr  = lane & 7;
    const int a_roff = lr + (sub & 1) * 8;
    const int a_koff = (sub >> 1) * 16;
    const int b_roff = lr + (sub >> 1) * 8;
    const int b_koff = (sub & 1) * 16;

    stage_g(sb + 0 * GK_TILE, Ahi, brow, 0, t);
    stage_g(sb + 1 * GK_TILE, Bhi, bcol, 0, t);
    stage_g(sb + 2 * GK_TILE, Blo, bcol, 0, t);
    CP_COMMIT();

    float acc[4][4][4];
#pragma unroll
    for (int mt = 0; mt < 4; mt++)
#pragma unroll
        for (int nt = 0; nt < 4; nt++)
#pragma unroll
            for (int e = 0; e < 4; e++) acc[mt][nt][e] = 0.0f;

    for (int kt = 0; kt < NKT; kt++) {
        CP_WAIT0();
        __syncthreads();
        if (kt + 1 < NKT) {
            const uint32_t nb = sb + ((kt + 1) & 1) * GK_BUF;
            const int k0 = (kt + 1) * 32;
            stage_g(nb + 0 * GK_TILE, Ahi, brow, k0, t);
            stage_g(nb + 1 * GK_TILE, Bhi, bcol, k0, t);
            stage_g(nb + 2 * GK_TILE, Blo, bcol, k0, t);
            CP_COMMIT();
        }
        const uint32_t bufb = sb + (kt & 1) * GK_BUF;

#pragma unroll
        for (int ks = 0; ks < 2; ks++) {
            const int ksb = ks * 32;
            uint32_t bh[2][4], bl[2][4];
#pragma unroll
            for (int np = 0; np < 2; np++) {
                const uint32_t off = (uint32_t)((wn * 32 + np * 16 + b_roff) * 64 + ksb + b_koff);
                ldsm_x4(bh[np], bufb + 1 * GK_TILE + sw64(off));
                ldsm_x4(bl[np], bufb + 2 * GK_TILE + sw64(off));
            }
#pragma unroll
            for (int mp = 0; mp < 2; mp++) {
                uint32_t ah[2][4];
#pragma unroll
                for (int q = 0; q < 2; q++) {
                    const int mt = mp * 2 + q;
                    const uint32_t off = (uint32_t)((wm * 64 + mt * 16 + a_roff) * 64 + ksb + a_koff);
                    ldsm_x4(ah[q], bufb + 0 * GK_TILE + sw64(off));
                }
#pragma unroll
                for (int q = 0; q < 2; q++)
#pragma unroll
                    for (int nt = 0; nt < 4; nt++)
                        mma_f16(acc[mp * 2 + q][nt], ah[q], &bh[nt >> 1][(nt & 1) * 2]);
#pragma unroll
                for (int q = 0; q < 2; q++)
#pragma unroll
                    for (int nt = 0; nt < 4; nt++)
                        mma_f16(acc[mp * 2 + q][nt], ah[q], &bl[nt >> 1][(nt & 1) * 2]);
            }
        }
    }

    const int g  = lane >> 2;
    const int tq = lane & 3;
#pragma unroll
    for (int mt = 0; mt < 4; mt++) {
        const int r0 = brow + wm * 64 + mt * 16 + g;
        float mr0 = 1.0f, mr1 = 1.0f;
        if (MODE == 1) { mr0 = mask[r0]; mr1 = mask[r0 + 8]; }
#pragma unroll
        for (int nt = 0; nt < 4; nt++) {
            const int c = bcol + wn * 32 + nt * 8 + tq * 2;
            const float b0 = bias[c], b1 = bias[c + 1];
            float2 v0, v1;
            v0.x = acc[mt][nt][0] + b0; v0.y = acc[mt][nt][1] + b1;
            v1.x = acc[mt][nt][2] + b0; v1.y = acc[mt][nt][3] + b1;
            if (MODE == 0) {
                v0.x *= scale; v0.y *= scale; v1.x *= scale; v1.y *= scale;
                const int h  = c >> 6;
                const int hd = c & (HDIM - 1);
                const int bi = r0 >> 11;
                const int s0 = r0 & (SS - 1);
                const size_t base = ((size_t)(bi * HH + h) * SS) * HDIM + hd;
                if (STORE_LO) {
                    uint32_t h0, l0, h1, l1;
                    split2h(v0.x, v0.y, h0, l0);
                    split2h(v1.x, v1.y, h1, l1);
                    *(uint32_t*)&out_hi[base + (size_t)s0 * HDIM] = h0;
                    *(uint32_t*)&out_lo[base + (size_t)s0 * HDIM] = l0;
                    *(uint32_t*)&out_hi[base + (size_t)(s0 + 8) * HDIM] = h1;
                    *(uint32_t*)&out_lo[base + (size_t)(s0 + 8) * HDIM] = l1;
                } else {
                    *(uint32_t*)&out_hi[base + (size_t)s0 * HDIM] = pack_h2(v0.x, v0.y);
                    *(uint32_t*)&out_hi[base + (size_t)(s0 + 8) * HDIM] = pack_h2(v1.x, v1.y);
                }
            } else {
                if (v0.x < 0.0f) v0.x *= 0.01f;
                if (v0.y < 0.0f) v0.y *= 0.01f;
                if (v1.x < 0.0f) v1.x *= 0.01f;
                if (v1.y < 0.0f) v1.y *= 0.01f;
                v0.x *= mr0; v0.y *= mr0;
                v1.x *= mr1; v1.y *= mr1;
                *(float2*)&out[(size_t)r0 * DD + c] = v0;
                *(float2*)&out[(size_t)(r0 + 8) * DD + c] = v1;
            }
        }
    }
}

// ---------------------------------------------------------------------------
// Flash attention, fp16 mma. BQ=128, BK=64, SW128.
// QK: qh*kh + ql*kh (K hi-only). PV: ph*(vh+vl). smem 80.5KB -> 2 CTAs/SM.
// ---------------------------------------------------------------------------
#define BQ     128
#define BK     64
#define QTILE  16384                 // 128 rows * 128 B
#define KVTILE 8192                  // 64 rows * 128 B
#define OFF_Q  0                     // Qhi, Qlo
#define OFF_K  (2 * QTILE)           // 2 bufs x hi
#define OFF_V  (OFF_K + 2 * KVTILE)  // 2 bufs x (hi,lo)
#define OFF_M  (OFF_V + 4 * KVTILE)
#define SM_ATTN (OFF_M + 2 * 256)    // 82432

__device__ __forceinline__ void stage_q(uint32_t dst, const __half* src,
                                        size_t gbase, int t)
{
#pragma unroll
    for (int i = 0; i < 4; i++) {
        int id  = t + i * 256;
        int row = id >> 3;
        int c   = id & 7;
        CP_ASYNC16(dst + sw128((uint32_t)(row * 128 + c * 16)),
                   src + gbase + (size_t)row * HDIM + c * 8);
    }
}

__device__ __forceinline__ void stage_kv(uint32_t dst, const __half* src,
                                         size_t gbase, int t)
{
#pragma unroll
    for (int i = 0; i < 2; i++) {
        int id  = t + i * 256;
        int row = id >> 3;
        int c   = id & 7;
        CP_ASYNC16(dst + sw128((uint32_t)(row * 128 + c * 16)),
                   src + gbase + (size_t)row * HDIM + c * 8);
    }
}

__global__ __launch_bounds__(256, 2)
void attn_mma(const float* __restrict__ mask, float* __restrict__ ctx)
{
    extern __shared__ __align__(128) char smem[];
    const uint32_t sb = smem_u32(smem);
    const int t    = threadIdx.x;
    const int wid  = t >> 5;
    const int lane = t & 31;
    const int qt = blockIdx.x;
    const int h  = blockIdx.y;
    const int b  = blockIdx.z;

    const int gidx = lane >> 2;
    const int tq   = lane & 3;
    const int sub  = lane >> 3;
    const int lr   = lane & 7;
    const int a_roff = lr + (sub & 1) * 8;
    const int a_koff = (sub >> 1) * 16;
    const int b_roff = lr + (sub >> 1) * 8;
    const int b_koff = (sub & 1) * 16;
    const int v_koff = lr + ((lane >> 3) & 1) * 8;
    const int v_nbyte = (lane >> 4) * 16;

    const size_t head = ((size_t)(b * HH + h) * SS) * HDIM;
    const size_t qg = head + (size_t)qt * BQ * HDIM;

    stage_q(sb + OFF_Q,          g_qh, qg, t);
    stage_q(sb + OFF_Q + QTILE,  g_ql, qg, t);
    stage_kv(sb + OFF_K,            g_kh, head, t);
    stage_kv(sb + OFF_V,            g_vh, head, t);
    stage_kv(sb + OFF_V + KVTILE,   g_vl, head, t);
    if (t < 16) CP_ASYNC16(sb + OFF_M + t * 16, mask + b * SS + t * 4);
    CP_COMMIT();

    float oacc[8][4];
#pragma unroll
    for (int nt = 0; nt < 8; nt++)
#pragma unroll
        for (int e = 0; e < 4; e++) oacc[nt][e] = 0.0f;
    float m0 = -1e30f, m1 = -1e30f, l0 = 0.0f, l1 = 0.0f;

    for (int kt = 0; kt < SS / BK; kt++) {
        CP_WAIT0();
        __syncthreads();
        if (kt + 1 < SS / BK) {
            const uint32_t kb = sb + OFF_K + ((kt + 1) & 1) * KVTILE;
            const uint32_t vb = sb + OFF_V + ((kt + 1) & 1) * 2 * KVTILE;
            const size_t kg = head + (size_t)(kt + 1) * BK * HDIM;
            stage_kv(kb,           g_kh, kg, t);
            stage_kv(vb,           g_vh, kg, t);
            stage_kv(vb + KVTILE,  g_vl, kg, t);
            if (t < 16)
                CP_ASYNC16(sb + OFF_M + ((kt + 1) & 1) * 256 + t * 16,
                           mask + b * SS + (kt + 1) * BK + t * 4);
            CP_COMMIT();
        }
        const uint32_t kbuf = sb + OFF_K + (kt & 1) * KVTILE;
        const uint32_t vbuf = sb + OFF_V + (kt & 1) * 2 * KVTILE;
        const float* mbuf = (const float*)(smem + OFF_M + (kt & 1) * 256);

        // ---- S = Q K^T: qh*kh + ql*kh ----
        float sacc[8][4];
#pragma unroll
        for (int nt = 0; nt < 8; nt++)
#pragma unroll
            for (int e = 0; e < 4; e++) sacc[nt][e] = 0.0f;

#pragma unroll
        for (int kc = 0; kc < 4; kc++) {
            uint32_t ah[4], al[4];
            const uint32_t qoff = (uint32_t)((wid * 16 + a_roff) * 128 + kc * 32 + a_koff);
            ldsm_x4(ah, sb + OFF_Q + sw128(qoff));
            ldsm_x4(al, sb + OFF_Q + QTILE + sw128(qoff));
#pragma unroll
            for (int np = 0; np < 4; np++) {
                uint32_t bh[4];
                const uint32_t koff = (uint32_t)((np * 16 + b_roff) * 128 + kc * 32 + b_koff);
                ldsm_x4(bh, kbuf + sw128(koff));
#pragma unroll
                for (int half = 0; half < 2; half++) {
                    float* d = sacc[np * 2 + half];
                    mma_f16(d, ah, &bh[half * 2]);
                    mma_f16(d, al, &bh[half * 2]);
                }
            }
        }

        // ---- add mask, online softmax ----
        float mx0 = -1e30f, mx1 = -1e30f;
#pragma unroll
        for (int nt = 0; nt < 8; nt++) {
            const int col = nt * 8 + tq * 2;
            const float ma0 = (1.0f - mbuf[col]) * -10000.0f;
            const float ma1 = (1.0f - mbuf[col + 1]) * -10000.0f;
            sacc[nt][0] += ma0; sacc[nt][1] += ma1;
            sacc[nt][2] += ma0; sacc[nt][3] += ma1;
            mx0 = fmaxf(mx0, fmaxf(sacc[nt][0], sacc[nt][1]));
            mx1 = fmaxf(mx1, fmaxf(sacc[nt][2], sacc[nt][3]));
        }
        mx0 = fmaxf(mx0, __shfl_xor_sync(0xffffffffu, mx0, 1));
        mx0 = fmaxf(mx0, __shfl_xor_sync(0xffffffffu, mx0, 2));
        mx1 = fmaxf(mx1, __shfl_xor_sync(0xffffffffu, mx1, 1));
        mx1 = fmaxf(mx1, __shfl_xor_sync(0xffffffffu, mx1, 2));

        const float mn0 = fmaxf(m0, mx0);
        const float mn1 = fmaxf(m1, mx1);
        const float al0 = __expf(m0 - mn0);
        const float al1 = __expf(m1 - mn1);
        m0 = mn0; m1 = mn1;

        float rs0 = 0.0f, rs1 = 0.0f;
#pragma unroll
        for (int nt = 0; nt < 8; nt++) {
            sacc[nt][0] = __expf(sacc[nt][0] - mn0);
            sacc[nt][1] = __expf(sacc[nt][1] - mn0);
            sacc[nt][2] = __expf(sacc[nt][2] - mn1);
            sacc[nt][3] = __expf(sacc[nt][3] - mn1);
            rs0 += sacc[nt][0] + sacc[nt][1];
            rs1 += sacc[nt][2] + sacc[nt][3];
        }
        rs0 += __shfl_xor_sync(0xffffffffu, rs0, 1);
        rs0 += __shfl_xor_sync(0xffffffffu, rs0, 2);
        rs1 += __shfl_xor_sync(0xffffffffu, rs1, 1);
        rs1 += __shfl_xor_sync(0xffffffffu, rs1, 2);
        l0 = l0 * al0 + rs0;
        l1 = l1 * al1 + rs1;

#pragma unroll
        for (int nt = 0; nt < 8; nt++) {
            oacc[nt][0] *= al0; oacc[nt][1] *= al0;
            oacc[nt][2] *= al1; oacc[nt][3] *= al1;
        }

        // ---- O += P V: ph*(vh+vl) ----
#pragma unroll
        for (int j = 0; j < 4; j++) {
            uint32_t ph[4];
            ph[0] = pack_h2(sacc[2*j][0],   sacc[2*j][1]);
            ph[1] = pack_h2(sacc[2*j][2],   sacc[2*j][3]);
            ph[2] = pack_h2(sacc[2*j+1][0], sacc[2*j+1][1]);
            ph[3] = pack_h2(sacc[2*j+1][2], sacc[2*j+1][3]);
#pragma unroll
            for (int np = 0; np < 4; np++) {
                uint32_t bvh[4], bvl[4];
                const uint32_t voff = (uint32_t)((j * 16 + v_koff) * 128 + np * 32 + v_nbyte);
                ldsm_x4_t(bvh, vbuf + sw128(voff));
                ldsm_x4_t(bvl, vbuf + KVTILE + sw128(voff));
#pragma unroll
                for (int half = 0; half < 2; half++) {
                    float* d = oacc[np * 2 + half];
                    mma_f16(d, ph, &bvh[half * 2]);
                    mma_f16(d, ph, &bvl[half * 2]);
                }
            }
        }
    }

    const float inv0 = 1.0f / l0;
    const float inv1 = 1.0f / l1;
    const int row0 = qt * BQ + wid * 16 + gidx;
#pragma unroll
    for (int nt = 0; nt < 8; nt++) {
        const int col = h * HDIM + nt * 8 + tq * 2;
        float2 v0, v1;
        v0.x = oacc[nt][0] * inv0; v0.y = oacc[nt][1] * inv0;
        v1.x = oacc[nt][2] * inv1; v1.y = oacc[nt][3] * inv1;
        *(float2*)&ctx[((size_t)b * SS + row0) * DD + col] = v0;
        *(float2*)&ctx[((size_t)b * SS + row0 + 8) * DD + col] = v1;
    }
}

// ---------------------------------------------------------------------------
// Residual add + LayerNorm -> fp16 hi output
// ---------------------------------------------------------------------------
__global__ __launch_bounds__(256)
void ln_kernel(const float* __restrict__ x0, const float* __restrict__ gam,
               const float* __restrict__ bet)
{
    __shared__ float red[16];
    const int row = blockIdx.x;
    const int t = threadIdx.x;
    const float* cptr = g_ctx + (size_t)row * DD;
    const float* xptr = x0 + (size_t)row * DD;

    float v[4];
    float sum = 0.0f, sq = 0.0f;
#pragma unroll
    for (int e = 0; e < 4; e++) {
        int idx = e * 256 + t;
        float x = cptr[idx] + xptr[idx];
        v[e] = x;
        sum += x;
        sq += x * x;
    }
#pragma unroll
    for (int off = 16; off; off >>= 1) {
        sum += __shfl_xor_sync(0xffffffffu, sum, off);
        sq  += __shfl_xor_sync(0xffffffffu, sq, off);
    }
    const int w = t >> 5;
    if ((t & 31) == 0) { red[w] = sum; red[8 + w] = sq; }
    __syncthreads();
    float tsum = 0.0f, tsq = 0.0f;
#pragma unroll
    for (int i = 0; i < 8; i++) { tsum += red[i]; tsq += red[8 + i]; }
    const float mu = tsum * (1.0f / DD);
    const float var = tsq * (1.0f / DD) - mu * mu;
    const float rs = rsqrtf(var + 1e-5f);

#pragma unroll
    for (int e = 0; e < 4; e++) {
        int idx = e * 256 + t;
        float y = (v[e] - mu) * rs * gam[idx] + bet[idx];
        g_xn_h[(size_t)row * DD + idx] = __float2half_rn(y);
    }
}

// ---------------------------------------------------------------------------
extern "C" void kernel_launch(void* const* d_in, const int* in_sizes, int n_in,
                              void* d_out, int out_size)
{
    (void)in_sizes; (void)n_in; (void)out_size;
    const float* inputs = (const float*)d_in[0];
    const float* mask   = (const float*)d_in[1];
    const float* Wq     = (const float*)d_in[2];
    const float* bq     = (const float*)d_in[3];
    const float* Wk     = (const float*)d_in[4];
    const float* bk     = (const float*)d_in[5];
    const float* Wv     = (const float*)d_in[6];
    const float* bv     = (const float*)d_in[7];
    const float* Wo     = (const float*)d_in[8];
    const float* bo     = (const float*)d_in[9];
    const float* ln_g   = (const float*)d_in[10];
    const float* ln_b   = (const float*)d_in[11];
    float* out = (float*)d_out;

    float* ctxp;
    __half *qh, *ql, *kh, *vh, *vl;
    __half *inh, *wqh, *wql, *wkh, *wkl, *wvh, *wvl, *woh, *wol, *xnh;
    cudaGetSymbolAddress((void**)&ctxp, g_ctx);
    cudaGetSymbolAddress((void**)&qh, g_qh);
    cudaGetSymbolAddress((void**)&ql, g_ql);
    cudaGetSymbolAddress((void**)&kh, g_kh);
    cudaGetSymbolAddress((void**)&vh, g_vh);
    cudaGetSymbolAddress((void**)&vl, g_vl);
    cudaGetSymbolAddress((void**)&inh, g_in_h);
    cudaGetSymbolAddress((void**)&wqh, g_wq_h);
    cudaGetSymbolAddress((void**)&wql, g_wq_l);
    cudaGetSymbolAddress((void**)&wkh, g_wk_h);
    cudaGetSymbolAddress((void**)&wkl, g_wk_l);
    cudaGetSymbolAddress((void**)&wvh, g_wv_h);
    cudaGetSymbolAddress((void**)&wvl, g_wv_l);
    cudaGetSymbolAddress((void**)&woh, g_wo_h);
    cudaGetSymbolAddress((void**)&wol, g_wo_l);
    cudaGetSymbolAddress((void**)&xnh, g_xn_h);

    cudaFuncSetAttribute((const void*)gemm_mma<0, 1>,
                         cudaFuncAttributeMaxDynamicSharedMemorySize, SM_GEMM);
    cudaFuncSetAttribute((const void*)gemm_mma<0, 0>,
                         cudaFuncAttributeMaxDynamicSharedMemorySize, SM_GEMM);
    cudaFuncSetAttribute((const void*)gemm_mma<1, 0>,
                         cudaFuncAttributeMaxDynamicSharedMemorySize, SM_GEMM);
    cudaFuncSetAttribute((const void*)attn_mma,
                         cudaFuncAttributeMaxDynamicSharedMemorySize, SM_ATTN);

    cvt_kernel<<<(MTOT * DD / 4) / 256, 256>>>(inputs, inh, MTOT * DD / 4);
    split_kernel<<<(DD * DD / 4) / 256, 256>>>(Wq, wqh, wql, DD * DD / 4);
    split_kernel<<<(DD * DD / 4) / 256, 256>>>(Wk, wkh, wkl, DD * DD / 4);
    split_kernel<<<(DD * DD / 4) / 256, 256>>>(Wv, wvh, wvl, DD * DD / 4);
    split_kernel<<<(DD * DD / 4) / 256, 256>>>(Wo, woh, wol, DD * DD / 4);

    dim3 ggrid(DD / 128, MTOT / 128);
    // Q: store hi+lo (lo used in QK). K: hi only. V: hi+lo (PV uses both).
    gemm_mma<0, 1><<<ggrid, 256, SM_GEMM>>>(inh, wqh, wql, bq, nullptr,
                                            nullptr, qh, ql, 0.125f);
    gemm_mma<0, 0><<<ggrid, 256, SM_GEMM>>>(inh, wkh, wkl, bk, nullptr,
                                            nullptr, kh, nullptr, 1.0f);
    gemm_mma<0, 1><<<ggrid, 256, SM_GEMM>>>(inh, wvh, wvl, bv, nullptr,
                                            nullptr, vh, vl, 1.0f);

    attn_mma<<<dim3(SS / BQ, HH, BB), 256, SM_ATTN>>>(mask, ctxp);

    ln_kernel<<<MTOT, 256>>>(inputs, ln_g, ln_b);

    gemm_mma<1, 0><<<ggrid, 256, SM_GEMM>>>(xnh, woh, wol, bo, mask,
                                            out, nullptr, nullptr, 1.0f);
}

// round 14
// speedup vs baseline: 6.0289x; 1.2321x over previous
#include <cuda_runtime.h>
#include <cuda_fp16.h>
#include <cstdint>

// Problem constants
#define BB   4
#define SS   2048
#define DD   1024
#define HH   16
#define HDIM 64
#define MTOT (BB * SS)   // 8192

// ---------------------------------------------------------------------------
// Scratch (__device__ globals; allocation is forbidden)
// ---------------------------------------------------------------------------
__device__ float g_ctx[(size_t)MTOT * DD];

__device__ __half g_qh[(size_t)BB * HH * SS * HDIM], g_ql[(size_t)BB * HH * SS * HDIM];
__device__ __half g_kh[(size_t)BB * HH * SS * HDIM];
__device__ __half g_vh[(size_t)BB * HH * SS * HDIM];

__device__ __half g_in_h[(size_t)MTOT * DD];
__device__ __half g_wq_h[(size_t)DD * DD], g_wq_l[(size_t)DD * DD];
__device__ __half g_wk_h[(size_t)DD * DD], g_wk_l[(size_t)DD * DD];
__device__ __half g_wv_h[(size_t)DD * DD];
__device__ __half g_wo_h[(size_t)DD * DD];
__device__ __half g_xn_h[(size_t)MTOT * DD];

// ---------------------------------------------------------------------------
// PTX helpers
// ---------------------------------------------------------------------------
__device__ __forceinline__ uint32_t smem_u32(const void* p) {
    uint32_t a;
    asm("{ .reg .u64 t; cvta.to.shared.u64 t, %1; cvt.u32.u64 %0, t; }"
        : "=r"(a) : "l"(p));
    return a;
}

__device__ __forceinline__ void ldsm_x4(uint32_t* r, uint32_t addr) {
    asm volatile("ldmatrix.sync.aligned.m8n8.x4.shared.b16 {%0,%1,%2,%3}, [%4];"
                 : "=r"(r[0]), "=r"(r[1]), "=r"(r[2]), "=r"(r[3]) : "r"(addr));
}

__device__ __forceinline__ void ldsm_x4_t(uint32_t* r, uint32_t addr) {
    asm volatile("ldmatrix.sync.aligned.m8n8.x4.trans.shared.b16 {%0,%1,%2,%3}, [%4];"
                 : "=r"(r[0]), "=r"(r[1]), "=r"(r[2]), "=r"(r[3]) : "r"(addr));
}

__device__ __forceinline__ void mma_f16(float* d, const uint32_t* a, const uint32_t* b) {
    asm volatile("mma.sync.aligned.m16n8k16.row.col.f32.f16.f16.f32 "
                 "{%0,%1,%2,%3}, {%4,%5,%6,%7}, {%8,%9}, {%0,%1,%2,%3};"
                 : "+f"(d[0]), "+f"(d[1]), "+f"(d[2]), "+f"(d[3])
                 : "r"(a[0]), "r"(a[1]), "r"(a[2]), "r"(a[3]), "r"(b[0]), "r"(b[1]));
}

#define CP_ASYNC16(dst, src) \
    asm volatile("cp.async.cg.shared.global [%0], [%1], 16;" \
                 :: "r"(dst), "l"(src) : "memory")
#define CP_COMMIT() asm volatile("cp.async.commit_group;" ::: "memory")
#define CP_WAIT0()  asm volatile("cp.async.wait_group 0;" ::: "memory")

// smem swizzles (tile-relative byte offsets)
__device__ __forceinline__ uint32_t sw64(uint32_t o)  { return o ^ (((o >> 7) & 3) << 4); }
__device__ __forceinline__ uint32_t sw128(uint32_t o) { return o ^ ((o >> 3) & 0x70); }

// split two floats into packed fp16x2 hi and lo
__device__ __forceinline__ void split2h(float a, float b, uint32_t& hi, uint32_t& lo) {
    __half2 H = __floats2half2_rn(a, b);
    float ra = a - __half2float(__low2half(H));
    float rb = b - __half2float(__high2half(H));
    __half2 L = __floats2half2_rn(ra, rb);
    hi = *(uint32_t*)&H;
    lo = *(uint32_t*)&L;
}

__device__ __forceinline__ uint32_t pack_h2(float a, float b) {
    __half2 H = __floats2half2_rn(a, b);
    return *(uint32_t*)&H;
}

// ---------------------------------------------------------------------------
// fp32 -> fp16 hi/lo split (Q/K weights) and hi-only convert (rest)
// ---------------------------------------------------------------------------
__global__ __launch_bounds__(256)
void split_kernel(const float* __restrict__ src, __half* __restrict__ hi,
                  __half* __restrict__ lo, int n4)
{
    int i = blockIdx.x * 256 + threadIdx.x;
    if (i >= n4) return;
    float4 v = ((const float4*)src)[i];
    uint32_t h0, l0, h1, l1;
    split2h(v.x, v.y, h0, l0);
    split2h(v.z, v.w, h1, l1);
    uint2 H; H.x = h0; H.y = h1;
    uint2 L; L.x = l0; L.y = l1;
    ((uint2*)hi)[i] = H;
    ((uint2*)lo)[i] = L;
}

__global__ __launch_bounds__(256)
void cvt_kernel(const float* __restrict__ src, __half* __restrict__ hi, int n4)
{
    int i = blockIdx.x * 256 + threadIdx.x;
    if (i >= n4) return;
    float4 v = ((const float4*)src)[i];
    uint2 H;
    H.x = pack_h2(v.x, v.y);
    H.y = pack_h2(v.z, v.w);
    ((uint2*)hi)[i] = H;
}

// ---------------------------------------------------------------------------
// mma.sync fp16 GEMM: C = A_hi * (W_hi [+ W_lo])^T + bias
// BTERMS=2: B two-term (W full precision). BTERMS=1: B hi only.
// 128x128 tile, 8 warps (64x32), BK=32, sw64 rows, 2 CTAs/SM.
// MODE 0: scatter (c+bias)*scale as fp16 into [B,H,S,HD] (STORE_LO: hi+lo)
// MODE 1: fp32 LeakyReLU + mask, row-major
// ---------------------------------------------------------------------------
#define GK_TILE 8192                 // 128 rows * 64 B
#define GK_BUF  (3 * GK_TILE)        // Ahi, Bhi, Blo slots
#define SM_GEMM (2 * GK_BUF)         // 49152
#define NKT     (DD / 32)

__device__ __forceinline__ void stage_g(uint32_t dst, const __half* src,
                                        int rowbase, int k0, int t)
{
#pragma unroll
    for (int i = 0; i < 2; i++) {
        int id  = t + i * 256;
        int row = id >> 2;
        int c   = (id & 3);
        CP_ASYNC16(dst + sw64((uint32_t)(row * 64 + c * 16)),
                   src + (size_t)(rowbase + row) * DD + k0 + c * 8);
    }
}

template <int MODE, int STORE_LO, int BTERMS>
__global__ __launch_bounds__(256, 2)
void gemm_mma(const __half* __restrict__ Ahi,
              const __half* __restrict__ Bhi, const __half* __restrict__ Blo,
              const float* __restrict__ bias, const float* __restrict__ mask,
              float* __restrict__ out,
              __half* __restrict__ out_hi, __half* __restrict__ out_lo,
              float scale)
{
    extern __shared__ __align__(128) char smem[];
    const uint32_t sb = smem_u32(smem);
    const int t    = threadIdx.x;
    const int wid  = t >> 5;
    const int lane = t & 31;
    const int brow = blockIdx.y * 128;
    const int bcol = blockIdx.x * 128;
    const int wm = wid & 1;
    const int wn = wid >> 1;

    const int sub = lane >> 3;
    const int lr  = lane & 7;
    const int a_roff = lr + (sub & 1) * 8;
    const int a_koff = (sub >> 1) * 16;
    const int b_roff = lr + (sub >> 1) * 8;
    const int b_koff = (sub & 1) * 16;

    stage_g(sb + 0 * GK_TILE, Ahi, brow, 0, t);
    stage_g(sb + 1 * GK_TILE, Bhi, bcol, 0, t);
    if (BTERMS == 2) stage_g(sb + 2 * GK_TILE, Blo, bcol, 0, t);
    CP_COMMIT();

    float acc[4][4][4];
#pragma unroll
    for (int mt = 0; mt < 4; mt++)
#pragma unroll
        for (int nt = 0; nt < 4; nt++)
#pragma unroll
            for (int e = 0; e < 4; e++) acc[mt][nt][e] = 0.0f;

    for (int kt = 0; kt < NKT; kt++) {
        CP_WAIT0();
        __syncthreads();
        if (kt + 1 < NKT) {
            const uint32_t nb = sb + ((kt + 1) & 1) * GK_BUF;
            const int k0 = (kt + 1) * 32;
            stage_g(nb + 0 * GK_TILE, Ahi, brow, k0, t);
            stage_g(nb + 1 * GK_TILE, Bhi, bcol, k0, t);
            if (BTERMS == 2) stage_g(nb + 2 * GK_TILE, Blo, bcol, k0, t);
            CP_COMMIT();
        }
        const uint32_t bufb = sb + (kt & 1) * GK_BUF;

#pragma unroll
        for (int ks = 0; ks < 2; ks++) {
            const int ksb = ks * 32;
            uint32_t bh[2][4], bl[2][4];
#pragma unroll
            for (int np = 0; np < 2; np++) {
                const uint32_t off = (uint32_t)((wn * 32 + np * 16 + b_roff) * 64 + ksb + b_koff);
                ldsm_x4(bh[np], bufb + 1 * GK_TILE + sw64(off));
                if (BTERMS == 2)
                    ldsm_x4(bl[np], bufb + 2 * GK_TILE + sw64(off));
            }
#pragma unroll
            for (int mp = 0; mp < 2; mp++) {
                uint32_t ah[2][4];
#pragma unroll
                for (int q = 0; q < 2; q++) {
                    const int mt = mp * 2 + q;
                    const uint32_t off = (uint32_t)((wm * 64 + mt * 16 + a_roff) * 64 + ksb + a_koff);
                    ldsm_x4(ah[q], bufb + 0 * GK_TILE + sw64(off));
                }
#pragma unroll
                for (int q = 0; q < 2; q++)
#pragma unroll
                    for (int nt = 0; nt < 4; nt++)
                        mma_f16(acc[mp * 2 + q][nt], ah[q], &bh[nt >> 1][(nt & 1) * 2]);
                if (BTERMS == 2) {
#pragma unroll
                    for (int q = 0; q < 2; q++)
#pragma unroll
                        for (int nt = 0; nt < 4; nt++)
                            mma_f16(acc[mp * 2 + q][nt], ah[q], &bl[nt >> 1][(nt & 1) * 2]);
                }
            }
        }
    }

    const int g  = lane >> 2;
    const int tq = lane & 3;
#pragma unroll
    for (int mt = 0; mt < 4; mt++) {
        const int r0 = brow + wm * 64 + mt * 16 + g;
        float mr0 = 1.0f, mr1 = 1.0f;
        if (MODE == 1) { mr0 = mask[r0]; mr1 = mask[r0 + 8]; }
#pragma unroll
        for (int nt = 0; nt < 4; nt++) {
            const int c = bcol + wn * 32 + nt * 8 + tq * 2;
            const float b0 = bias[c], b1 = bias[c + 1];
            float2 v0, v1;
            v0.x = acc[mt][nt][0] + b0; v0.y = acc[mt][nt][1] + b1;
            v1.x = acc[mt][nt][2] + b0; v1.y = acc[mt][nt][3] + b1;
            if (MODE == 0) {
                v0.x *= scale; v0.y *= scale; v1.x *= scale; v1.y *= scale;
                const int h  = c >> 6;
                const int hd = c & (HDIM - 1);
                const int bi = r0 >> 11;
                const int s0 = r0 & (SS - 1);
                const size_t base = ((size_t)(bi * HH + h) * SS) * HDIM + hd;
                if (STORE_LO) {
                    uint32_t h0, l0, h1, l1;
                    split2h(v0.x, v0.y, h0, l0);
                    split2h(v1.x, v1.y, h1, l1);
                    *(uint32_t*)&out_hi[base + (size_t)s0 * HDIM] = h0;
                    *(uint32_t*)&out_lo[base + (size_t)s0 * HDIM] = l0;
                    *(uint32_t*)&out_hi[base + (size_t)(s0 + 8) * HDIM] = h1;
                    *(uint32_t*)&out_lo[base + (size_t)(s0 + 8) * HDIM] = l1;
                } else {
                    *(uint32_t*)&out_hi[base + (size_t)s0 * HDIM] = pack_h2(v0.x, v0.y);
                    *(uint32_t*)&out_hi[base + (size_t)(s0 + 8) * HDIM] = pack_h2(v1.x, v1.y);
                }
            } else {
                if (v0.x < 0.0f) v0.x *= 0.01f;
                if (v0.y < 0.0f) v0.y *= 0.01f;
                if (v1.x < 0.0f) v1.x *= 0.01f;
                if (v1.y < 0.0f) v1.y *= 0.01f;
                v0.x *= mr0; v0.y *= mr0;
                v1.x *= mr1; v1.y *= mr1;
                *(float2*)&out[(size_t)r0 * DD + c] = v0;
                *(float2*)&out[(size_t)(r0 + 8) * DD + c] = v1;
            }
        }
    }
}

// ---------------------------------------------------------------------------
// Flash attention, fp16 mma. BQ=128, BK=64, SW128.
// QK: qh*kh + ql*kh. PV: ph*vh (V hi only). smem 64.5KB -> 2 CTAs/SM.
// ---------------------------------------------------------------------------
#define BQ     128
#define BK     64
#define QTILE  16384                 // 128 rows * 128 B
#define KVTILE 8192                  // 64 rows * 128 B
#define OFF_Q  0                     // Qhi, Qlo
#define OFF_K  (2 * QTILE)           // 2 bufs x hi
#define OFF_V  (OFF_K + 2 * KVTILE)  // 2 bufs x hi
#define OFF_M  (OFF_V + 2 * KVTILE)
#define SM_ATTN (OFF_M + 2 * 256)    // 66048

__device__ __forceinline__ void stage_q(uint32_t dst, const __half* src,
                                        size_t gbase, int t)
{
#pragma unroll
    for (int i = 0; i < 4; i++) {
        int id  = t + i * 256;
        int row = id >> 3;
        int c   = id & 7;
        CP_ASYNC16(dst + sw128((uint32_t)(row * 128 + c * 16)),
                   src + gbase + (size_t)row * HDIM + c * 8);
    }
}

__device__ __forceinline__ void stage_kv(uint32_t dst, const __half* src,
                                         size_t gbase, int t)
{
#pragma unroll
    for (int i = 0; i < 2; i++) {
        int id  = t + i * 256;
        int row = id >> 3;
        int c   = id & 7;
        CP_ASYNC16(dst + sw128((uint32_t)(row * 128 + c * 16)),
                   src + gbase + (size_t)row * HDIM + c * 8);
    }
}

__global__ __launch_bounds__(256, 2)
void attn_mma(const float* __restrict__ mask, float* __restrict__ ctx)
{
    extern __shared__ __align__(128) char smem[];
    const uint32_t sb = smem_u32(smem);
    const int t    = threadIdx.x;
    const int wid  = t >> 5;
    const int lane = t & 31;
    const int qt = blockIdx.x;
    const int h  = blockIdx.y;
    const int b  = blockIdx.z;

    const int gidx = lane >> 2;
    const int tq   = lane & 3;
    const int sub  = lane >> 3;
    const int lr   = lane & 7;
    const int a_roff = lr + (sub & 1) * 8;
    const int a_koff = (sub >> 1) * 16;
    const int b_roff = lr + (sub >> 1) * 8;
    const int b_koff = (sub & 1) * 16;
    const int v_koff = lr + ((lane >> 3) & 1) * 8;
    const int v_nbyte = (lane >> 4) * 16;

    const size_t head = ((size_t)(b * HH + h) * SS) * HDIM;
    const size_t qg = head + (size_t)qt * BQ * HDIM;

    stage_q(sb + OFF_Q,          g_qh, qg, t);
    stage_q(sb + OFF_Q + QTILE,  g_ql, qg, t);
    stage_kv(sb + OFF_K, g_kh, head, t);
    stage_kv(sb + OFF_V, g_vh, head, t);
    if (t < 16) CP_ASYNC16(sb + OFF_M + t * 16, mask + b * SS + t * 4);
    CP_COMMIT();

    float oacc[8][4];
#pragma unroll
    for (int nt = 0; nt < 8; nt++)
#pragma unroll
        for (int e = 0; e < 4; e++) oacc[nt][e] = 0.0f;
    float m0 = -1e30f, m1 = -1e30f, l0 = 0.0f, l1 = 0.0f;

    for (int kt = 0; kt < SS / BK; kt++) {
        CP_WAIT0();
        __syncthreads();
        if (kt + 1 < SS / BK) {
            const uint32_t kb = sb + OFF_K + ((kt + 1) & 1) * KVTILE;
            const uint32_t vb = sb + OFF_V + ((kt + 1) & 1) * KVTILE;
            const size_t kg = head + (size_t)(kt + 1) * BK * HDIM;
            stage_kv(kb, g_kh, kg, t);
            stage_kv(vb, g_vh, kg, t);
            if (t < 16)
                CP_ASYNC16(sb + OFF_M + ((kt + 1) & 1) * 256 + t * 16,
                           mask + b * SS + (kt + 1) * BK + t * 4);
            CP_COMMIT();
        }
        const uint32_t kbuf = sb + OFF_K + (kt & 1) * KVTILE;
        const uint32_t vbuf = sb + OFF_V + (kt & 1) * KVTILE;
        const float* mbuf = (const float*)(smem + OFF_M + (kt & 1) * 256);

        // ---- S = Q K^T: qh*kh + ql*kh ----
        float sacc[8][4];
#pragma unroll
        for (int nt = 0; nt < 8; nt++)
#pragma unroll
            for (int e = 0; e < 4; e++) sacc[nt][e] = 0.0f;

#pragma unroll
        for (int kc = 0; kc < 4; kc++) {
            uint32_t ah[4], al[4];
            const uint32_t qoff = (uint32_t)((wid * 16 + a_roff) * 128 + kc * 32 + a_koff);
            ldsm_x4(ah, sb + OFF_Q + sw128(qoff));
            ldsm_x4(al, sb + OFF_Q + QTILE + sw128(qoff));
#pragma unroll
            for (int np = 0; np < 4; np++) {
                uint32_t bh[4];
                const uint32_t koff = (uint32_t)((np * 16 + b_roff) * 128 + kc * 32 + b_koff);
                ldsm_x4(bh, kbuf + sw128(koff));
#pragma unroll
                for (int half = 0; half < 2; half++) {
                    float* d = sacc[np * 2 + half];
                    mma_f16(d, ah, &bh[half * 2]);
                    mma_f16(d, al, &bh[half * 2]);
                }
            }
        }

        // ---- add mask, online softmax ----
        float mx0 = -1e30f, mx1 = -1e30f;
#pragma unroll
        for (int nt = 0; nt < 8; nt++) {
            const int col = nt * 8 + tq * 2;
            const float ma0 = (1.0f - mbuf[col]) * -10000.0f;
            const float ma1 = (1.0f - mbuf[col + 1]) * -10000.0f;
            sacc[nt][0] += ma0; sacc[nt][1] += ma1;
            sacc[nt][2] += ma0; sacc[nt][3] += ma1;
            mx0 = fmaxf(mx0, fmaxf(sacc[nt][0], sacc[nt][1]));
            mx1 = fmaxf(mx1, fmaxf(sacc[nt][2], sacc[nt][3]));
        }
        mx0 = fmaxf(mx0, __shfl_xor_sync(0xffffffffu, mx0, 1));
        mx0 = fmaxf(mx0, __shfl_xor_sync(0xffffffffu, mx0, 2));
        mx1 = fmaxf(mx1, __shfl_xor_sync(0xffffffffu, mx1, 1));
        mx1 = fmaxf(mx1, __shfl_xor_sync(0xffffffffu, mx1, 2));

        const float mn0 = fmaxf(m0, mx0);
        const float mn1 = fmaxf(m1, mx1);
        const float al0 = __expf(m0 - mn0);
        const float al1 = __expf(m1 - mn1);
        m0 = mn0; m1 = mn1;

        float rs0 = 0.0f, rs1 = 0.0f;
#pragma unroll
        for (int nt = 0; nt < 8; nt++) {
            sacc[nt][0] = __expf(sacc[nt][0] - mn0);
            sacc[nt][1] = __expf(sacc[nt][1] - mn0);
            sacc[nt][2] = __expf(sacc[nt][2] - mn1);
            sacc[nt][3] = __expf(sacc[nt][3] - mn1);
            rs0 += sacc[nt][0] + sacc[nt][1];
            rs1 += sacc[nt][2] + sacc[nt][3];
        }
        rs0 += __shfl_xor_sync(0xffffffffu, rs0, 1);
        rs0 += __shfl_xor_sync(0xffffffffu, rs0, 2);
        rs1 += __shfl_xor_sync(0xffffffffu, rs1, 1);
        rs1 += __shfl_xor_sync(0xffffffffu, rs1, 2);
        l0 = l0 * al0 + rs0;
        l1 = l1 * al1 + rs1;

#pragma unroll
        for (int nt = 0; nt < 8; nt++) {
            oacc[nt][0] *= al0; oacc[nt][1] *= al0;
            oacc[nt][2] *= al1; oacc[nt][3] *= al1;
        }

        // ---- O += P V (V hi only) ----
#pragma unroll
        for (int j = 0; j < 4; j++) {
            uint32_t ph[4];
            ph[0] = pack_h2(sacc[2*j][0],   sacc[2*j][1]);
            ph[1] = pack_h2(sacc[2*j][2],   sacc[2*j][3]);
            ph[2] = pack_h2(sacc[2*j+1][0], sacc[2*j+1][1]);
            ph[3] = pack_h2(sacc[2*j+1][2], sacc[2*j+1][3]);
#pragma unroll
            for (int np = 0; np < 4; np++) {
                uint32_t bvh[4];
                const uint32_t voff = (uint32_t)((j * 16 + v_koff) * 128 + np * 32 + v_nbyte);
                ldsm_x4_t(bvh, vbuf + sw128(voff));
#pragma unroll
                for (int half = 0; half < 2; half++)
                    mma_f16(oacc[np * 2 + half], ph, &bvh[half * 2]);
            }
        }
    }

    const float inv0 = 1.0f / l0;
    const float inv1 = 1.0f / l1;
    const int row0 = qt * BQ + wid * 16 + gidx;
#pragma unroll
    for (int nt = 0; nt < 8; nt++) {
        const int col = h * HDIM + nt * 8 + tq * 2;
        float2 v0, v1;
        v0.x = oacc[nt][0] * inv0; v0.y = oacc[nt][1] * inv0;
        v1.x = oacc[nt][2] * inv1; v1.y = oacc[nt][3] * inv1;
        *(float2*)&ctx[((size_t)b * SS + row0) * DD + col] = v0;
        *(float2*)&ctx[((size_t)b * SS + row0 + 8) * DD + col] = v1;
    }
}

// ---------------------------------------------------------------------------
// Residual add + LayerNorm -> fp16 hi output
// ---------------------------------------------------------------------------
__global__ __launch_bounds__(256)
void ln_kernel(const float* __restrict__ x0, const float* __restrict__ gam,
               const float* __restrict__ bet)
{
    __shared__ float red[16];
    const int row = blockIdx.x;
    const int t = threadIdx.x;
    const float* cptr = g_ctx + (size_t)row * DD;
    const float* xptr = x0 + (size_t)row * DD;

    float v[4];
    float sum = 0.0f, sq = 0.0f;
#pragma unroll
    for (int e = 0; e < 4; e++) {
        int idx = e * 256 + t;
        float x = cptr[idx] + xptr[idx];
        v[e] = x;
        sum += x;
        sq += x * x;
    }
#pragma unroll
    for (int off = 16; off; off >>= 1) {
        sum += __shfl_xor_sync(0xffffffffu, sum, off);
        sq  += __shfl_xor_sync(0xffffffffu, sq, off);
    }
    const int w = t >> 5;
    if ((t & 31) == 0) { red[w] = sum; red[8 + w] = sq; }
    __syncthreads();
    float tsum = 0.0f, tsq = 0.0f;
#pragma unroll
    for (int i = 0; i < 8; i++) { tsum += red[i]; tsq += red[8 + i]; }
    const float mu = tsum * (1.0f / DD);
    const float var = tsq * (1.0f / DD) - mu * mu;
    const float rs = rsqrtf(var + 1e-5f);

#pragma unroll
    for (int e = 0; e < 4; e++) {
        int idx = e * 256 + t;
        float y = (v[e] - mu) * rs * gam[idx] + bet[idx];
        g_xn_h[(size_t)row * DD + idx] = __float2half_rn(y);
    }
}

// ---------------------------------------------------------------------------
extern "C" void kernel_launch(void* const* d_in, const int* in_sizes, int n_in,
                              void* d_out, int out_size)
{
    (void)in_sizes; (void)n_in; (void)out_size;
    const float* inputs = (const float*)d_in[0];
    const float* mask   = (const float*)d_in[1];
    const float* Wq     = (const float*)d_in[2];
    const float* bq     = (const float*)d_in[3];
    const float* Wk     = (const float*)d_in[4];
    const float* bk     = (const float*)d_in[5];
    const float* Wv     = (const float*)d_in[6];
    const float* bv     = (const float*)d_in[7];
    const float* Wo     = (const float*)d_in[8];
    const float* bo     = (const float*)d_in[9];
    const float* ln_g   = (const float*)d_in[10];
    const float* ln_b   = (const float*)d_in[11];
    float* out = (float*)d_out;

    float* ctxp;
    __half *qh, *ql, *kh, *vh;
    __half *inh, *wqh, *wql, *wkh, *wkl, *wvh, *woh, *xnh;
    cudaGetSymbolAddress((void**)&ctxp, g_ctx);
    cudaGetSymbolAddress((void**)&qh, g_qh);
    cudaGetSymbolAddress((void**)&ql, g_ql);
    cudaGetSymbolAddress((void**)&kh, g_kh);
    cudaGetSymbolAddress((void**)&vh, g_vh);
    cudaGetSymbolAddress((void**)&inh, g_in_h);
    cudaGetSymbolAddress((void**)&wqh, g_wq_h);
    cudaGetSymbolAddress((void**)&wql, g_wq_l);
    cudaGetSymbolAddress((void**)&wkh, g_wk_h);
    cudaGetSymbolAddress((void**)&wkl, g_wk_l);
    cudaGetSymbolAddress((void**)&wvh, g_wv_h);
    cudaGetSymbolAddress((void**)&woh, g_wo_h);
    cudaGetSymbolAddress((void**)&xnh, g_xn_h);

    cudaFuncSetAttribute((const void*)gemm_mma<0, 1, 2>,
                         cudaFuncAttributeMaxDynamicSharedMemorySize, SM_GEMM);
    cudaFuncSetAttribute((const void*)gemm_mma<0, 0, 2>,
                         cudaFuncAttributeMaxDynamicSharedMemorySize, SM_GEMM);
    cudaFuncSetAttribute((const void*)gemm_mma<0, 0, 1>,
                         cudaFuncAttributeMaxDynamicSharedMemorySize, SM_GEMM);
    cudaFuncSetAttribute((const void*)gemm_mma<1, 0, 1>,
                         cudaFuncAttributeMaxDynamicSharedMemorySize, SM_GEMM);
    cudaFuncSetAttribute((const void*)attn_mma,
                         cudaFuncAttributeMaxDynamicSharedMemorySize, SM_ATTN);

    cvt_kernel<<<(MTOT * DD / 4) / 256, 256>>>(inputs, inh, MTOT * DD / 4);
    split_kernel<<<(DD * DD / 4) / 256, 256>>>(Wq, wqh, wql, DD * DD / 4);
    split_kernel<<<(DD * DD / 4) / 256, 256>>>(Wk, wkh, wkl, DD * DD / 4);
    cvt_kernel<<<(DD * DD / 4) / 256, 256>>>(Wv, wvh, DD * DD / 4);
    cvt_kernel<<<(DD * DD / 4) / 256, 256>>>(Wo, woh, DD * DD / 4);

    dim3 ggrid(DD / 128, MTOT / 128);
    // Q: B 2-term, store hi+lo. K: B 2-term, hi only. V: B 1-term, hi only.
    gemm_mma<0, 1, 2><<<ggrid, 256, SM_GEMM>>>(inh, wqh, wql, bq, nullptr,
                                               nullptr, qh, ql, 0.125f);
    gemm_mma<0, 0, 2><<<ggrid, 256, SM_GEMM>>>(inh, wkh, wkl, bk, nullptr,
                                               nullptr, kh, nullptr, 1.0f);
    gemm_mma<0, 0, 1><<<ggrid, 256, SM_GEMM>>>(inh, wvh, nullptr, bv, nullptr,
                                               nullptr, vh, nullptr, 1.0f);

    attn_mma<<<dim3(SS / BQ, HH, BB), 256, SM_ATTN>>>(mask, ctxp);

    ln_kernel<<<MTOT, 256>>>(inputs, ln_g, ln_b);

    // out projection: B 1-term
    gemm_mma<1, 0, 1><<<ggrid, 256, SM_GEMM>>>(xnh, woh, nullptr, bo, mask,
                                               out, nullptr, nullptr, 1.0f);
}

// round 17
// speedup vs baseline: 7.4910x; 1.2425x over previous
#include <cuda_runtime.h>
#include <cuda_fp16.h>
#include <cstdint>

// Problem constants
#define BB   4
#define SS   2048
#define DD   1024
#define HH   16
#define HDIM 64
#define MTOT (BB * SS)   // 8192

// ---------------------------------------------------------------------------
// Scratch (__device__ globals; allocation is forbidden)
// ---------------------------------------------------------------------------
__device__ float g_ctx[(size_t)MTOT * DD];

__device__ __half g_qh[(size_t)BB * HH * SS * HDIM];
__device__ __half g_kh[(size_t)BB * HH * SS * HDIM];
__device__ __half g_vh[(size_t)BB * HH * SS * HDIM];

__device__ __half g_in_h[(size_t)MTOT * DD];
__device__ __half g_wq_h[(size_t)DD * DD];
__device__ __half g_wk_h[(size_t)DD * DD];
__device__ __half g_wv_h[(size_t)DD * DD];
__device__ __half g_wo_h[(size_t)DD * DD];
__device__ __half g_xn_h[(size_t)MTOT * DD];

// ---------------------------------------------------------------------------
// PTX helpers
// ---------------------------------------------------------------------------
__device__ __forceinline__ uint32_t smem_u32(const void* p) {
    uint32_t a;
    asm("{ .reg .u64 t; cvta.to.shared.u64 t, %1; cvt.u32.u64 %0, t; }"
        : "=r"(a) : "l"(p));
    return a;
}

__device__ __forceinline__ void ldsm_x4(uint32_t* r, uint32_t addr) {
    asm volatile("ldmatrix.sync.aligned.m8n8.x4.shared.b16 {%0,%1,%2,%3}, [%4];"
                 : "=r"(r[0]), "=r"(r[1]), "=r"(r[2]), "=r"(r[3]) : "r"(addr));
}

__device__ __forceinline__ void ldsm_x4_t(uint32_t* r, uint32_t addr) {
    asm volatile("ldmatrix.sync.aligned.m8n8.x4.trans.shared.b16 {%0,%1,%2,%3}, [%4];"
                 : "=r"(r[0]), "=r"(r[1]), "=r"(r[2]), "=r"(r[3]) : "r"(addr));
}

__device__ __forceinline__ void mma_f16(float* d, const uint32_t* a, const uint32_t* b) {
    asm volatile("mma.sync.aligned.m16n8k16.row.col.f32.f16.f16.f32 "
                 "{%0,%1,%2,%3}, {%4,%5,%6,%7}, {%8,%9}, {%0,%1,%2,%3};"
                 : "+f"(d[0]), "+f"(d[1]), "+f"(d[2]), "+f"(d[3])
                 : "r"(a[0]), "r"(a[1]), "r"(a[2]), "r"(a[3]), "r"(b[0]), "r"(b[1]));
}

#define CP_ASYNC16(dst, src) \
    asm volatile("cp.async.cg.shared.global [%0], [%1], 16;" \
                 :: "r"(dst), "l"(src) : "memory")
#define CP_COMMIT() asm volatile("cp.async.commit_group;" ::: "memory")
#define CP_WAIT0()  asm volatile("cp.async.wait_group 0;" ::: "memory")

// smem swizzles (tile-relative byte offsets)
__device__ __forceinline__ uint32_t sw64(uint32_t o)  { return o ^ (((o >> 7) & 3) << 4); }
__device__ __forceinline__ uint32_t sw128(uint32_t o) { return o ^ ((o >> 3) & 0x70); }

__device__ __forceinline__ uint32_t pack_h2(float a, float b) {
    __half2 H = __floats2half2_rn(a, b);
    return *(uint32_t*)&H;
}

// ---------------------------------------------------------------------------
// fp32 -> fp16 convert
// ---------------------------------------------------------------------------
__global__ __launch_bounds__(256)
void cvt_kernel(const float* __restrict__ src, __half* __restrict__ hi, int n4)
{
    int i = blockIdx.x * 256 + threadIdx.x;
    if (i >= n4) return;
    float4 v = ((const float4*)src)[i];
    uint2 H;
    H.x = pack_h2(v.x, v.y);
    H.y = pack_h2(v.z, v.w);
    ((uint2*)hi)[i] = H;
}

// ---------------------------------------------------------------------------
// mma.sync fp16 GEMM: C = A_hi * W_hi^T + bias
// 128x128 tile, 8 warps (64x32), BK=32, sw64 rows, 2 CTAs/SM.
// MODE 0: scatter (c+bias)*scale as fp16 into [B,H,S,HD]
// MODE 1: fp32 LeakyReLU + mask, row-major
// ---------------------------------------------------------------------------
#define GK_TILE 8192                 // 128 rows * 64 B
#define GK_BUF  (2 * GK_TILE)        // Ahi, Bhi
#define SM_GEMM (2 * GK_BUF)         // 32768
#define NKT     (DD / 32)

__device__ __forceinline__ void stage_g(uint32_t dst, const __half* src,
                                        int rowbase, int k0, int t)
{
#pragma unroll
    for (int i = 0; i < 2; i++) {
        int id  = t + i * 256;
        int row = id >> 2;
        int c   = (id & 3);
        CP_ASYNC16(dst + sw64((uint32_t)(row * 64 + c * 16)),
                   src + (size_t)(rowbase + row) * DD + k0 + c * 8);
    }
}

template <int MODE>
__global__ __launch_bounds__(256, 2)
void gemm_mma(const __half* __restrict__ Ahi, const __half* __restrict__ Bhi,
              const float* __restrict__ bias, const float* __restrict__ mask,
              float* __restrict__ out, __half* __restrict__ out_hi,
              float scale)
{
    extern __shared__ __align__(128) char smem[];
    const uint32_t sb = smem_u32(smem);
    const int t    = threadIdx.x;
    const int wid  = t >> 5;
    const int lane = t & 31;
    const int brow = blockIdx.y * 128;
    const int bcol = blockIdx.x * 128;
    const int wm = wid & 1;
    const int wn = wid >> 1;

    const int sub = lane >> 3;
    const int lr  = lane & 7;
    const int a_roff = lr + (sub & 1) * 8;
    const int a_koff = (sub >> 1) * 16;
    const int b_roff = lr + (sub >> 1) * 8;
    const int b_koff = (sub & 1) * 16;

    stage_g(sb + 0 * GK_TILE, Ahi, brow, 0, t);
    stage_g(sb + 1 * GK_TILE, Bhi, bcol, 0, t);
    CP_COMMIT();

    float acc[4][4][4];
#pragma unroll
    for (int mt = 0; mt < 4; mt++)
#pragma unroll
        for (int nt = 0; nt < 4; nt++)
#pragma unroll
            for (int e = 0; e < 4; e++) acc[mt][nt][e] = 0.0f;

    for (int kt = 0; kt < NKT; kt++) {
        CP_WAIT0();
        __syncthreads();
        if (kt + 1 < NKT) {
            const uint32_t nb = sb + ((kt + 1) & 1) * GK_BUF;
            const int k0 = (kt + 1) * 32;
            stage_g(nb + 0 * GK_TILE, Ahi, brow, k0, t);
            stage_g(nb + 1 * GK_TILE, Bhi, bcol, k0, t);
            CP_COMMIT();
        }
        const uint32_t bufb = sb + (kt & 1) * GK_BUF;

#pragma unroll
        for (int ks = 0; ks < 2; ks++) {
            const int ksb = ks * 32;
            uint32_t bh[2][4];
#pragma unroll
            for (int np = 0; np < 2; np++) {
                const uint32_t off = (uint32_t)((wn * 32 + np * 16 + b_roff) * 64 + ksb + b_koff);
                ldsm_x4(bh[np], bufb + 1 * GK_TILE + sw64(off));
            }
#pragma unroll
            for (int mp = 0; mp < 2; mp++) {
                uint32_t ah[2][4];
#pragma unroll
                for (int q = 0; q < 2; q++) {
                    const int mt = mp * 2 + q;
                    const uint32_t off = (uint32_t)((wm * 64 + mt * 16 + a_roff) * 64 + ksb + a_koff);
                    ldsm_x4(ah[q], bufb + 0 * GK_TILE + sw64(off));
                }
#pragma unroll
                for (int q = 0; q < 2; q++)
#pragma unroll
                    for (int nt = 0; nt < 4; nt++)
                        mma_f16(acc[mp * 2 + q][nt], ah[q], &bh[nt >> 1][(nt & 1) * 2]);
            }
        }
    }

    const int g  = lane >> 2;
    const int tq = lane & 3;
#pragma unroll
    for (int mt = 0; mt < 4; mt++) {
        const int r0 = brow + wm * 64 + mt * 16 + g;
        float mr0 = 1.0f, mr1 = 1.0f;
        if (MODE == 1) { mr0 = mask[r0]; mr1 = mask[r0 + 8]; }
#pragma unroll
        for (int nt = 0; nt < 4; nt++) {
            const int c = bcol + wn * 32 + nt * 8 + tq * 2;
            const float b0 = bias[c], b1 = bias[c + 1];
            float2 v0, v1;
            v0.x = acc[mt][nt][0] + b0; v0.y = acc[mt][nt][1] + b1;
            v1.x = acc[mt][nt][2] + b0; v1.y = acc[mt][nt][3] + b1;
            if (MODE == 0) {
                v0.x *= scale; v0.y *= scale; v1.x *= scale; v1.y *= scale;
                const int h  = c >> 6;
                const int hd = c & (HDIM - 1);
                const int bi = r0 >> 11;
                const int s0 = r0 & (SS - 1);
                const size_t base = ((size_t)(bi * HH + h) * SS) * HDIM + hd;
                *(uint32_t*)&out_hi[base + (size_t)s0 * HDIM] = pack_h2(v0.x, v0.y);
                *(uint32_t*)&out_hi[base + (size_t)(s0 + 8) * HDIM] = pack_h2(v1.x, v1.y);
            } else {
                if (v0.x < 0.0f) v0.x *= 0.01f;
                if (v0.y < 0.0f) v0.y *= 0.01f;
                if (v1.x < 0.0f) v1.x *= 0.01f;
                if (v1.y < 0.0f) v1.y *= 0.01f;
                v0.x *= mr0; v0.y *= mr0;
                v1.x *= mr1; v1.y *= mr1;
                *(float2*)&out[(size_t)r0 * DD + c] = v0;
                *(float2*)&out[(size_t)(r0 + 8) * DD + c] = v1;
            }
        }
    }
}

// ---------------------------------------------------------------------------
// Flash attention, fp16 mma. BQ=128, BK=64, SW128.
// QK: qh*kh. PV: ph*vh. smem 49.7KB -> 2 CTAs/SM.
// ---------------------------------------------------------------------------
#define BQ     128
#define BK     64
#define QTILE  16384                 // 128 rows * 128 B
#define KVTILE 8192                  // 64 rows * 128 B
#define OFF_Q  0                     // Q hi
#define OFF_K  QTILE                 // 2 bufs x hi
#define OFF_V  (OFF_K + 2 * KVTILE)
#define OFF_M  (OFF_V + 2 * KVTILE)
#define SM_ATTN (OFF_M + 2 * 256)    // 49664

__device__ __forceinline__ void stage_q(uint32_t dst, const __half* src,
                                        size_t gbase, int t)
{
#pragma unroll
    for (int i = 0; i < 4; i++) {
        int id  = t + i * 256;
        int row = id >> 3;
        int c   = id & 7;
        CP_ASYNC16(dst + sw128((uint32_t)(row * 128 + c * 16)),
                   src + gbase + (size_t)row * HDIM + c * 8);
    }
}

__device__ __forceinline__ void stage_kv(uint32_t dst, const __half* src,
                                         size_t gbase, int t)
{
#pragma unroll
    for (int i = 0; i < 2; i++) {
        int id  = t + i * 256;
        int row = id >> 3;
        int c   = id & 7;
        CP_ASYNC16(dst + sw128((uint32_t)(row * 128 + c * 16)),
                   src + gbase + (size_t)row * HDIM + c * 8);
    }
}

__global__ __launch_bounds__(256, 2)
void attn_mma(const float* __restrict__ mask, float* __restrict__ ctx)
{
    extern __shared__ __align__(128) char smem[];
    const uint32_t sb = smem_u32(smem);
    const int t    = threadIdx.x;
    const int wid  = t >> 5;
    const int lane = t & 31;
    const int qt = blockIdx.x;
    const int h  = blockIdx.y;
    const int b  = blockIdx.z;

    const int gidx = lane >> 2;
    const int tq   = lane & 3;
    const int sub  = lane >> 3;
    const int lr   = lane & 7;
    const int a_roff = lr + (sub & 1) * 8;
    const int a_koff = (sub >> 1) * 16;
    const int b_roff = lr + (sub >> 1) * 8;
    const int b_koff = (sub & 1) * 16;
    const int v_koff = lr + ((lane >> 3) & 1) * 8;
    const int v_nbyte = (lane >> 4) * 16;

    const size_t head = ((size_t)(b * HH + h) * SS) * HDIM;
    const size_t qg = head + (size_t)qt * BQ * HDIM;

    stage_q(sb + OFF_Q, g_qh, qg, t);
    stage_kv(sb + OFF_K, g_kh, head, t);
    stage_kv(sb + OFF_V, g_vh, head, t);
    if (t < 16) CP_ASYNC16(sb + OFF_M + t * 16, mask + b * SS + t * 4);
    CP_COMMIT();

    float oacc[8][4];
#pragma unroll
    for (int nt = 0; nt < 8; nt++)
#pragma unroll
        for (int e = 0; e < 4; e++) oacc[nt][e] = 0.0f;
    float m0 = -1e30f, m1 = -1e30f, l0 = 0.0f, l1 = 0.0f;

    for (int kt = 0; kt < SS / BK; kt++) {
        CP_WAIT0();
        __syncthreads();
        if (kt + 1 < SS / BK) {
            const uint32_t kb = sb + OFF_K + ((kt + 1) & 1) * KVTILE;
            const uint32_t vb = sb + OFF_V + ((kt + 1) & 1) * KVTILE;
            const size_t kg = head + (size_t)(kt + 1) * BK * HDIM;
            stage_kv(kb, g_kh, kg, t);
            stage_kv(vb, g_vh, kg, t);
            if (t < 16)
                CP_ASYNC16(sb + OFF_M + ((kt + 1) & 1) * 256 + t * 16,
                           mask + b * SS + (kt + 1) * BK + t * 4);
            CP_COMMIT();
        }
        const uint32_t kbuf = sb + OFF_K + (kt & 1) * KVTILE;
        const uint32_t vbuf = sb + OFF_V + (kt & 1) * KVTILE;
        const float* mbuf = (const float*)(smem + OFF_M + (kt & 1) * 256);

        // ---- S = Q K^T (single term) ----
        float sacc[8][4];
#pragma unroll
        for (int nt = 0; nt < 8; nt++)
#pragma unroll
            for (int e = 0; e < 4; e++) sacc[nt][e] = 0.0f;

#pragma unroll
        for (int kc = 0; kc < 4; kc++) {
            uint32_t ah[4];
            const uint32_t qoff = (uint32_t)((wid * 16 + a_roff) * 128 + kc * 32 + a_koff);
            ldsm_x4(ah, sb + OFF_Q + sw128(qoff));
#pragma unroll
            for (int np = 0; np < 4; np++) {
                uint32_t bh[4];
                const uint32_t koff = (uint32_t)((np * 16 + b_roff) * 128 + kc * 32 + b_koff);
                ldsm_x4(bh, kbuf + sw128(koff));
#pragma unroll
                for (int half = 0; half < 2; half++)
                    mma_f16(sacc[np * 2 + half], ah, &bh[half * 2]);
            }
        }

        // ---- add mask, online softmax ----
        float mx0 = -1e30f, mx1 = -1e30f;
#pragma unroll
        for (int nt = 0; nt < 8; nt++) {
            const int col = nt * 8 + tq * 2;
            const float ma0 = (1.0f - mbuf[col]) * -10000.0f;
            const float ma1 = (1.0f - mbuf[col + 1]) * -10000.0f;
            sacc[nt][0] += ma0; sacc[nt][1] += ma1;
            sacc[nt][2] += ma0; sacc[nt][3] += ma1;
            mx0 = fmaxf(mx0, fmaxf(sacc[nt][0], sacc[nt][1]));
            mx1 = fmaxf(mx1, fmaxf(sacc[nt][2], sacc[nt][3]));
        }
        mx0 = fmaxf(mx0, __shfl_xor_sync(0xffffffffu, mx0, 1));
        mx0 = fmaxf(mx0, __shfl_xor_sync(0xffffffffu, mx0, 2));
        mx1 = fmaxf(mx1, __shfl_xor_sync(0xffffffffu, mx1, 1));
        mx1 = fmaxf(mx1, __shfl_xor_sync(0xffffffffu, mx1, 2));

        const float mn0 = fmaxf(m0, mx0);
        const float mn1 = fmaxf(m1, mx1);
        const float al0 = __expf(m0 - mn0);
        const float al1 = __expf(m1 - mn1);
        m0 = mn0; m1 = mn1;

        float rs0 = 0.0f, rs1 = 0.0f;
#pragma unroll
        for (int nt = 0; nt < 8; nt++) {
            sacc[nt][0] = __expf(sacc[nt][0] - mn0);
            sacc[nt][1] = __expf(sacc[nt][1] - mn0);
            sacc[nt][2] = __expf(sacc[nt][2] - mn1);
            sacc[nt][3] = __expf(sacc[nt][3] - mn1);
            rs0 += sacc[nt][0] + sacc[nt][1];
            rs1 += sacc[nt][2] + sacc[nt][3];
        }
        rs0 += __shfl_xor_sync(0xffffffffu, rs0, 1);
        rs0 += __shfl_xor_sync(0xffffffffu, rs0, 2);
        rs1 += __shfl_xor_sync(0xffffffffu, rs1, 1);
        rs1 += __shfl_xor_sync(0xffffffffu, rs1, 2);
        l0 = l0 * al0 + rs0;
        l1 = l1 * al1 + rs1;

#pragma unroll
        for (int nt = 0; nt < 8; nt++) {
            oacc[nt][0] *= al0; oacc[nt][1] *= al0;
            oacc[nt][2] *= al1; oacc[nt][3] *= al1;
        }

        // ---- O += P V ----
#pragma unroll
        for (int j = 0; j < 4; j++) {
            uint32_t ph[4];
            ph[0] = pack_h2(sacc[2*j][0],   sacc[2*j][1]);
            ph[1] = pack_h2(sacc[2*j][2],   sacc[2*j][3]);
            ph[2] = pack_h2(sacc[2*j+1][0], sacc[2*j+1][1]);
            ph[3] = pack_h2(sacc[2*j+1][2], sacc[2*j+1][3]);
#pragma unroll
            for (int np = 0; np < 4; np++) {
                uint32_t bvh[4];
                const uint32_t voff = (uint32_t)((j * 16 + v_koff) * 128 + np * 32 + v_nbyte);
                ldsm_x4_t(bvh, vbuf + sw128(voff));
#pragma unroll
                for (int half = 0; half < 2; half++)
                    mma_f16(oacc[np * 2 + half], ph, &bvh[half * 2]);
            }
        }
    }

    const float inv0 = 1.0f / l0;
    const float inv1 = 1.0f / l1;
    const int row0 = qt * BQ + wid * 16 + gidx;
#pragma unroll
    for (int nt = 0; nt < 8; nt++) {
        const int col = h * HDIM + nt * 8 + tq * 2;
        float2 v0, v1;
        v0.x = oacc[nt][0] * inv0; v0.y = oacc[nt][1] * inv0;
        v1.x = oacc[nt][2] * inv1; v1.y = oacc[nt][3] * inv1;
        *(float2*)&ctx[((size_t)b * SS + row0) * DD + col] = v0;
        *(float2*)&ctx[((size_t)b * SS + row0 + 8) * DD + col] = v1;
    }
}

// ---------------------------------------------------------------------------
// Residual add + LayerNorm -> fp16 hi output
// ---------------------------------------------------------------------------
__global__ __launch_bounds__(256)
void ln_kernel(const float* __restrict__ x0, const float* __restrict__ gam,
               const float* __restrict__ bet)
{
    __shared__ float red[16];
    const int row = blockIdx.x;
    const int t = threadIdx.x;
    const float* cptr = g_ctx + (size_t)row * DD;
    const float* xptr = x0 + (size_t)row * DD;

    float v[4];
    float sum = 0.0f, sq = 0.0f;
#pragma unroll
    for (int e = 0; e < 4; e++) {
        int idx = e * 256 + t;
        float x = cptr[idx] + xptr[idx];
        v[e] = x;
        sum += x;
        sq += x * x;
    }
#pragma unroll
    for (int off = 16; off; off >>= 1) {
        sum += __shfl_xor_sync(0xffffffffu, sum, off);
        sq  += __shfl_xor_sync(0xffffffffu, sq, off);
    }
    const int w = t >> 5;
    if ((t & 31) == 0) { red[w] = sum; red[8 + w] = sq; }
    __syncthreads();
    float tsum = 0.0f, tsq = 0.0f;
#pragma unroll
    for (int i = 0; i < 8; i++) { tsum += red[i]; tsq += red[8 + i]; }
    const float mu = tsum * (1.0f / DD);
    const float var = tsq * (1.0f / DD) - mu * mu;
    const float rs = rsqrtf(var + 1e-5f);

#pragma unroll
    for (int e = 0; e < 4; e++) {
        int idx = e * 256 + t;
        float y = (v[e] - mu) * rs * gam[idx] + bet[idx];
        g_xn_h[(size_t)row * DD + idx] = __float2half_rn(y);
    }
}

// ---------------------------------------------------------------------------
extern "C" void kernel_launch(void* const* d_in, const int* in_sizes, int n_in,
                              void* d_out, int out_size)
{
    (void)in_sizes; (void)n_in; (void)out_size;
    const float* inputs = (const float*)d_in[0];
    const float* mask   = (const float*)d_in[1];
    const float* Wq     = (const float*)d_in[2];
    const float* bq     = (const float*)d_in[3];
    const float* Wk     = (const float*)d_in[4];
    const float* bk     = (const float*)d_in[5];
    const float* Wv     = (const float*)d_in[6];
    const float* bv     = (const float*)d_in[7];
    const float* Wo     = (const float*)d_in[8];
    const float* bo     = (const float*)d_in[9];
    const float* ln_g   = (const float*)d_in[10];
    const float* ln_b   = (const float*)d_in[11];
    float* out = (float*)d_out;

    float* ctxp;
    __half *qh, *kh, *vh;
    __half *inh, *wqh, *wkh, *wvh, *woh, *xnh;
    cudaGetSymbolAddress((void**)&ctxp, g_ctx);
    cudaGetSymbolAddress((void**)&qh, g_qh);
    cudaGetSymbolAddress((void**)&kh, g_kh);
    cudaGetSymbolAddress((void**)&vh, g_vh);
    cudaGetSymbolAddress((void**)&inh, g_in_h);
    cudaGetSymbolAddress((void**)&wqh, g_wq_h);
    cudaGetSymbolAddress((void**)&wkh, g_wk_h);
    cudaGetSymbolAddress((void**)&wvh, g_wv_h);
    cudaGetSymbolAddress((void**)&woh, g_wo_h);
    cudaGetSymbolAddress((void**)&xnh, g_xn_h);

    cudaFuncSetAttribute((const void*)gemm_mma<0>,
                         cudaFuncAttributeMaxDynamicSharedMemorySize, SM_GEMM);
    cudaFuncSetAttribute((const void*)gemm_mma<1>,
                         cudaFuncAttributeMaxDynamicSharedMemorySize, SM_GEMM);
    cudaFuncSetAttribute((const void*)attn_mma,
                         cudaFuncAttributeMaxDynamicSharedMemorySize, SM_ATTN);

    cvt_kernel<<<(MTOT * DD / 4) / 256, 256>>>(inputs, inh, MTOT * DD / 4);
    cvt_kernel<<<(DD * DD / 4) / 256, 256>>>(Wq, wqh, DD * DD / 4);
    cvt_kernel<<<(DD * DD / 4) / 256, 256>>>(Wk, wkh, DD * DD / 4);
    cvt_kernel<<<(DD * DD / 4) / 256, 256>>>(Wv, wvh, DD * DD / 4);
    cvt_kernel<<<(DD * DD / 4) / 256, 256>>>(Wo, woh, DD * DD / 4);

    dim3 ggrid(DD / 128, MTOT / 128);
    gemm_mma<0><<<ggrid, 256, SM_GEMM>>>(inh, wqh, bq, nullptr, nullptr, qh, 0.125f);
    gemm_mma<0><<<ggrid, 256, SM_GEMM>>>(inh, wkh, bk, nullptr, nullptr, kh, 1.0f);
    gemm_mma<0><<<ggrid, 256, SM_GEMM>>>(inh, wvh, bv, nullptr, nullptr, vh, 1.0f);

    attn_mma<<<dim3(SS / BQ, HH, BB), 256, SM_ATTN>>>(mask, ctxp);

    ln_kernel<<<MTOT, 256>>>(inputs, ln_g, ln_b);

    gemm_mma<1><<<ggrid, 256, SM_GEMM>>>(xnh, woh, bo, mask, out, nullptr, 1.0f);
}